// round 4
// baseline (speedup 1.0000x reference)
#include <cuda_runtime.h>
#include <cstdint>
#include <cstddef>

#define BB 2
#define SS 2048
#define EE 1024
#define HH 16
#define DHD 64
#define HID 256

// ---------------- scratch (device globals: allocation-free) ----------------
__device__ float g_Q[(size_t)BB * SS * EE];
__device__ float g_K[(size_t)BB * SS * EE];
__device__ float g_V[(size_t)BB * SS * EE];
__device__ float g_CTX[(size_t)BB * SS * EE];
__device__ float g_P[(size_t)BB * HH * SS * SS];   // 537 MB raw scores
__device__ float g_gate[BB * HH];
__device__ float2 g_stat[(size_t)BB * HH * SS];    // (rowmax, 1/Z)

// ---------------- helpers ----------------
__device__ __forceinline__ float fast_exp(float x) {
    float y = x * 1.4426950408889634f;
    float n = rintf(y);
    float t = (y - n) * 0.6931471805599453f;
    float p = 1.0f + t * (1.0f + t * (0.5f + t * (0.16666667f +
              t * (0.041666668f + t * 0.008333334f))));
    n = fmaxf(n, -126.0f);
    return p * __int_as_float(((int)n + 127) << 23);
}

__device__ __forceinline__ uint32_t f2tf32(float x) {
    uint32_t r; asm("cvt.rna.tf32.f32 %0, %1;" : "=r"(r) : "f"(x)); return r;
}
__device__ __forceinline__ void cvt_inplace(uint32_t& r) {
    asm("cvt.rna.tf32.f32 %0, %0;" : "+r"(r));
}

__device__ __forceinline__ void mma_tf32(float* d, const uint32_t* a, const uint32_t* b) {
    asm volatile("mma.sync.aligned.m16n8k8.row.col.f32.tf32.tf32.f32 "
                 "{%0,%1,%2,%3}, {%4,%5,%6,%7}, {%8,%9}, {%0,%1,%2,%3};"
                 : "+f"(d[0]), "+f"(d[1]), "+f"(d[2]), "+f"(d[3])
                 : "r"(a[0]), "r"(a[1]), "r"(a[2]), "r"(a[3]),
                   "r"(b[0]), "r"(b[1]));
}

__device__ __forceinline__ void ldsm_x4(uint32_t* r, uint32_t addr) {
    asm volatile("ldmatrix.sync.aligned.m8n8.x4.shared.b16 {%0,%1,%2,%3}, [%4];"
                 : "=r"(r[0]), "=r"(r[1]), "=r"(r[2]), "=r"(r[3]) : "r"(addr));
}

__device__ __forceinline__ void cp_async16(uint32_t smem, const void* g) {
    asm volatile("cp.async.cg.shared.global [%0], [%1], 16;" :: "r"(smem), "l"(g));
}
__device__ __forceinline__ void cp_commit() { asm volatile("cp.async.commit_group;"); }
__device__ __forceinline__ void cp_wait0() { asm volatile("cp.async.wait_group 0;"); }

// ---------------- sync gate ----------------
__global__ void gate_kernel(const float* __restrict__ sf,
                            const float* __restrict__ Ws1, const float* __restrict__ bs1,
                            const float* __restrict__ Ws2, const float* __restrict__ bs2)
{
    __shared__ float h1[BB][HID];
    int t = threadIdx.x;
    for (int b = 0; b < BB; ++b) {
        float acc = bs1[t];
        for (int e = 0; e < EE; ++e)
            acc += sf[b * EE + e] * Ws1[(size_t)e * HID + t];
        h1[b][t] = fmaxf(acc, 0.0f);
    }
    __syncthreads();
    if (t < BB * HH) {
        int b = t / HH, h = t % HH;
        float acc = bs2[h];
        for (int k = 0; k < HID; ++k)
            acc += h1[b][k] * Ws2[k * HH + h];
        float sig = 1.0f / (1.0f + __expf(-acc));
        g_gate[b * HH + h] = sig * 0.125f;
    }
}

// ======== NN tf32 GEMM 128x128x16, cp.async staging, cvt post-LDSM ==========
__global__ __launch_bounds__(256)
void gemm_nn_ca(const float* __restrict__ A, const float* __restrict__ B,
                const float* __restrict__ bias, float* __restrict__ C,
                int K, int lda, int ldb, int ldc)
{
    constexpr int AST = 20;
    constexpr int BST = 136;

    __shared__ uint32_t As[2][128 * AST];
    __shared__ uint32_t Bs[2][16 * BST];

    const int tid = threadIdx.x;
    const int lane = tid & 31, warp = tid >> 5;
    const int wr = warp & 1, wc = warp >> 1;    // 2 x 4 warps
    const int lr = lane >> 2, lc = lane & 3;

    const int bm = blockIdx.y * 128;
    const int bn = blockIdx.x * 128;

    const int ar = tid >> 2, ac = (tid & 3) * 4;
    const int brw = tid >> 5, bcl = (tid & 31) * 4;

    const float* Ag0 = A + (size_t)(bm + ar) * lda + ac;
    const float* Ag1 = Ag0 + (size_t)64 * lda;
    const float* Bg0 = B + (size_t)brw * ldb + bn + bcl;
    const float* Bg1 = Bg0 + (size_t)8 * ldb;

    const uint32_t As_u32[2] = { (uint32_t)__cvta_generic_to_shared(&As[0][0]),
                                 (uint32_t)__cvta_generic_to_shared(&As[1][0]) };
    const uint32_t Bs_u32[2] = { (uint32_t)__cvta_generic_to_shared(&Bs[0][0]),
                                 (uint32_t)__cvta_generic_to_shared(&Bs[1][0]) };
    const uint32_t a_off0 = (uint32_t)((ar * AST + ac) * 4);
    const uint32_t a_off1 = (uint32_t)(((ar + 64) * AST + ac) * 4);
    const uint32_t b_off0 = (uint32_t)((brw * BST + bcl) * 4);
    const uint32_t b_off1 = (uint32_t)(((brw + 8) * BST + bcl) * 4);

    auto issue_stage = [&](int kt, int buf) {
        int k0 = kt * 16;
        cp_async16(As_u32[buf] + a_off0, Ag0 + k0);
        cp_async16(As_u32[buf] + a_off1, Ag1 + k0);
        cp_async16(Bs_u32[buf] + b_off0, Bg0 + (size_t)k0 * ldb);
        cp_async16(Bs_u32[buf] + b_off1, Bg1 + (size_t)k0 * ldb);
        cp_commit();
    };

    const int a_row_l = wr * 64 + (lane & 15);
    const int a_csel = (lane >> 4) << 2;

    float acc[4][4][4];
#pragma unroll
    for (int i = 0; i < 4; ++i)
#pragma unroll
        for (int j = 0; j < 4; ++j)
#pragma unroll
            for (int r = 0; r < 4; ++r) acc[i][j][r] = 0.0f;

    const int nk = K >> 4;
    issue_stage(0, 0);
    int buf = 0;

    for (int kt = 0; kt < nk; ++kt) {
        cp_wait0();
        __syncthreads();
        if (kt + 1 < nk) issue_stage(kt + 1, buf ^ 1);
#pragma unroll
        for (int ks = 0; ks < 2; ++ks) {
            const int k = ks * 8;
            uint32_t af[4][4], bf[4][2];
#pragma unroll
            for (int mf = 0; mf < 4; ++mf) {
                ldsm_x4(af[mf], As_u32[buf] +
                        (uint32_t)(((a_row_l + mf * 16) * AST + k + a_csel) * 4));
#pragma unroll
                for (int r = 0; r < 4; ++r) cvt_inplace(af[mf][r]);
            }
#pragma unroll
            for (int nf = 0; nf < 4; ++nf) {
                int n = wc * 32 + nf * 8 + lr;
                bf[nf][0] = Bs[buf][(k + lc) * BST + n];
                bf[nf][1] = Bs[buf][(k + 4 + lc) * BST + n];
                cvt_inplace(bf[nf][0]); cvt_inplace(bf[nf][1]);
            }
#pragma unroll
            for (int mf = 0; mf < 4; ++mf)
#pragma unroll
                for (int nf = 0; nf < 4; ++nf)
                    mma_tf32(acc[mf][nf], af[mf], bf[nf]);
        }
        __syncthreads();
        buf ^= 1;
    }

#pragma unroll
    for (int nf = 0; nf < 4; ++nf) {
        int col = bn + wc * 32 + nf * 8 + lc * 2;
        float b0 = 0.0f, b1 = 0.0f;
        if (bias) { b0 = bias[col]; b1 = bias[col + 1]; }
#pragma unroll
        for (int mf = 0; mf < 4; ++mf) {
            int row = bm + wr * 64 + mf * 16 + lr;
            *(float2*)&C[(size_t)row * ldc + col] =
                make_float2(acc[mf][nf][0] + b0, acc[mf][nf][1] + b1);
            *(float2*)&C[(size_t)(row + 8) * ldc + col] =
                make_float2(acc[mf][nf][2] + b0, acc[mf][nf][3] + b1);
        }
    }
}

// ======================= scores: P = gate * Q @ K^T (tf32, LDSM A+B) =========
__global__ __launch_bounds__(256)
void scores_nt_tf32(const float* __restrict__ Q, const float* __restrict__ Kt,
                    float* __restrict__ P)
{
    extern __shared__ uint32_t sm[];
    uint32_t* As = sm;              // [128][68] queries
    uint32_t* Bs = sm + 128 * 68;   // [128][68] keys

    const int tid = threadIdx.x;
    const int lane = tid & 31, warp = tid >> 5;
    const int wr = warp & 1, wc = warp >> 1;
    const int lr = lane >> 2, lc = lane & 3;
    const int bh = blockIdx.z, b = bh >> 4, h = bh & 15;
    const int mi = blockIdx.y * 128, nj = blockIdx.x * 128;

    const float* Ag = Q + (size_t)b * SS * EE + h * 64;
    const float* Bg = Kt + (size_t)b * SS * EE + h * 64;

#pragma unroll
    for (int it = 0; it < 8; ++it) {
        int idx = it * 1024 + tid * 4;
        int r = idx >> 6, k = idx & 63;
        float4 qa = *(const float4*)&Ag[(size_t)(mi + r) * EE + k];
        float4 ka = *(const float4*)&Bg[(size_t)(nj + r) * EE + k];
        *(uint4*)&As[r * 68 + k] = make_uint4(f2tf32(qa.x), f2tf32(qa.y), f2tf32(qa.z), f2tf32(qa.w));
        *(uint4*)&Bs[r * 68 + k] = make_uint4(f2tf32(ka.x), f2tf32(ka.y), f2tf32(ka.z), f2tf32(ka.w));
    }
    __syncthreads();

    const uint32_t Abase = (uint32_t)__cvta_generic_to_shared(As);
    const uint32_t Bbase = (uint32_t)__cvta_generic_to_shared(Bs);
    const int a_row_l = wr * 64 + (lane & 15);
    const int a_csel = (lane >> 4) << 2;
    const int b_row_l = wc * 32 + (lane & 7) + ((lane >> 4) << 3);
    const int b_csel = (lane & 8) ? 4 : 0;

    float acc[4][4][4];
#pragma unroll
    for (int i = 0; i < 4; ++i)
#pragma unroll
        for (int j = 0; j < 4; ++j)
#pragma unroll
            for (int r = 0; r < 4; ++r) acc[i][j][r] = 0.0f;

#pragma unroll
    for (int ks = 0; ks < 8; ++ks) {
        const int k = ks * 8;
        uint32_t af[4][4], bf[4][2];
#pragma unroll
        for (int mf = 0; mf < 4; ++mf)
            ldsm_x4(af[mf], Abase + (uint32_t)(((a_row_l + mf * 16) * 68 + k + a_csel) * 4));
#pragma unroll
        for (int np = 0; np < 2; ++np) {
            uint32_t r4[4];
            ldsm_x4(r4, Bbase + (uint32_t)(((b_row_l + np * 16) * 68 + k + b_csel) * 4));
            bf[np * 2][0] = r4[0]; bf[np * 2][1] = r4[1];
            bf[np * 2 + 1][0] = r4[2]; bf[np * 2 + 1][1] = r4[3];
        }
#pragma unroll
        for (int mf = 0; mf < 4; ++mf)
#pragma unroll
            for (int nf = 0; nf < 4; ++nf)
                mma_tf32(acc[mf][nf], af[mf], bf[nf]);
    }

    const float g = g_gate[bh];
    float* Cbase = P + ((size_t)bh * SS + mi) * SS + nj;
#pragma unroll
    for (int mf = 0; mf < 4; ++mf) {
#pragma unroll
        for (int nf = 0; nf < 4; ++nf) {
            int row = wr * 64 + mf * 16 + lr;
            int col = wc * 32 + nf * 8 + lc * 2;
            *(float2*)&Cbase[(size_t)row * SS + col] =
                make_float2(acc[mf][nf][0] * g, acc[mf][nf][1] * g);
            *(float2*)&Cbase[(size_t)(row + 8) * SS + col] =
                make_float2(acc[mf][nf][2] * g, acc[mf][nf][3] * g);
        }
    }
}

// ---------- softmax stats (m, 1/Z) + head-mean; NO probs write-back ---------
__global__ __launch_bounds__(256)
void softmax_stats_mean(const float* __restrict__ Pm, float* __restrict__ om)
{
    __shared__ float meanbuf[SS];
    __shared__ float red[8];
    const int i = blockIdx.x, b = blockIdx.y;
    const int tid = threadIdx.x;
    const int lane = tid & 31, wid = tid >> 5;

#pragma unroll
    for (int r = 0; r < 8; ++r) meanbuf[tid + 256 * r] = 0.0f;

    for (int h = 0; h < HH; ++h) {
        const float* row = Pm + ((size_t)(b * HH + h) * SS + i) * SS;
        float s[8];
        float mx = -3.4e38f;
#pragma unroll
        for (int r = 0; r < 8; ++r) { s[r] = row[tid + 256 * r]; mx = fmaxf(mx, s[r]); }
#pragma unroll
        for (int o = 16; o > 0; o >>= 1) mx = fmaxf(mx, __shfl_xor_sync(0xffffffffu, mx, o));
        if (lane == 0) red[wid] = mx;
        __syncthreads();
        float m2 = red[0];
#pragma unroll
        for (int w = 1; w < 8; ++w) m2 = fmaxf(m2, red[w]);
        __syncthreads();

        float sum = 0.0f;
#pragma unroll
        for (int r = 0; r < 8; ++r) { s[r] = fast_exp(s[r] - m2); sum += s[r]; }
#pragma unroll
        for (int o = 16; o > 0; o >>= 1) sum += __shfl_xor_sync(0xffffffffu, sum, o);
        if (lane == 0) red[wid] = sum;
        __syncthreads();
        float tot = 0.0f;
#pragma unroll
        for (int w = 0; w < 8; ++w) tot += red[w];
        float inv = 1.0f / tot;
        if (tid == 0) g_stat[(size_t)(b * HH + h) * SS + i] = make_float2(m2, inv);
#pragma unroll
        for (int r = 0; r < 8; ++r)
            meanbuf[tid + 256 * r] += s[r] * inv * 0.0625f;
        __syncthreads();
    }
    float* o = om + (size_t)(b * SS + i) * SS;
#pragma unroll
    for (int r = 0; r < 8; ++r) o[tid + 256 * r] = meanbuf[tid + 256 * r];
}

// ---------- PV: ctx = softmax(s) @ V, normalizing raw scores on the fly -----
__global__ __launch_bounds__(256)
void pv_flash(const float* __restrict__ P, const float* __restrict__ V,
              float* __restrict__ C)
{
    constexpr int AST = 20;
    constexpr int BST = 72;

    __shared__ uint32_t As[2][128 * AST];
    __shared__ uint32_t Bs[2][16 * BST];

    const int tid = threadIdx.x;
    const int lane = tid & 31, warp = tid >> 5;
    const int wr = warp & 3, wc = warp >> 2;    // 4 x 2 warps; WM=32, WN=32
    const int lr = lane >> 2, lc = lane & 3;

    const int bh = blockIdx.z, b = bh >> 4, h = bh & 15;
    const int bm = blockIdx.y * 128;

    const float* A = P + ((size_t)bh * SS + bm) * SS;
    const float* Bv = V + (size_t)b * SS * EE + h * 64;
    float* Cc = C + (size_t)b * SS * EE + h * 64 + (size_t)bm * EE;

    const int ar = tid >> 2, ac = (tid & 3) * 4;
    const int brw = tid >> 4, bcl = (tid & 15) * 4;

    const float2 st0 = g_stat[(size_t)bh * SS + bm + ar];
    const float2 st1 = g_stat[(size_t)bh * SS + bm + ar + 64];

    float4 av[2], bv;

    auto load_regs = [&](int kt) {
        int k0 = kt * 16;
        av[0] = *(const float4*)&A[(size_t)ar * SS + k0 + ac];
        av[1] = *(const float4*)&A[(size_t)(ar + 64) * SS + k0 + ac];
        bv = *(const float4*)&Bv[(size_t)(k0 + brw) * EE + bcl];
    };
    auto store_smem = [&](int buf) {
        float4 p0, p1;
        p0.x = fast_exp(av[0].x - st0.x) * st0.y;
        p0.y = fast_exp(av[0].y - st0.x) * st0.y;
        p0.z = fast_exp(av[0].z - st0.x) * st0.y;
        p0.w = fast_exp(av[0].w - st0.x) * st0.y;
        p1.x = fast_exp(av[1].x - st1.x) * st1.y;
        p1.y = fast_exp(av[1].y - st1.x) * st1.y;
        p1.z = fast_exp(av[1].z - st1.x) * st1.y;
        p1.w = fast_exp(av[1].w - st1.x) * st1.y;
        *(uint4*)&As[buf][ar * AST + ac] =
            make_uint4(f2tf32(p0.x), f2tf32(p0.y), f2tf32(p0.z), f2tf32(p0.w));
        *(uint4*)&As[buf][(ar + 64) * AST + ac] =
            make_uint4(f2tf32(p1.x), f2tf32(p1.y), f2tf32(p1.z), f2tf32(p1.w));
        *(uint4*)&Bs[buf][brw * BST + bcl] =
            make_uint4(f2tf32(bv.x), f2tf32(bv.y), f2tf32(bv.z), f2tf32(bv.w));
    };

    const int a_row_l = wr * 32 + (lane & 15);
    const int a_csel = (lane >> 4) << 2;
    const uint32_t As_u32[2] = { (uint32_t)__cvta_generic_to_shared(&As[0][0]),
                                 (uint32_t)__cvta_generic_to_shared(&As[1][0]) };

    float acc[2][4][4];
#pragma unroll
    for (int i = 0; i < 2; ++i)
#pragma unroll
        for (int j = 0; j < 4; ++j)
#pragma unroll
            for (int r = 0; r < 4; ++r) acc[i][j][r] = 0.0f;

    const int nk = SS >> 4;   // 128
    load_regs(0);
    store_smem(0);
    __syncthreads();
    int buf = 0;

    for (int kt = 0; kt < nk; ++kt) {
        if (kt + 1 < nk) load_regs(kt + 1);
#pragma unroll
        for (int ks = 0; ks < 2; ++ks) {
            const int k = ks * 8;
            uint32_t af[2][4], bf[4][2];
#pragma unroll
            for (int mf = 0; mf < 2; ++mf)
                ldsm_x4(af[mf], As_u32[buf] +
                        (uint32_t)(((a_row_l + mf * 16) * AST + k + a_csel) * 4));
#pragma unroll
            for (int nf = 0; nf < 4; ++nf) {
                int n = wc * 32 + nf * 8 + lr;
                bf[nf][0] = Bs[buf][(k + lc) * BST + n];
                bf[nf][1] = Bs[buf][(k + 4 + lc) * BST + n];
            }
#pragma unroll
            for (int mf = 0; mf < 2; ++mf)
#pragma unroll
                for (int nf = 0; nf < 4; ++nf)
                    mma_tf32(acc[mf][nf], af[mf], bf[nf]);
        }
        if (kt + 1 < nk) {
            store_smem(buf ^ 1);
            __syncthreads();
            buf ^= 1;
        }
    }

#pragma unroll
    for (int mf = 0; mf < 2; ++mf) {
#pragma unroll
        for (int nf = 0; nf < 4; ++nf) {
            int row = wr * 32 + mf * 16 + lr;
            int col = wc * 32 + nf * 8 + lc * 2;
            *(float2*)&Cc[(size_t)row * EE + col] =
                make_float2(acc[mf][nf][0], acc[mf][nf][1]);
            *(float2*)&Cc[(size_t)(row + 8) * EE + col] =
                make_float2(acc[mf][nf][2], acc[mf][nf][3]);
        }
    }
}

// ---------------- launch ----------------
extern "C" void kernel_launch(void* const* d_in, const int* in_sizes, int n_in,
                              void* d_out, int out_size)
{
    const float* x   = (const float*)d_in[0];
    const float* sf  = (const float*)d_in[1];
    const float* Wq  = (const float*)d_in[2];
    const float* bq  = (const float*)d_in[3];
    const float* Wk  = (const float*)d_in[4];
    const float* bk  = (const float*)d_in[5];
    const float* Wv  = (const float*)d_in[6];
    const float* bv  = (const float*)d_in[7];
    const float* Ws1 = (const float*)d_in[8];
    const float* bs1 = (const float*)d_in[9];
    const float* Ws2 = (const float*)d_in[10];
    const float* bs2 = (const float*)d_in[11];
    const float* Wo  = (const float*)d_in[12];
    const float* bo  = (const float*)d_in[13];
    float* out = (float*)d_out;

    float *pQ, *pK, *pV, *pC, *pP;
    cudaGetSymbolAddress((void**)&pQ, g_Q);
    cudaGetSymbolAddress((void**)&pK, g_K);
    cudaGetSymbolAddress((void**)&pV, g_V);
    cudaGetSymbolAddress((void**)&pC, g_CTX);
    cudaGetSymbolAddress((void**)&pP, g_P);

    // 1. sync gate (tiny)
    gate_kernel<<<1, 256>>>(sf, Ws1, bs1, Ws2, bs2);

    // 2. QKV projections (cp.async tf32 MMA)
    dim3 gqkv(EE / 128, (BB * SS) / 128, 1);
    gemm_nn_ca<<<gqkv, 256>>>(x, Wq, bq, pQ, EE, EE, EE, EE);
    gemm_nn_ca<<<gqkv, 256>>>(x, Wk, bk, pK, EE, EE, EE, EE);
    gemm_nn_ca<<<gqkv, 256>>>(x, Wv, bv, pV, EE, EE, EE, EE);

    // 3. raw scores = gate/sqrt(DH) * Q K^T
    cudaFuncSetAttribute(scores_nt_tf32, cudaFuncAttributeMaxDynamicSharedMemorySize,
                         2 * 128 * 68 * 4);
    scores_nt_tf32<<<dim3(SS / 128, SS / 128, BB * HH), 256, 2 * 128 * 68 * 4>>>(pQ, pK, pP);

    // 4. softmax stats + head-mean -> second half of d_out (no probs write)
    softmax_stats_mean<<<dim3(SS, BB), 256>>>(pP, out + (size_t)BB * SS * EE);

    // 5. ctx = softmax(s) @ V, on-the-fly normalization
    pv_flash<<<dim3(1, SS / 128, BB * HH), 256>>>(pP, pV, pC);

    // 6. out = ctx @ Wo + bo -> first half of d_out
    gemm_nn_ca<<<dim3(EE / 128, (BB * SS) / 128, 1), 256>>>(pC, Wo, bo, out, EE, EE, EE, EE);

    (void)in_sizes; (void)n_in; (void)out_size;
}

// round 5
// speedup vs baseline: 1.1624x; 1.1624x over previous
#include <cuda_runtime.h>
#include <cuda_fp16.h>
#include <cstdint>
#include <cstddef>

#define BB 2
#define SS 2048
#define EE 1024
#define HH 16
#define DHD 64
#define HID 256

// ---------------- scratch (device globals: allocation-free) ----------------
__device__ float  g_Q[(size_t)BB * SS * EE];
__device__ float  g_K[(size_t)BB * SS * EE];
__device__ float  g_V[(size_t)BB * SS * EE];
__device__ float  g_CTX[(size_t)BB * SS * EE];
__device__ __half g_Ph[(size_t)BB * HH * SS * SS];   // 268 MB: p~ = exp(s-8), fp16
__device__ float  g_rs[(size_t)BB * HH * 16 * SS];   // per-(row, jblock) partial sums
__device__ float  g_invZ[(size_t)BB * HH * SS];
__device__ float  g_gate[BB * HH];

// ---------------- helpers ----------------
__device__ __forceinline__ float fast_exp(float x) {
    float y = x * 1.4426950408889634f;
    float n = rintf(y);
    float t = (y - n) * 0.6931471805599453f;
    float p = 1.0f + t * (1.0f + t * (0.5f + t * (0.16666667f +
              t * (0.041666668f + t * 0.008333334f))));
    n = fmaxf(n, -126.0f);
    return p * __int_as_float(((int)n + 127) << 23);
}

__device__ __forceinline__ uint32_t f2tf32(float x) {
    uint32_t r; asm("cvt.rna.tf32.f32 %0, %1;" : "=r"(r) : "f"(x)); return r;
}

__device__ __forceinline__ void mma_tf32(float* d, const uint32_t* a, const uint32_t* b) {
    asm volatile("mma.sync.aligned.m16n8k8.row.col.f32.tf32.tf32.f32 "
                 "{%0,%1,%2,%3}, {%4,%5,%6,%7}, {%8,%9}, {%0,%1,%2,%3};"
                 : "+f"(d[0]), "+f"(d[1]), "+f"(d[2]), "+f"(d[3])
                 : "r"(a[0]), "r"(a[1]), "r"(a[2]), "r"(a[3]),
                   "r"(b[0]), "r"(b[1]));
}

__device__ __forceinline__ void ldsm_x4(uint32_t* r, uint32_t addr) {
    asm volatile("ldmatrix.sync.aligned.m8n8.x4.shared.b16 {%0,%1,%2,%3}, [%4];"
                 : "=r"(r[0]), "=r"(r[1]), "=r"(r[2]), "=r"(r[3]) : "r"(addr));
}

// ---------------- sync gate ----------------
__global__ void gate_kernel(const float* __restrict__ sf,
                            const float* __restrict__ Ws1, const float* __restrict__ bs1,
                            const float* __restrict__ Ws2, const float* __restrict__ bs2)
{
    __shared__ float h1[BB][HID];
    int t = threadIdx.x;
    for (int b = 0; b < BB; ++b) {
        float acc = bs1[t];
        for (int e = 0; e < EE; ++e)
            acc += sf[b * EE + e] * Ws1[(size_t)e * HID + t];
        h1[b][t] = fmaxf(acc, 0.0f);
    }
    __syncthreads();
    if (t < BB * HH) {
        int b = t / HH, h = t % HH;
        float acc = bs2[h];
        for (int k = 0; k < HID; ++k)
            acc += h1[b][k] * Ws2[k * HH + h];
        float sig = 1.0f / (1.0f + __expf(-acc));
        g_gate[b * HH + h] = sig * 0.125f;
    }
}

// ============ NN tf32 GEMM 128x128x16 (R3 variant: reg staging + LDSM) ======
__global__ __launch_bounds__(256)
void gemm_nn_tf32(const float* __restrict__ A, const float* __restrict__ B,
                  const float* __restrict__ bias, float* __restrict__ C,
                  int K, int lda, int ldb, int ldc)
{
    constexpr int AST = 20;
    constexpr int BST = 136;

    __shared__ uint32_t As[2][128 * AST];
    __shared__ uint32_t Bs[2][16 * BST];

    const int tid = threadIdx.x;
    const int lane = tid & 31, warp = tid >> 5;
    const int wr = warp & 1, wc = warp >> 1;
    const int lr = lane >> 2, lc = lane & 3;

    const int bm = blockIdx.y * 128;
    const int bn = blockIdx.x * 128;

    const int ar = tid >> 2, ac = (tid & 3) * 4;
    const int brw = tid >> 5, bcl = (tid & 31) * 4;

    const float* Ag0 = A + (size_t)(bm + ar) * lda + ac;
    const float* Ag1 = Ag0 + (size_t)64 * lda;
    const float* Bg0 = B + (size_t)brw * ldb + bn + bcl;
    const float* Bg1 = Bg0 + (size_t)8 * ldb;

    const int a_row_l = wr * 64 + (lane & 15);
    const int a_csel = (lane >> 4) << 2;
    const uint32_t As_u32[2] = { (uint32_t)__cvta_generic_to_shared(&As[0][0]),
                                 (uint32_t)__cvta_generic_to_shared(&As[1][0]) };

    float4 av0, av1, bv0, bv1;
    auto load_regs = [&](int kt) {
        int k0 = kt * 16;
        av0 = *(const float4*)(Ag0 + k0);
        av1 = *(const float4*)(Ag1 + k0);
        bv0 = *(const float4*)(Bg0 + (size_t)k0 * ldb);
        bv1 = *(const float4*)(Bg1 + (size_t)k0 * ldb);
    };
    auto store_smem = [&](int buf) {
        *(uint4*)&As[buf][ar * AST + ac] =
            make_uint4(f2tf32(av0.x), f2tf32(av0.y), f2tf32(av0.z), f2tf32(av0.w));
        *(uint4*)&As[buf][(ar + 64) * AST + ac] =
            make_uint4(f2tf32(av1.x), f2tf32(av1.y), f2tf32(av1.z), f2tf32(av1.w));
        *(uint4*)&Bs[buf][brw * BST + bcl] =
            make_uint4(f2tf32(bv0.x), f2tf32(bv0.y), f2tf32(bv0.z), f2tf32(bv0.w));
        *(uint4*)&Bs[buf][(brw + 8) * BST + bcl] =
            make_uint4(f2tf32(bv1.x), f2tf32(bv1.y), f2tf32(bv1.z), f2tf32(bv1.w));
    };

    float acc[4][4][4];
#pragma unroll
    for (int i = 0; i < 4; ++i)
#pragma unroll
        for (int j = 0; j < 4; ++j)
#pragma unroll
            for (int r = 0; r < 4; ++r) acc[i][j][r] = 0.0f;

    const int nk = K >> 4;
    load_regs(0);
    store_smem(0);
    __syncthreads();
    int buf = 0;

    for (int kt = 0; kt < nk; ++kt) {
        if (kt + 1 < nk) load_regs(kt + 1);
#pragma unroll
        for (int ks = 0; ks < 2; ++ks) {
            const int k = ks * 8;
            uint32_t af[4][4], bf[4][2];
#pragma unroll
            for (int mf = 0; mf < 4; ++mf)
                ldsm_x4(af[mf], As_u32[buf] +
                        (uint32_t)(((a_row_l + mf * 16) * AST + k + a_csel) * 4));
#pragma unroll
            for (int nf = 0; nf < 4; ++nf) {
                int n = wc * 32 + nf * 8 + lr;
                bf[nf][0] = Bs[buf][(k + lc) * BST + n];
                bf[nf][1] = Bs[buf][(k + 4 + lc) * BST + n];
            }
#pragma unroll
            for (int mf = 0; mf < 4; ++mf)
#pragma unroll
                for (int nf = 0; nf < 4; ++nf)
                    mma_tf32(acc[mf][nf], af[mf], bf[nf]);
        }
        if (kt + 1 < nk) {
            store_smem(buf ^ 1);
            __syncthreads();
            buf ^= 1;
        }
    }

#pragma unroll
    for (int nf = 0; nf < 4; ++nf) {
        int col = bn + wc * 32 + nf * 8 + lc * 2;
        float b0 = 0.0f, b1 = 0.0f;
        if (bias) { b0 = bias[col]; b1 = bias[col + 1]; }
#pragma unroll
        for (int mf = 0; mf < 4; ++mf) {
            int row = bm + wr * 64 + mf * 16 + lr;
            *(float2*)&C[(size_t)row * ldc + col] =
                make_float2(acc[mf][nf][0] + b0, acc[mf][nf][1] + b1);
            *(float2*)&C[(size_t)(row + 8) * ldc + col] =
                make_float2(acc[mf][nf][2] + b0, acc[mf][nf][3] + b1);
        }
    }
}

// ===== scores+exp: p~ = exp(gate*QK^T - 8) -> fp16, + per-jblock row sums ===
__global__ __launch_bounds__(256)
void scores_exp(const float* __restrict__ Q, const float* __restrict__ Kt,
                __half* __restrict__ Ph)
{
    extern __shared__ uint32_t sm[];
    uint32_t* As = sm;              // [128][68] queries
    uint32_t* Bs = sm + 128 * 68;   // [128][68] keys
    __shared__ float rowsum[128];

    const int tid = threadIdx.x;
    const int lane = tid & 31, warp = tid >> 5;
    const int wr = warp & 1, wc = warp >> 1;
    const int lr = lane >> 2, lc = lane & 3;
    const int bh = blockIdx.z, b = bh >> 4, h = bh & 15;
    const int mi = blockIdx.y * 128, nj = blockIdx.x * 128;

    if (tid < 128) rowsum[tid] = 0.0f;

    const float* Ag = Q + (size_t)b * SS * EE + h * 64;
    const float* Bg = Kt + (size_t)b * SS * EE + h * 64;

#pragma unroll
    for (int it = 0; it < 8; ++it) {
        int idx = it * 1024 + tid * 4;
        int r = idx >> 6, k = idx & 63;
        float4 qa = *(const float4*)&Ag[(size_t)(mi + r) * EE + k];
        float4 ka = *(const float4*)&Bg[(size_t)(nj + r) * EE + k];
        *(uint4*)&As[r * 68 + k] = make_uint4(f2tf32(qa.x), f2tf32(qa.y), f2tf32(qa.z), f2tf32(qa.w));
        *(uint4*)&Bs[r * 68 + k] = make_uint4(f2tf32(ka.x), f2tf32(ka.y), f2tf32(ka.z), f2tf32(ka.w));
    }
    __syncthreads();

    const uint32_t Abase = (uint32_t)__cvta_generic_to_shared(As);
    const uint32_t Bbase = (uint32_t)__cvta_generic_to_shared(Bs);
    const int a_row_l = wr * 64 + (lane & 15);
    const int a_csel = (lane >> 4) << 2;
    const int b_row_l = wc * 32 + (lane & 7) + ((lane >> 4) << 3);
    const int b_csel = (lane & 8) ? 4 : 0;

    float acc[4][4][4];
#pragma unroll
    for (int i = 0; i < 4; ++i)
#pragma unroll
        for (int j = 0; j < 4; ++j)
#pragma unroll
            for (int r = 0; r < 4; ++r) acc[i][j][r] = 0.0f;

#pragma unroll
    for (int ks = 0; ks < 8; ++ks) {
        const int k = ks * 8;
        uint32_t af[4][4], bf[4][2];
#pragma unroll
        for (int mf = 0; mf < 4; ++mf)
            ldsm_x4(af[mf], Abase + (uint32_t)(((a_row_l + mf * 16) * 68 + k + a_csel) * 4));
#pragma unroll
        for (int np = 0; np < 2; ++np) {
            uint32_t r4[4];
            ldsm_x4(r4, Bbase + (uint32_t)(((b_row_l + np * 16) * 68 + k + b_csel) * 4));
            bf[np * 2][0] = r4[0]; bf[np * 2][1] = r4[1];
            bf[np * 2 + 1][0] = r4[2]; bf[np * 2 + 1][1] = r4[3];
        }
#pragma unroll
        for (int mf = 0; mf < 4; ++mf)
#pragma unroll
            for (int nf = 0; nf < 4; ++nf)
                mma_tf32(acc[mf][nf], af[mf], bf[nf]);
    }

    // epilogue: p~ = exp(g*s - 8) -> fp16; accumulate row sums
    const float g = g_gate[bh];
    __half* Pb = Ph + ((size_t)bh * SS + mi) * SS + nj;
    float ps0[4], ps1[4];
#pragma unroll
    for (int mf = 0; mf < 4; ++mf) { ps0[mf] = 0.0f; ps1[mf] = 0.0f; }

#pragma unroll
    for (int mf = 0; mf < 4; ++mf) {
        int row = wr * 64 + mf * 16 + lr;
#pragma unroll
        for (int nf = 0; nf < 4; ++nf) {
            int col = wc * 32 + nf * 8 + lc * 2;
            float p0 = fminf(fast_exp(fmaf(acc[mf][nf][0], g, -8.0f)), 60000.0f);
            float p1 = fminf(fast_exp(fmaf(acc[mf][nf][1], g, -8.0f)), 60000.0f);
            float p2 = fminf(fast_exp(fmaf(acc[mf][nf][2], g, -8.0f)), 60000.0f);
            float p3 = fminf(fast_exp(fmaf(acc[mf][nf][3], g, -8.0f)), 60000.0f);
            __half2 w0 = __floats2half2_rn(p0, p1);
            __half2 w1 = __floats2half2_rn(p2, p3);
            *(__half2*)&Pb[(size_t)row * SS + col] = w0;
            *(__half2*)&Pb[(size_t)(row + 8) * SS + col] = w1;
            float2 q0 = __half22float2(w0);     // rounded values for consistent Z
            float2 q1 = __half22float2(w1);
            ps0[mf] += q0.x + q0.y;
            ps1[mf] += q1.x + q1.y;
        }
    }
#pragma unroll
    for (int mf = 0; mf < 4; ++mf) {
#pragma unroll
        for (int o = 1; o < 4; o <<= 1) {
            ps0[mf] += __shfl_xor_sync(0xffffffffu, ps0[mf], o);
            ps1[mf] += __shfl_xor_sync(0xffffffffu, ps1[mf], o);
        }
        if (lc == 0) {
            atomicAdd(&rowsum[wr * 64 + mf * 16 + lr], ps0[mf]);
            atomicAdd(&rowsum[wr * 64 + mf * 16 + lr + 8], ps1[mf]);
        }
    }
    __syncthreads();
    if (tid < 128)
        g_rs[((size_t)bh * 16 + blockIdx.x) * SS + mi + tid] = rowsum[tid];
}

// ---------------- reduce partial sums -> 1/Z ----------------
__global__ __launch_bounds__(256)
void reduce_z()
{
    const int i = blockIdx.x * 256 + threadIdx.x;
    const int bh = blockIdx.y;
    float z = 0.0f;
#pragma unroll
    for (int jb = 0; jb < 16; ++jb)
        z += g_rs[((size_t)bh * 16 + jb) * SS + i];
    g_invZ[(size_t)bh * SS + i] = 1.0f / z;
}

// ---------- PV: ctx = (p~ @ V) * invZ(row), p~ fp16 -> tf32 MMA -------------
__global__ __launch_bounds__(256)
void pv_fp16(const __half* __restrict__ Ph, const float* __restrict__ V,
             float* __restrict__ C)
{
    constexpr int AST = 20;
    constexpr int BST = 72;

    __shared__ uint32_t As[2][128 * AST];
    __shared__ uint32_t Bs[2][16 * BST];

    const int tid = threadIdx.x;
    const int lane = tid & 31, warp = tid >> 5;
    const int wr = warp & 3, wc = warp >> 2;    // 4 x 2 warps; WM=32, WN=32
    const int lr = lane >> 2, lc = lane & 3;

    const int bh = blockIdx.z, b = bh >> 4, h = bh & 15;
    const int bm = blockIdx.y * 128;

    const __half* A = Ph + ((size_t)bh * SS + bm) * SS;
    const float* Bv = V + (size_t)b * SS * EE + h * 64;
    float* Cc = C + (size_t)b * SS * EE + h * 64 + (size_t)bm * EE;

    const int arow = tid >> 1, aseg = (tid & 1) * 8;
    const int brw = tid >> 4, bcl = (tid & 15) * 4;

    uint4 av; float4 bv;
    auto load_regs = [&](int kt) {
        int k0 = kt * 16;
        av = *(const uint4*)&A[(size_t)arow * SS + k0 + aseg];
        bv = *(const float4*)&Bv[(size_t)(k0 + brw) * EE + bcl];
    };
    auto store_smem = [&](int buf) {
        float2 f0 = __half22float2(*reinterpret_cast<__half2*>(&av.x));
        float2 f1 = __half22float2(*reinterpret_cast<__half2*>(&av.y));
        float2 f2 = __half22float2(*reinterpret_cast<__half2*>(&av.z));
        float2 f3 = __half22float2(*reinterpret_cast<__half2*>(&av.w));
        *(uint4*)&As[buf][arow * AST + aseg] =
            make_uint4(f2tf32(f0.x), f2tf32(f0.y), f2tf32(f1.x), f2tf32(f1.y));
        *(uint4*)&As[buf][arow * AST + aseg + 4] =
            make_uint4(f2tf32(f2.x), f2tf32(f2.y), f2tf32(f3.x), f2tf32(f3.y));
        *(uint4*)&Bs[buf][brw * BST + bcl] =
            make_uint4(f2tf32(bv.x), f2tf32(bv.y), f2tf32(bv.z), f2tf32(bv.w));
    };

    const int a_row_l = wr * 32 + (lane & 15);
    const int a_csel = (lane >> 4) << 2;
    const uint32_t As_u32[2] = { (uint32_t)__cvta_generic_to_shared(&As[0][0]),
                                 (uint32_t)__cvta_generic_to_shared(&As[1][0]) };

    float acc[2][4][4];
#pragma unroll
    for (int i = 0; i < 2; ++i)
#pragma unroll
        for (int j = 0; j < 4; ++j)
#pragma unroll
            for (int r = 0; r < 4; ++r) acc[i][j][r] = 0.0f;

    const int nk = SS >> 4;   // 128
    load_regs(0);
    store_smem(0);
    __syncthreads();
    int buf = 0;

    for (int kt = 0; kt < nk; ++kt) {
        if (kt + 1 < nk) load_regs(kt + 1);
#pragma unroll
        for (int ks = 0; ks < 2; ++ks) {
            const int k = ks * 8;
            uint32_t af[2][4], bf[4][2];
#pragma unroll
            for (int mf = 0; mf < 2; ++mf)
                ldsm_x4(af[mf], As_u32[buf] +
                        (uint32_t)(((a_row_l + mf * 16) * AST + k + a_csel) * 4));
#pragma unroll
            for (int nf = 0; nf < 4; ++nf) {
                int n = wc * 32 + nf * 8 + lr;
                bf[nf][0] = Bs[buf][(k + lc) * BST + n];
                bf[nf][1] = Bs[buf][(k + 4 + lc) * BST + n];
            }
#pragma unroll
            for (int mf = 0; mf < 2; ++mf)
#pragma unroll
                for (int nf = 0; nf < 4; ++nf)
                    mma_tf32(acc[mf][nf], af[mf], bf[nf]);
        }
        if (kt + 1 < nk) {
            store_smem(buf ^ 1);
            __syncthreads();
            buf ^= 1;
        }
    }

#pragma unroll
    for (int mf = 0; mf < 2; ++mf) {
        int row = wr * 32 + mf * 16 + lr;
        float iz0 = g_invZ[(size_t)bh * SS + bm + row];
        float iz1 = g_invZ[(size_t)bh * SS + bm + row + 8];
#pragma unroll
        for (int nf = 0; nf < 4; ++nf) {
            int col = wc * 32 + nf * 8 + lc * 2;
            *(float2*)&Cc[(size_t)row * EE + col] =
                make_float2(acc[mf][nf][0] * iz0, acc[mf][nf][1] * iz0);
            *(float2*)&Cc[(size_t)(row + 8) * EE + col] =
                make_float2(acc[mf][nf][2] * iz1, acc[mf][nf][3] * iz1);
        }
    }
}

// ---------- attn mean over heads: out[b,i,j] = sum_h p~ * invZ_h / 16 -------
__global__ __launch_bounds__(256)
void mean_kernel(const __half* __restrict__ Ph, float* __restrict__ om)
{
    const int i = blockIdx.x, b = blockIdx.y;
    const int tid = threadIdx.x;

    float2 m[4];
#pragma unroll
    for (int r = 0; r < 4; ++r) m[r] = make_float2(0.0f, 0.0f);

    for (int h = 0; h < HH; ++h) {
        const __half2* row2 = (const __half2*)(Ph + ((size_t)(b * HH + h) * SS + i) * SS);
        float w = g_invZ[(size_t)(b * HH + h) * SS + i] * 0.0625f;
#pragma unroll
        for (int r = 0; r < 4; ++r) {
            float2 v = __half22float2(row2[tid + 256 * r]);
            m[r].x = fmaf(w, v.x, m[r].x);
            m[r].y = fmaf(w, v.y, m[r].y);
        }
    }
    float2* o2 = (float2*)(om + (size_t)(b * SS + i) * SS);
#pragma unroll
    for (int r = 0; r < 4; ++r) o2[tid + 256 * r] = m[r];
}

// ---------------- launch ----------------
extern "C" void kernel_launch(void* const* d_in, const int* in_sizes, int n_in,
                              void* d_out, int out_size)
{
    const float* x   = (const float*)d_in[0];
    const float* sf  = (const float*)d_in[1];
    const float* Wq  = (const float*)d_in[2];
    const float* bq  = (const float*)d_in[3];
    const float* Wk  = (const float*)d_in[4];
    const float* bk  = (const float*)d_in[5];
    const float* Wv  = (const float*)d_in[6];
    const float* bv  = (const float*)d_in[7];
    const float* Ws1 = (const float*)d_in[8];
    const float* bs1 = (const float*)d_in[9];
    const float* Ws2 = (const float*)d_in[10];
    const float* bs2 = (const float*)d_in[11];
    const float* Wo  = (const float*)d_in[12];
    const float* bo  = (const float*)d_in[13];
    float* out = (float*)d_out;

    float *pQ, *pK, *pV, *pC;
    __half* pPh;
    cudaGetSymbolAddress((void**)&pQ, g_Q);
    cudaGetSymbolAddress((void**)&pK, g_K);
    cudaGetSymbolAddress((void**)&pV, g_V);
    cudaGetSymbolAddress((void**)&pC, g_CTX);
    cudaGetSymbolAddress((void**)&pPh, g_Ph);

    // 1. sync gate (tiny)
    gate_kernel<<<1, 256>>>(sf, Ws1, bs1, Ws2, bs2);

    // 2. QKV projections
    dim3 gqkv(EE / 128, (BB * SS) / 128, 1);
    gemm_nn_tf32<<<gqkv, 256>>>(x, Wq, bq, pQ, EE, EE, EE, EE);
    gemm_nn_tf32<<<gqkv, 256>>>(x, Wk, bk, pK, EE, EE, EE, EE);
    gemm_nn_tf32<<<gqkv, 256>>>(x, Wv, bv, pV, EE, EE, EE, EE);

    // 3. scores + exp -> fp16 p~, partial row sums
    cudaFuncSetAttribute(scores_exp, cudaFuncAttributeMaxDynamicSharedMemorySize,
                         2 * 128 * 68 * 4);
    scores_exp<<<dim3(SS / 128, SS / 128, BB * HH), 256, 2 * 128 * 68 * 4>>>(pQ, pK, pPh);

    // 4. reduce -> 1/Z
    reduce_z<<<dim3(SS / 256, BB * HH), 256>>>();

    // 5. ctx = (p~ @ V) * invZ
    pv_fp16<<<dim3(1, SS / 128, BB * HH), 256>>>(pPh, pV, pC);

    // 6. attn mean -> second half of d_out
    mean_kernel<<<dim3(SS, BB), 256>>>(pPh, out + (size_t)BB * SS * EE);

    // 7. out = ctx @ Wo + bo -> first half of d_out
    gemm_nn_tf32<<<dim3(EE / 128, (BB * SS) / 128, 1), 256>>>(pC, Wo, bo, out, EE, EE, EE, EE);

    (void)in_sizes; (void)n_in; (void)out_size;
}

// round 7
// speedup vs baseline: 1.6698x; 1.4366x over previous
#include <cuda_runtime.h>
#include <cuda_fp16.h>
#include <cstdint>
#include <cstddef>

#define BB 2
#define SS 2048
#define EE 1024
#define HH 16
#define DHD 64
#define HID 256

// ---------------- scratch (device globals: allocation-free) ----------------
__device__ __half g_Xh[(size_t)BB * SS * EE];
__device__ __half g_Wh[4][(size_t)EE * EE];
__device__ __half g_Qh[(size_t)BB * SS * EE];
__device__ __half g_Kh[(size_t)BB * SS * EE];
__device__ __half g_Vh[(size_t)BB * SS * EE];
__device__ float  g_CTX[(size_t)BB * SS * EE];
__device__ __half g_Ph[(size_t)BB * HH * SS * SS];   // 268 MB p~ = exp(s-8)
__device__ float  g_rs[(size_t)BB * HH * 16 * SS];
__device__ float  g_invZ[(size_t)BB * HH * SS];
__device__ float  g_gate[BB * HH];

// ---------------- helpers ----------------
__device__ __forceinline__ float fast_exp(float x) {
    float y = x * 1.4426950408889634f;
    float n = rintf(y);
    float t = (y - n) * 0.6931471805599453f;
    float p = 1.0f + t * (1.0f + t * (0.5f + t * (0.16666667f +
              t * (0.041666668f + t * 0.008333334f))));
    n = fmaxf(n, -126.0f);
    return p * __int_as_float(((int)n + 127) << 23);
}

__device__ __forceinline__ void mma_f16(float* d, const uint32_t* a, const uint32_t* b) {
    asm volatile("mma.sync.aligned.m16n8k16.row.col.f32.f16.f16.f32 "
                 "{%0,%1,%2,%3}, {%4,%5,%6,%7}, {%8,%9}, {%0,%1,%2,%3};"
                 : "+f"(d[0]), "+f"(d[1]), "+f"(d[2]), "+f"(d[3])
                 : "r"(a[0]), "r"(a[1]), "r"(a[2]), "r"(a[3]),
                   "r"(b[0]), "r"(b[1]));
}

__device__ __forceinline__ void ldsm_x4(uint32_t* r, uint32_t addr) {
    asm volatile("ldmatrix.sync.aligned.m8n8.x4.shared.b16 {%0,%1,%2,%3}, [%4];"
                 : "=r"(r[0]), "=r"(r[1]), "=r"(r[2]), "=r"(r[3]) : "r"(addr));
}
__device__ __forceinline__ void ldsm_x4_t(uint32_t* r, uint32_t addr) {
    asm volatile("ldmatrix.sync.aligned.m8n8.x4.trans.shared.b16 {%0,%1,%2,%3}, [%4];"
                 : "=r"(r[0]), "=r"(r[1]), "=r"(r[2]), "=r"(r[3]) : "r"(addr));
}

__device__ __forceinline__ void cp_async16(uint32_t smem, const void* g) {
    asm volatile("cp.async.cg.shared.global [%0], [%1], 16;" :: "r"(smem), "l"(g));
}
__device__ __forceinline__ void cp_commit() { asm volatile("cp.async.commit_group;"); }
__device__ __forceinline__ void cp_wait0()  { asm volatile("cp.async.wait_group 0;"); }
__device__ __forceinline__ void cp_wait1()  { asm volatile("cp.async.wait_group 1;"); }

__device__ __forceinline__ uint32_t h2u(__half2 h) { return *(uint32_t*)&h; }

// ---------------- f32 -> f16 conversion ----------------
__global__ void f2h(const float* __restrict__ s, __half* __restrict__ d, int n4)
{
    int i = blockIdx.x * blockDim.x + threadIdx.x;
    if (i < n4) {
        float4 v = ((const float4*)s)[i];
        ((__half2*)d)[2 * i]     = __floats2half2_rn(v.x, v.y);
        ((__half2*)d)[2 * i + 1] = __floats2half2_rn(v.z, v.w);
    }
}

// ---------------- sync gate ----------------
__global__ void gate_kernel(const float* __restrict__ sf,
                            const float* __restrict__ Ws1, const float* __restrict__ bs1,
                            const float* __restrict__ Ws2, const float* __restrict__ bs2)
{
    __shared__ float h1[BB][HID];
    int t = threadIdx.x;
    for (int b = 0; b < BB; ++b) {
        float acc = bs1[t];
        for (int e = 0; e < EE; ++e)
            acc += sf[b * EE + e] * Ws1[(size_t)e * HID + t];
        h1[b][t] = fmaxf(acc, 0.0f);
    }
    __syncthreads();
    if (t < BB * HH) {
        int b = t / HH, h = t % HH;
        float acc = bs2[h];
        for (int k = 0; k < HID; ++k)
            acc += h1[b][k] * Ws2[k * HH + h];
        float sig = 1.0f / (1.0f + __expf(-acc));
        g_gate[b * HH + h] = sig * 0.125f;
    }
}

// ======= fp16 MMA GEMM 128x128x32: C = A[M,K] @ B[K,N] + bias ==============
// A_HALF: A fp16 via cp.async; else fp32 with cvt staging. OUT_HALF: C fp16.
template<bool A_HALF, bool OUT_HALF>
__global__ __launch_bounds__(256)
void gemm_h(const void* __restrict__ Ap, const __half* __restrict__ Bh,
            const float* __restrict__ bias, void* __restrict__ Cp)
{
    constexpr int SA = 40;    // halves per A row (80 B = 20 words)
    constexpr int SB = 136;   // halves per B row (272 B = 68 words)
    __shared__ __half As[2][128 * SA];
    __shared__ __half Bs[2][32 * SB];

    const int tid = threadIdx.x;
    const int lane = tid & 31, warp = tid >> 5;
    const int wr = warp & 1, wc = warp >> 1;    // 2x4 warps; WM=64, WN=32
    const int lr = lane >> 2, lc = lane & 3;
    const int bm = blockIdx.y * 128, bn = blockIdx.x * 128;

    const uint32_t AsB[2] = { (uint32_t)__cvta_generic_to_shared(&As[0][0]),
                              (uint32_t)__cvta_generic_to_shared(&As[1][0]) };
    const uint32_t BsB[2] = { (uint32_t)__cvta_generic_to_shared(&Bs[0][0]),
                              (uint32_t)__cvta_generic_to_shared(&Bs[1][0]) };

    // B cp.async: 32 rows x 16 chunks = 512, 2 per thread
    const int brow0 = tid >> 4, bch0 = tid & 15;      // chunk c = tid
    const int brow1 = (tid + 256) >> 4, bch1 = tid & 15;
    auto issueB = [&](int kt, int buf) {
        cp_async16(BsB[buf] + (uint32_t)((brow0 * SB + bch0 * 8) * 2),
                   Bh + (size_t)(kt * 32 + brow0) * EE + bn + bch0 * 8);
        cp_async16(BsB[buf] + (uint32_t)((brow1 * SB + bch1 * 8) * 2),
                   Bh + (size_t)(kt * 32 + brow1) * EE + bn + bch1 * 8);
    };

    // A: fp16 cp.async path (2 chunks) or fp32 staging path
    const __half* Ah = (const __half*)Ap;
    const float*  Af = (const float*)Ap;
    const int arow0 = tid >> 2, ach0 = tid & 3;       // half chunks
    const int arow1 = (tid + 256) >> 2, ach1 = tid & 3;
    const int frow = tid >> 1, fcol = (tid & 1) * 16; // fp32 staging
    float4 av[4];

    auto issueA_h = [&](int kt, int buf) {
        cp_async16(AsB[buf] + (uint32_t)((arow0 * SA + ach0 * 8) * 2),
                   Ah + (size_t)(bm + arow0) * EE + kt * 32 + ach0 * 8);
        cp_async16(AsB[buf] + (uint32_t)((arow1 * SA + ach1 * 8) * 2),
                   Ah + (size_t)(bm + arow1) * EE + kt * 32 + ach1 * 8);
    };
    auto loadA_f = [&](int kt) {
#pragma unroll
        for (int i = 0; i < 4; ++i)
            av[i] = *(const float4*)&Af[(size_t)(bm + frow) * EE + kt * 32 + fcol + i * 4];
    };
    auto storeA_f = [&](int buf) {
#pragma unroll
        for (int i = 0; i < 4; ++i) {
            __half2 h0 = __floats2half2_rn(av[i].x, av[i].y);
            __half2 h1 = __floats2half2_rn(av[i].z, av[i].w);
            *(uint2*)&As[buf][frow * SA + fcol + i * 4] = make_uint2(h2u(h0), h2u(h1));
        }
    };

    float acc[4][4][4];
#pragma unroll
    for (int i = 0; i < 4; ++i)
#pragma unroll
        for (int j = 0; j < 4; ++j)
#pragma unroll
            for (int r = 0; r < 4; ++r) acc[i][j][r] = 0.0f;

    const int a_row_l = wr * 64 + (lane & 15);
    const int a_koff = (lane >> 4) * 8;
    const int b_krow = (lane & 7) + ((lane >> 3) & 1) * 8;
    const int b_noff = (lane >> 4) * 8;

    const int nk = EE / 32;   // 32
    if (A_HALF) { issueA_h(0, 0); issueB(0, 0); cp_commit(); }
    else        { issueB(0, 0); cp_commit(); loadA_f(0); storeA_f(0); }

    for (int kt = 0; kt < nk; ++kt) {
        const int buf = kt & 1;
        if (kt + 1 < nk) {
            if (A_HALF) { issueA_h(kt + 1, buf ^ 1); issueB(kt + 1, buf ^ 1); cp_commit(); }
            else        { issueB(kt + 1, buf ^ 1); cp_commit(); loadA_f(kt + 1); }
            cp_wait1();
        } else cp_wait0();
        __syncthreads();

#pragma unroll
        for (int ks = 0; ks < 2; ++ks) {
            const int k0 = ks * 16;
            uint32_t af[4][4], bf[4][2];
#pragma unroll
            for (int mf = 0; mf < 4; ++mf)
                ldsm_x4(af[mf], AsB[buf] +
                        (uint32_t)(((a_row_l + mf * 16) * SA + k0 + a_koff) * 2));
#pragma unroll
            for (int np = 0; np < 2; ++np) {
                uint32_t r4[4];
                int n0 = wc * 32 + np * 16;
                ldsm_x4_t(r4, BsB[buf] +
                          (uint32_t)(((k0 + b_krow) * SB + n0 + b_noff) * 2));
                bf[np * 2][0] = r4[0]; bf[np * 2][1] = r4[1];
                bf[np * 2 + 1][0] = r4[2]; bf[np * 2 + 1][1] = r4[3];
            }
#pragma unroll
            for (int mf = 0; mf < 4; ++mf)
#pragma unroll
                for (int nf = 0; nf < 4; ++nf)
                    mma_f16(acc[mf][nf], af[mf], bf[nf]);
        }
        if (!A_HALF && kt + 1 < nk) storeA_f(buf ^ 1);
        __syncthreads();
    }

    // epilogue
#pragma unroll
    for (int nf = 0; nf < 4; ++nf) {
        int col = bn + wc * 32 + nf * 8 + lc * 2;
        float b0 = bias[col], b1 = bias[col + 1];
#pragma unroll
        for (int mf = 0; mf < 4; ++mf) {
            int row = bm + wr * 64 + mf * 16 + lr;
            if (OUT_HALF) {
                __half* Ch = (__half*)Cp;
                *(__half2*)&Ch[(size_t)row * EE + col] =
                    __floats2half2_rn(acc[mf][nf][0] + b0, acc[mf][nf][1] + b1);
                *(__half2*)&Ch[(size_t)(row + 8) * EE + col] =
                    __floats2half2_rn(acc[mf][nf][2] + b0, acc[mf][nf][3] + b1);
            } else {
                float* Cf = (float*)Cp;
                *(float2*)&Cf[(size_t)row * EE + col] =
                    make_float2(acc[mf][nf][0] + b0, acc[mf][nf][1] + b1);
                *(float2*)&Cf[(size_t)(row + 8) * EE + col] =
                    make_float2(acc[mf][nf][2] + b0, acc[mf][nf][3] + b1);
            }
        }
    }
}

// ===== scores+exp (fp16 MMA): p~ = exp(gate*QK^T - 8) -> fp16, row sums =====
__global__ __launch_bounds__(256)
void scores_exp_h(const __half* __restrict__ Qh, const __half* __restrict__ Kh,
                  __half* __restrict__ Ph)
{
    constexpr int ST = 72;   // halves per row (144 B = 36 words)
    __shared__ __half Qs[128 * ST];
    __shared__ __half Ks[128 * ST];
    __shared__ float rowsum[128];

    const int tid = threadIdx.x;
    const int lane = tid & 31, warp = tid >> 5;
    const int wr = warp & 1, wc = warp >> 1;
    const int lr = lane >> 2, lc = lane & 3;
    const int bh = blockIdx.z, b = bh >> 4, h = bh & 15;
    const int mi = blockIdx.y * 128, nj = blockIdx.x * 128;

    if (tid < 128) rowsum[tid] = 0.0f;

    const uint32_t QsB = (uint32_t)__cvta_generic_to_shared(Qs);
    const uint32_t KsB = (uint32_t)__cvta_generic_to_shared(Ks);

#pragma unroll
    for (int i = 0; i < 4; ++i) {
        int c = tid + i * 256;
        int row = c >> 3, ch = c & 7;
        cp_async16(QsB + (uint32_t)((row * ST + ch * 8) * 2),
                   Qh + (size_t)(b * SS + mi + row) * EE + h * 64 + ch * 8);
        cp_async16(KsB + (uint32_t)((row * ST + ch * 8) * 2),
                   Kh + (size_t)(b * SS + nj + row) * EE + h * 64 + ch * 8);
    }
    cp_commit();
    cp_wait0();
    __syncthreads();

    const int a_row_l = wr * 64 + (lane & 15);
    const int a_koff = (lane >> 4) * 8;
    const int b_nrow = (lane & 7) + (lane >> 4) * 8;
    const int b_koff = ((lane >> 3) & 1) * 8;

    float acc[4][4][4];
#pragma unroll
    for (int i = 0; i < 4; ++i)
#pragma unroll
        for (int j = 0; j < 4; ++j)
#pragma unroll
            for (int r = 0; r < 4; ++r) acc[i][j][r] = 0.0f;

#pragma unroll
    for (int ks = 0; ks < 4; ++ks) {
        const int k0 = ks * 16;
        uint32_t af[4][4], bf[4][2];
#pragma unroll
        for (int mf = 0; mf < 4; ++mf)
            ldsm_x4(af[mf], QsB + (uint32_t)(((a_row_l + mf * 16) * ST + k0 + a_koff) * 2));
#pragma unroll
        for (int np = 0; np < 2; ++np) {
            uint32_t r4[4];
            int n0 = wc * 32 + np * 16;
            ldsm_x4(r4, KsB + (uint32_t)(((n0 + b_nrow) * ST + k0 + b_koff) * 2));
            bf[np * 2][0] = r4[0]; bf[np * 2][1] = r4[1];
            bf[np * 2 + 1][0] = r4[2]; bf[np * 2 + 1][1] = r4[3];
        }
#pragma unroll
        for (int mf = 0; mf < 4; ++mf)
#pragma unroll
            for (int nf = 0; nf < 4; ++nf)
                mma_f16(acc[mf][nf], af[mf], bf[nf]);
    }

    const float g = g_gate[bh];
    __half* Pb = Ph + ((size_t)bh * SS + mi) * SS + nj;
    float ps0[4], ps1[4];
#pragma unroll
    for (int mf = 0; mf < 4; ++mf) { ps0[mf] = 0.0f; ps1[mf] = 0.0f; }

#pragma unroll
    for (int mf = 0; mf < 4; ++mf) {
        int row = wr * 64 + mf * 16 + lr;
#pragma unroll
        for (int nf = 0; nf < 4; ++nf) {
            int col = wc * 32 + nf * 8 + lc * 2;
            float p0 = fminf(fast_exp(fmaf(acc[mf][nf][0], g, -8.0f)), 60000.0f);
            float p1 = fminf(fast_exp(fmaf(acc[mf][nf][1], g, -8.0f)), 60000.0f);
            float p2 = fminf(fast_exp(fmaf(acc[mf][nf][2], g, -8.0f)), 60000.0f);
            float p3 = fminf(fast_exp(fmaf(acc[mf][nf][3], g, -8.0f)), 60000.0f);
            __half2 w0 = __floats2half2_rn(p0, p1);
            __half2 w1 = __floats2half2_rn(p2, p3);
            *(__half2*)&Pb[(size_t)row * SS + col] = w0;
            *(__half2*)&Pb[(size_t)(row + 8) * SS + col] = w1;
            float2 q0 = __half22float2(w0);
            float2 q1 = __half22float2(w1);
            ps0[mf] += q0.x + q0.y;
            ps1[mf] += q1.x + q1.y;
        }
    }
#pragma unroll
    for (int mf = 0; mf < 4; ++mf) {
#pragma unroll
        for (int o = 1; o < 4; o <<= 1) {
            ps0[mf] += __shfl_xor_sync(0xffffffffu, ps0[mf], o);
            ps1[mf] += __shfl_xor_sync(0xffffffffu, ps1[mf], o);
        }
        if (lc == 0) {
            atomicAdd(&rowsum[wr * 64 + mf * 16 + lr], ps0[mf]);
            atomicAdd(&rowsum[wr * 64 + mf * 16 + lr + 8], ps1[mf]);
        }
    }
    __syncthreads();
    if (tid < 128)
        g_rs[((size_t)bh * 16 + blockIdx.x) * SS + mi + tid] = rowsum[tid];
}

// ---------------- reduce partial sums -> 1/Z ----------------
__global__ __launch_bounds__(256)
void reduce_z()
{
    const int i = blockIdx.x * 256 + threadIdx.x;
    const int bh = blockIdx.y;
    float z = 0.0f;
#pragma unroll
    for (int jb = 0; jb < 16; ++jb)
        z += g_rs[((size_t)bh * 16 + jb) * SS + i];
    g_invZ[(size_t)bh * SS + i] = 1.0f / z;
}

// ---------- PV (fp16 MMA): ctx = (p~ @ V) * invZ(row), fp32 out -------------
__global__ __launch_bounds__(256)
void pv_h(const __half* __restrict__ Ph, const __half* __restrict__ Vh,
          float* __restrict__ C)
{
    constexpr int SA = 40;
    constexpr int SB = 72;
    __shared__ __half As[2][128 * SA];
    __shared__ __half Bs[2][32 * SB];

    const int tid = threadIdx.x;
    const int lane = tid & 31, warp = tid >> 5;
    const int wr = warp & 3, wc = warp >> 2;    // 4x2 warps; WM=32, WN=32
    const int lr = lane >> 2, lc = lane & 3;

    const int bh = blockIdx.z, b = bh >> 4, h = bh & 15;
    const int bm = blockIdx.y * 128;

    const uint32_t AsB[2] = { (uint32_t)__cvta_generic_to_shared(&As[0][0]),
                              (uint32_t)__cvta_generic_to_shared(&As[1][0]) };
    const uint32_t BsB[2] = { (uint32_t)__cvta_generic_to_shared(&Bs[0][0]),
                              (uint32_t)__cvta_generic_to_shared(&Bs[1][0]) };

    const int arow0 = tid >> 2, ach0 = tid & 3;
    const int arow1 = (tid + 256) >> 2, ach1 = tid & 3;
    const int brow = tid >> 3, bch = tid & 7;   // 32 rows x 8 chunks = 256

    auto issue = [&](int kt, int buf) {
        cp_async16(AsB[buf] + (uint32_t)((arow0 * SA + ach0 * 8) * 2),
                   Ph + ((size_t)bh * SS + bm + arow0) * SS + kt * 32 + ach0 * 8);
        cp_async16(AsB[buf] + (uint32_t)((arow1 * SA + ach1 * 8) * 2),
                   Ph + ((size_t)bh * SS + bm + arow1) * SS + kt * 32 + ach1 * 8);
        cp_async16(BsB[buf] + (uint32_t)((brow * SB + bch * 8) * 2),
                   Vh + (size_t)(b * SS + kt * 32 + brow) * EE + h * 64 + bch * 8);
        cp_commit();
    };

    const int a_row_l = wr * 32 + (lane & 15);
    const int a_koff = (lane >> 4) * 8;
    const int b_krow = (lane & 7) + ((lane >> 3) & 1) * 8;
    const int b_noff = (lane >> 4) * 8;

    float acc[2][4][4];
#pragma unroll
    for (int i = 0; i < 2; ++i)
#pragma unroll
        for (int j = 0; j < 4; ++j)
#pragma unroll
            for (int r = 0; r < 4; ++r) acc[i][j][r] = 0.0f;

    const int nk = SS / 32;   // 64
    issue(0, 0);

    for (int kt = 0; kt < nk; ++kt) {
        const int buf = kt & 1;
        if (kt + 1 < nk) { issue(kt + 1, buf ^ 1); cp_wait1(); }
        else cp_wait0();
        __syncthreads();

#pragma unroll
        for (int ks = 0; ks < 2; ++ks) {
            const int k0 = ks * 16;
            uint32_t af[2][4], bf[4][2];
#pragma unroll
            for (int mf = 0; mf < 2; ++mf)
                ldsm_x4(af[mf], AsB[buf] +
                        (uint32_t)(((a_row_l + mf * 16) * SA + k0 + a_koff) * 2));
#pragma unroll
            for (int np = 0; np < 2; ++np) {
                uint32_t r4[4];
                int n0 = wc * 32 + np * 16;
                ldsm_x4_t(r4, BsB[buf] +
                          (uint32_t)(((k0 + b_krow) * SB + n0 + b_noff) * 2));
                bf[np * 2][0] = r4[0]; bf[np * 2][1] = r4[1];
                bf[np * 2 + 1][0] = r4[2]; bf[np * 2 + 1][1] = r4[3];
            }
#pragma unroll
            for (int mf = 0; mf < 2; ++mf)
#pragma unroll
                for (int nf = 0; nf < 4; ++nf)
                    mma_f16(acc[mf][nf], af[mf], bf[nf]);
        }
        __syncthreads();
    }

    float* Cc = C + (size_t)b * SS * EE + h * 64 + (size_t)bm * EE;
#pragma unroll
    for (int mf = 0; mf < 2; ++mf) {
        int row = wr * 32 + mf * 16 + lr;
        float iz0 = g_invZ[(size_t)bh * SS + bm + row];
        float iz1 = g_invZ[(size_t)bh * SS + bm + row + 8];
#pragma unroll
        for (int nf = 0; nf < 4; ++nf) {
            int col = wc * 32 + nf * 8 + lc * 2;
            *(float2*)&Cc[(size_t)row * EE + col] =
                make_float2(acc[mf][nf][0] * iz0, acc[mf][nf][1] * iz0);
            *(float2*)&Cc[(size_t)(row + 8) * EE + col] =
                make_float2(acc[mf][nf][2] * iz1, acc[mf][nf][3] * iz1);
        }
    }
}

// ---------- attn mean over heads: out[b,i,j] = sum_h p~ * invZ_h / 16 -------
__global__ __launch_bounds__(256)
void mean_kernel(const __half* __restrict__ Ph, float* __restrict__ om)
{
    const int i = blockIdx.x, b = blockIdx.y;
    const int tid = threadIdx.x;

    float2 m[4];
#pragma unroll
    for (int r = 0; r < 4; ++r) m[r] = make_float2(0.0f, 0.0f);

    for (int h = 0; h < HH; ++h) {
        const __half2* row2 = (const __half2*)(Ph + ((size_t)(b * HH + h) * SS + i) * SS);
        float w = g_invZ[(size_t)(b * HH + h) * SS + i] * 0.0625f;
#pragma unroll
        for (int r = 0; r < 4; ++r) {
            float2 v = __half22float2(row2[tid + 256 * r]);
            m[r].x = fmaf(w, v.x, m[r].x);
            m[r].y = fmaf(w, v.y, m[r].y);
        }
    }
    float2* o2 = (float2*)(om + (size_t)(b * SS + i) * SS);
#pragma unroll
    for (int r = 0; r < 4; ++r) o2[tid + 256 * r] = m[r];
}

// ---------------- launch ----------------
extern "C" void kernel_launch(void* const* d_in, const int* in_sizes, int n_in,
                              void* d_out, int out_size)
{
    const float* x   = (const float*)d_in[0];
    const float* sf  = (const float*)d_in[1];
    const float* Wq  = (const float*)d_in[2];
    const float* bq  = (const float*)d_in[3];
    const float* Wk  = (const float*)d_in[4];
    const float* bk  = (const float*)d_in[5];
    const float* Wv  = (const float*)d_in[6];
    const float* bv  = (const float*)d_in[7];
    const float* Ws1 = (const float*)d_in[8];
    const float* bs1 = (const float*)d_in[9];
    const float* Ws2 = (const float*)d_in[10];
    const float* bs2 = (const float*)d_in[11];
    const float* Wo  = (const float*)d_in[12];
    const float* bo  = (const float*)d_in[13];
    float* out = (float*)d_out;

    __half *pXh, *pWh, *pQh, *pKh, *pVh, *pPh;
    float *pC;
    cudaGetSymbolAddress((void**)&pXh, g_Xh);
    cudaGetSymbolAddress((void**)&pWh, g_Wh);
    cudaGetSymbolAddress((void**)&pQh, g_Qh);
    cudaGetSymbolAddress((void**)&pKh, g_Kh);
    cudaGetSymbolAddress((void**)&pVh, g_Vh);
    cudaGetSymbolAddress((void**)&pPh, g_Ph);
    cudaGetSymbolAddress((void**)&pC, g_CTX);

    const size_t WSZ = (size_t)EE * EE;
    const int XN4 = (BB * SS * EE) / 4;      // 1,048,576
    const int WN4 = (EE * EE) / 4;           // 262,144

    // 0. conversions + gate
    f2h<<<XN4 / 256, 256>>>(x, pXh, XN4);
    f2h<<<WN4 / 256, 256>>>(Wq, pWh + 0 * WSZ, WN4);
    f2h<<<WN4 / 256, 256>>>(Wk, pWh + 1 * WSZ, WN4);
    f2h<<<WN4 / 256, 256>>>(Wv, pWh + 2 * WSZ, WN4);
    f2h<<<WN4 / 256, 256>>>(Wo, pWh + 3 * WSZ, WN4);
    gate_kernel<<<1, 256>>>(sf, Ws1, bs1, Ws2, bs2);

    // 1. QKV projections (fp16 MMA, fp16 out)
    dim3 gqkv(EE / 128, (BB * SS) / 128);
    gemm_h<true, true><<<gqkv, 256>>>(pXh, pWh + 0 * WSZ, bq, pQh);
    gemm_h<true, true><<<gqkv, 256>>>(pXh, pWh + 1 * WSZ, bk, pKh);
    gemm_h<true, true><<<gqkv, 256>>>(pXh, pWh + 2 * WSZ, bv, pVh);

    // 2. scores + exp -> fp16 p~, partial row sums
    scores_exp_h<<<dim3(SS / 128, SS / 128, BB * HH), 256>>>(pQh, pKh, pPh);

    // 3. reduce -> 1/Z
    reduce_z<<<dim3(SS / 256, BB * HH), 256>>>();

    // 4. ctx = (p~ @ V) * invZ  (fp32 ctx)
    pv_h<<<dim3(1, SS / 128, BB * HH), 256>>>(pPh, pVh, pC);

    // 5. attn mean -> second half of d_out
    mean_kernel<<<dim3(SS, BB), 256>>>(pPh, out + (size_t)BB * SS * EE);

    // 6. out = ctx @ Wo + bo (fp32 A staging, fp32 out)
    gemm_h<false, false><<<gqkv, 256>>>(pC, pWh + 3 * WSZ, bo, out);

    (void)in_sizes; (void)n_in; (void)out_size;
}

// round 8
// speedup vs baseline: 1.7948x; 1.0748x over previous
#include <cuda_runtime.h>
#include <cuda_fp16.h>
#include <cstdint>
#include <cstddef>

#define BB 2
#define SS 2048
#define EE 1024
#define HH 16
#define DHD 64
#define HID 256

// ---------------- scratch (device globals: allocation-free) ----------------
__device__ __half g_Xh[(size_t)BB * SS * EE];
__device__ __half g_Wh[4][(size_t)EE * EE];
__device__ __half g_Qh[(size_t)BB * SS * EE];
__device__ __half g_Kh[(size_t)BB * SS * EE];
__device__ __half g_Vh[(size_t)BB * SS * EE];
__device__ float  g_CTX[(size_t)BB * SS * EE];
__device__ __half g_Ph[(size_t)BB * HH * SS * SS];   // 268 MB p~ = exp(s-8)
__device__ float  g_invZ[(size_t)BB * HH * SS];
__device__ float  g_gate[BB * HH];

// ---------------- helpers ----------------
__device__ __forceinline__ float fast_exp(float x) {
    float y = x * 1.4426950408889634f;
    float n = rintf(y);
    float t = (y - n) * 0.6931471805599453f;
    float p = 1.0f + t * (1.0f + t * (0.5f + t * (0.16666667f +
              t * (0.041666668f + t * 0.008333334f))));
    n = fmaxf(n, -126.0f);
    return p * __int_as_float(((int)n + 127) << 23);
}

__device__ __forceinline__ void mma_f16(float* d, const uint32_t* a, const uint32_t* b) {
    asm volatile("mma.sync.aligned.m16n8k16.row.col.f32.f16.f16.f32 "
                 "{%0,%1,%2,%3}, {%4,%5,%6,%7}, {%8,%9}, {%0,%1,%2,%3};"
                 : "+f"(d[0]), "+f"(d[1]), "+f"(d[2]), "+f"(d[3])
                 : "r"(a[0]), "r"(a[1]), "r"(a[2]), "r"(a[3]),
                   "r"(b[0]), "r"(b[1]));
}

__device__ __forceinline__ void ldsm_x4(uint32_t* r, uint32_t addr) {
    asm volatile("ldmatrix.sync.aligned.m8n8.x4.shared.b16 {%0,%1,%2,%3}, [%4];"
                 : "=r"(r[0]), "=r"(r[1]), "=r"(r[2]), "=r"(r[3]) : "r"(addr));
}
__device__ __forceinline__ void ldsm_x4_t(uint32_t* r, uint32_t addr) {
    asm volatile("ldmatrix.sync.aligned.m8n8.x4.trans.shared.b16 {%0,%1,%2,%3}, [%4];"
                 : "=r"(r[0]), "=r"(r[1]), "=r"(r[2]), "=r"(r[3]) : "r"(addr));
}

__device__ __forceinline__ void cp_async16(uint32_t smem, const void* g) {
    asm volatile("cp.async.cg.shared.global [%0], [%1], 16;" :: "r"(smem), "l"(g));
}
__device__ __forceinline__ void cp_commit() { asm volatile("cp.async.commit_group;"); }
__device__ __forceinline__ void cp_wait0()  { asm volatile("cp.async.wait_group 0;"); }
__device__ __forceinline__ void cp_wait1()  { asm volatile("cp.async.wait_group 1;"); }

__device__ __forceinline__ uint32_t h2u(__half2 h) { return *(uint32_t*)&h; }

// ---------------- f32 -> f16 conversion ----------------
__global__ void f2h(const float* __restrict__ s, __half* __restrict__ d, int n4)
{
    int i = blockIdx.x * blockDim.x + threadIdx.x;
    if (i < n4) {
        float4 v = ((const float4*)s)[i];
        ((__half2*)d)[2 * i]     = __floats2half2_rn(v.x, v.y);
        ((__half2*)d)[2 * i + 1] = __floats2half2_rn(v.z, v.w);
    }
}

// ---------------- sync gate ----------------
__global__ void gate_kernel(const float* __restrict__ sf,
                            const float* __restrict__ Ws1, const float* __restrict__ bs1,
                            const float* __restrict__ Ws2, const float* __restrict__ bs2)
{
    __shared__ float h1[BB][HID];
    int t = threadIdx.x;
    for (int b = 0; b < BB; ++b) {
        float acc = bs1[t];
        for (int e = 0; e < EE; ++e)
            acc += sf[b * EE + e] * Ws1[(size_t)e * HID + t];
        h1[b][t] = fmaxf(acc, 0.0f);
    }
    __syncthreads();
    if (t < BB * HH) {
        int b = t / HH, h = t % HH;
        float acc = bs2[h];
        for (int k = 0; k < HID; ++k)
            acc += h1[b][k] * Ws2[k * HH + h];
        float sig = 1.0f / (1.0f + __expf(-acc));
        g_gate[b * HH + h] = sig * 0.125f;
    }
}

// ======= fp16 MMA GEMM 128x128x32: C = A[M,K] @ B[K,N] + bias ==============
template<bool A_HALF, bool OUT_HALF>
__global__ __launch_bounds__(256)
void gemm_h(const void* __restrict__ Ap, const __half* __restrict__ Bh,
            const float* __restrict__ bias, void* __restrict__ Cp)
{
    constexpr int SA = 40;
    constexpr int SB = 136;
    __shared__ __half As[2][128 * SA];
    __shared__ __half Bs[2][32 * SB];

    const int tid = threadIdx.x;
    const int lane = tid & 31, warp = tid >> 5;
    const int wr = warp & 1, wc = warp >> 1;
    const int lr = lane >> 2, lc = lane & 3;
    const int bm = blockIdx.y * 128, bn = blockIdx.x * 128;

    const uint32_t AsB[2] = { (uint32_t)__cvta_generic_to_shared(&As[0][0]),
                              (uint32_t)__cvta_generic_to_shared(&As[1][0]) };
    const uint32_t BsB[2] = { (uint32_t)__cvta_generic_to_shared(&Bs[0][0]),
                              (uint32_t)__cvta_generic_to_shared(&Bs[1][0]) };

    const int brow0 = tid >> 4, bch0 = tid & 15;
    const int brow1 = (tid + 256) >> 4, bch1 = tid & 15;
    auto issueB = [&](int kt, int buf) {
        cp_async16(BsB[buf] + (uint32_t)((brow0 * SB + bch0 * 8) * 2),
                   Bh + (size_t)(kt * 32 + brow0) * EE + bn + bch0 * 8);
        cp_async16(BsB[buf] + (uint32_t)((brow1 * SB + bch1 * 8) * 2),
                   Bh + (size_t)(kt * 32 + brow1) * EE + bn + bch1 * 8);
    };

    const __half* Ah = (const __half*)Ap;
    const float*  Af = (const float*)Ap;
    const int arow0 = tid >> 2, ach0 = tid & 3;
    const int arow1 = (tid + 256) >> 2, ach1 = tid & 3;
    const int frow = tid >> 1, fcol = (tid & 1) * 16;
    float4 av[4];

    auto issueA_h = [&](int kt, int buf) {
        cp_async16(AsB[buf] + (uint32_t)((arow0 * SA + ach0 * 8) * 2),
                   Ah + (size_t)(bm + arow0) * EE + kt * 32 + ach0 * 8);
        cp_async16(AsB[buf] + (uint32_t)((arow1 * SA + ach1 * 8) * 2),
                   Ah + (size_t)(bm + arow1) * EE + kt * 32 + ach1 * 8);
    };
    auto loadA_f = [&](int kt) {
#pragma unroll
        for (int i = 0; i < 4; ++i)
            av[i] = *(const float4*)&Af[(size_t)(bm + frow) * EE + kt * 32 + fcol + i * 4];
    };
    auto storeA_f = [&](int buf) {
#pragma unroll
        for (int i = 0; i < 4; ++i) {
            __half2 h0 = __floats2half2_rn(av[i].x, av[i].y);
            __half2 h1 = __floats2half2_rn(av[i].z, av[i].w);
            *(uint2*)&As[buf][frow * SA + fcol + i * 4] = make_uint2(h2u(h0), h2u(h1));
        }
    };

    float acc[4][4][4];
#pragma unroll
    for (int i = 0; i < 4; ++i)
#pragma unroll
        for (int j = 0; j < 4; ++j)
#pragma unroll
            for (int r = 0; r < 4; ++r) acc[i][j][r] = 0.0f;

    const int a_row_l = wr * 64 + (lane & 15);
    const int a_koff = (lane >> 4) * 8;
    const int b_krow = (lane & 7) + ((lane >> 3) & 1) * 8;
    const int b_noff = (lane >> 4) * 8;

    const int nk = EE / 32;
    if (A_HALF) { issueA_h(0, 0); issueB(0, 0); cp_commit(); }
    else        { issueB(0, 0); cp_commit(); loadA_f(0); storeA_f(0); }

    for (int kt = 0; kt < nk; ++kt) {
        const int buf = kt & 1;
        if (kt + 1 < nk) {
            if (A_HALF) { issueA_h(kt + 1, buf ^ 1); issueB(kt + 1, buf ^ 1); cp_commit(); }
            else        { issueB(kt + 1, buf ^ 1); cp_commit(); loadA_f(kt + 1); }
            cp_wait1();
        } else cp_wait0();
        __syncthreads();

#pragma unroll
        for (int ks = 0; ks < 2; ++ks) {
            const int k0 = ks * 16;
            uint32_t af[4][4], bf[4][2];
#pragma unroll
            for (int mf = 0; mf < 4; ++mf)
                ldsm_x4(af[mf], AsB[buf] +
                        (uint32_t)(((a_row_l + mf * 16) * SA + k0 + a_koff) * 2));
#pragma unroll
            for (int np = 0; np < 2; ++np) {
                uint32_t r4[4];
                int n0 = wc * 32 + np * 16;
                ldsm_x4_t(r4, BsB[buf] +
                          (uint32_t)(((k0 + b_krow) * SB + n0 + b_noff) * 2));
                bf[np * 2][0] = r4[0]; bf[np * 2][1] = r4[1];
                bf[np * 2 + 1][0] = r4[2]; bf[np * 2 + 1][1] = r4[3];
            }
#pragma unroll
            for (int mf = 0; mf < 4; ++mf)
#pragma unroll
                for (int nf = 0; nf < 4; ++nf)
                    mma_f16(acc[mf][nf], af[mf], bf[nf]);
        }
        if (!A_HALF && kt + 1 < nk) storeA_f(buf ^ 1);
        __syncthreads();
    }

#pragma unroll
    for (int nf = 0; nf < 4; ++nf) {
        int col = bn + wc * 32 + nf * 8 + lc * 2;
        float b0 = bias[col], b1 = bias[col + 1];
#pragma unroll
        for (int mf = 0; mf < 4; ++mf) {
            int row = bm + wr * 64 + mf * 16 + lr;
            if (OUT_HALF) {
                __half* Ch = (__half*)Cp;
                *(__half2*)&Ch[(size_t)row * EE + col] =
                    __floats2half2_rn(acc[mf][nf][0] + b0, acc[mf][nf][1] + b1);
                *(__half2*)&Ch[(size_t)(row + 8) * EE + col] =
                    __floats2half2_rn(acc[mf][nf][2] + b0, acc[mf][nf][3] + b1);
            } else {
                float* Cf = (float*)Cp;
                *(float2*)&Cf[(size_t)row * EE + col] =
                    make_float2(acc[mf][nf][0] + b0, acc[mf][nf][1] + b1);
                *(float2*)&Cf[(size_t)(row + 8) * EE + col] =
                    make_float2(acc[mf][nf][2] + b0, acc[mf][nf][3] + b1);
            }
        }
    }
}

// ===== fused attention: scores + exp + p~ store + Z + PV ====================
// Block: (i-tile of 128 queries) x (b,h). 8 warps, warp w owns rows w*16..+15.
#define FA_ST 72
#define FA_SMEM (5 * 128 * FA_ST * 2)

__global__ __launch_bounds__(256)
void attn_fused(const __half* __restrict__ Qh, const __half* __restrict__ Kh,
                const __half* __restrict__ Vh, __half* __restrict__ Ph,
                float* __restrict__ C)
{
    extern __shared__ __half sm[];
    const uint32_t QsB  = (uint32_t)__cvta_generic_to_shared(sm);
    const uint32_t KsB[2] = { QsB + 128 * FA_ST * 2, QsB + 2 * 128 * FA_ST * 2 };
    const uint32_t VsB[2] = { QsB + 3 * 128 * FA_ST * 2, QsB + 4 * 128 * FA_ST * 2 };

    const int tid = threadIdx.x;
    const int lane = tid & 31, warp = tid >> 5;
    const int lr = lane >> 2, lc = lane & 3;
    const int bh = blockIdx.y, b = bh >> 4, h = bh & 15;
    const int mi = blockIdx.x * 128;

    // Q load: 128 rows x 8 chunks of 8 halves
#pragma unroll
    for (int i = 0; i < 4; ++i) {
        int c = tid + i * 256;
        int row = c >> 3, ch = c & 7;
        cp_async16(QsB + (uint32_t)((row * FA_ST + ch * 8) * 2),
                   Qh + (size_t)(b * SS + mi + row) * EE + h * 64 + ch * 8);
    }
    cp_commit();

    auto issueKV = [&](int jt, int buf) {
#pragma unroll
        for (int i = 0; i < 4; ++i) {
            int c = tid + i * 256;
            int row = c >> 3, ch = c & 7;
            cp_async16(KsB[buf] + (uint32_t)((row * FA_ST + ch * 8) * 2),
                       Kh + (size_t)(b * SS + jt * 128 + row) * EE + h * 64 + ch * 8);
            cp_async16(VsB[buf] + (uint32_t)((row * FA_ST + ch * 8) * 2),
                       Vh + (size_t)(b * SS + jt * 128 + row) * EE + h * 64 + ch * 8);
        }
        cp_commit();
    };
    issueKV(0, 0);

    const float g = g_gate[bh];
    const int a_row  = warp * 16 + (lane & 15);
    const int a_koff = (lane >> 4) * 8;
    const int b1_nrow = (lane & 7) + (lane >> 4) * 8;       // MMA1 B (K, non-trans)
    const int b1_koff = ((lane >> 3) & 1) * 8;
    const int b2_krow = (lane & 7) + ((lane >> 3) & 1) * 8; // MMA2 B (V, trans)
    const int b2_noff = (lane >> 4) * 8;

    float ctx[8][4];
#pragma unroll
    for (int i = 0; i < 8; ++i)
#pragma unroll
        for (int r = 0; r < 4; ++r) ctx[i][r] = 0.0f;
    float zs0 = 0.0f, zs1 = 0.0f;

    const int grow = mi + warp * 16 + lr;    // global query row (and +8)
    __half* Prow0 = Ph + ((size_t)bh * SS + grow) * SS;
    __half* Prow1 = Ph + ((size_t)bh * SS + grow + 8) * SS;

    for (int jt = 0; jt < 16; ++jt) {
        const int buf = jt & 1;
        if (jt + 1 < 16) { issueKV(jt + 1, buf ^ 1); cp_wait1(); }
        else cp_wait0();
        __syncthreads();

        // ---- MMA1: scores 128(q) x 128(k) x 64 ----
        float acc[16][4];
#pragma unroll
        for (int i = 0; i < 16; ++i)
#pragma unroll
            for (int r = 0; r < 4; ++r) acc[i][r] = 0.0f;

#pragma unroll
        for (int ks = 0; ks < 4; ++ks) {
            uint32_t af[4];
            ldsm_x4(af, QsB + (uint32_t)((a_row * FA_ST + ks * 16 + a_koff) * 2));
#pragma unroll
            for (int np = 0; np < 8; ++np) {
                uint32_t r4[4];
                ldsm_x4(r4, KsB[buf] +
                        (uint32_t)(((np * 16 + b1_nrow) * FA_ST + ks * 16 + b1_koff) * 2));
                mma_f16(acc[np * 2], af, r4);
                mma_f16(acc[np * 2 + 1], af, r4 + 2);
            }
        }

        // ---- epilogue: exp -> p~ (fp16), store, Z, and MMA2 per k-step ----
        const int jc = jt * 128;
#pragma unroll
        for (int kp = 0; kp < 8; ++kp) {
            float pa0 = fminf(fast_exp(fmaf(acc[2 * kp][0], g, -8.0f)), 60000.0f);
            float pa1 = fminf(fast_exp(fmaf(acc[2 * kp][1], g, -8.0f)), 60000.0f);
            float pb0 = fminf(fast_exp(fmaf(acc[2 * kp][2], g, -8.0f)), 60000.0f);
            float pb1 = fminf(fast_exp(fmaf(acc[2 * kp][3], g, -8.0f)), 60000.0f);
            float pc0 = fminf(fast_exp(fmaf(acc[2 * kp + 1][0], g, -8.0f)), 60000.0f);
            float pc1 = fminf(fast_exp(fmaf(acc[2 * kp + 1][1], g, -8.0f)), 60000.0f);
            float pd0 = fminf(fast_exp(fmaf(acc[2 * kp + 1][2], g, -8.0f)), 60000.0f);
            float pd1 = fminf(fast_exp(fmaf(acc[2 * kp + 1][3], g, -8.0f)), 60000.0f);
            __half2 wa = __floats2half2_rn(pa0, pa1);   // row lr,   col 16kp+2lc
            __half2 wb = __floats2half2_rn(pb0, pb1);   // row lr+8, col 16kp+2lc
            __half2 wc2 = __floats2half2_rn(pc0, pc1);  // row lr,   col 16kp+8+2lc
            __half2 wd = __floats2half2_rn(pd0, pd1);   // row lr+8, col 16kp+8+2lc

            int col = jc + 16 * kp + 2 * lc;
            *(__half2*)&Prow0[col]     = wa;
            *(__half2*)&Prow1[col]     = wb;
            *(__half2*)&Prow0[col + 8] = wc2;
            *(__half2*)&Prow1[col + 8] = wd;

            float2 qa = __half22float2(wa), qb = __half22float2(wb);
            float2 qc = __half22float2(wc2), qd = __half22float2(wd);
            zs0 += qa.x + qa.y + qc.x + qc.y;
            zs1 += qb.x + qb.y + qd.x + qd.y;

            uint32_t af2[4] = { h2u(wa), h2u(wb), h2u(wc2), h2u(wd) };
#pragma unroll
            for (int np = 0; np < 4; ++np) {
                uint32_t r4[4];
                ldsm_x4_t(r4, VsB[buf] +
                          (uint32_t)(((kp * 16 + b2_krow) * FA_ST + np * 16 + b2_noff) * 2));
                mma_f16(ctx[np * 2], af2, r4);
                mma_f16(ctx[np * 2 + 1], af2, r4 + 2);
            }
        }
        __syncthreads();
    }

    // ---- finalize Z, normalize, write ctx ----
    zs0 += __shfl_xor_sync(0xffffffffu, zs0, 1);
    zs0 += __shfl_xor_sync(0xffffffffu, zs0, 2);
    zs1 += __shfl_xor_sync(0xffffffffu, zs1, 1);
    zs1 += __shfl_xor_sync(0xffffffffu, zs1, 2);
    float iz0 = 1.0f / zs0, iz1 = 1.0f / zs1;
    if (lc == 0) {
        g_invZ[(size_t)bh * SS + grow]     = iz0;
        g_invZ[(size_t)bh * SS + grow + 8] = iz1;
    }

    float* Cc = C + (size_t)b * SS * EE + h * 64;
#pragma unroll
    for (int np = 0; np < 8; ++np) {
        int n = np * 8 + 2 * lc;
        *(float2*)&Cc[(size_t)grow * EE + n] =
            make_float2(ctx[np][0] * iz0, ctx[np][1] * iz0);
        *(float2*)&Cc[(size_t)(grow + 8) * EE + n] =
            make_float2(ctx[np][2] * iz1, ctx[np][3] * iz1);
    }
}

// ---------- attn mean over heads: out[b,i,j] = sum_h p~ * invZ_h / 16 -------
__global__ __launch_bounds__(256)
void mean_kernel(const __half* __restrict__ Ph, float* __restrict__ om)
{
    const int i = blockIdx.x, b = blockIdx.y;
    const int tid = threadIdx.x;

    float2 m[4];
#pragma unroll
    for (int r = 0; r < 4; ++r) m[r] = make_float2(0.0f, 0.0f);

    for (int h = 0; h < HH; ++h) {
        const __half2* row2 = (const __half2*)(Ph + ((size_t)(b * HH + h) * SS + i) * SS);
        float w = g_invZ[(size_t)(b * HH + h) * SS + i] * 0.0625f;
#pragma unroll
        for (int r = 0; r < 4; ++r) {
            float2 v = __half22float2(row2[tid + 256 * r]);
            m[r].x = fmaf(w, v.x, m[r].x);
            m[r].y = fmaf(w, v.y, m[r].y);
        }
    }
    float2* o2 = (float2*)(om + (size_t)(b * SS + i) * SS);
#pragma unroll
    for (int r = 0; r < 4; ++r) o2[tid + 256 * r] = m[r];
}

// ---------------- launch ----------------
extern "C" void kernel_launch(void* const* d_in, const int* in_sizes, int n_in,
                              void* d_out, int out_size)
{
    const float* x   = (const float*)d_in[0];
    const float* sf  = (const float*)d_in[1];
    const float* Wq  = (const float*)d_in[2];
    const float* bq  = (const float*)d_in[3];
    const float* Wk  = (const float*)d_in[4];
    const float* bk  = (const float*)d_in[5];
    const float* Wv  = (const float*)d_in[6];
    const float* bv  = (const float*)d_in[7];
    const float* Ws1 = (const float*)d_in[8];
    const float* bs1 = (const float*)d_in[9];
    const float* Ws2 = (const float*)d_in[10];
    const float* bs2 = (const float*)d_in[11];
    const float* Wo  = (const float*)d_in[12];
    const float* bo  = (const float*)d_in[13];
    float* out = (float*)d_out;

    __half *pXh, *pWh, *pQh, *pKh, *pVh, *pPh;
    float *pC;
    cudaGetSymbolAddress((void**)&pXh, g_Xh);
    cudaGetSymbolAddress((void**)&pWh, g_Wh);
    cudaGetSymbolAddress((void**)&pQh, g_Qh);
    cudaGetSymbolAddress((void**)&pKh, g_Kh);
    cudaGetSymbolAddress((void**)&pVh, g_Vh);
    cudaGetSymbolAddress((void**)&pPh, g_Ph);
    cudaGetSymbolAddress((void**)&pC, g_CTX);

    const size_t WSZ = (size_t)EE * EE;
    const int XN4 = (BB * SS * EE) / 4;
    const int WN4 = (EE * EE) / 4;

    // 0. conversions + gate
    f2h<<<XN4 / 256, 256>>>(x, pXh, XN4);
    f2h<<<WN4 / 256, 256>>>(Wq, pWh + 0 * WSZ, WN4);
    f2h<<<WN4 / 256, 256>>>(Wk, pWh + 1 * WSZ, WN4);
    f2h<<<WN4 / 256, 256>>>(Wv, pWh + 2 * WSZ, WN4);
    f2h<<<WN4 / 256, 256>>>(Wo, pWh + 3 * WSZ, WN4);
    gate_kernel<<<1, 256>>>(sf, Ws1, bs1, Ws2, bs2);

    // 1. QKV projections (fp16 MMA, fp16 out)
    dim3 gqkv(EE / 128, (BB * SS) / 128);
    gemm_h<true, true><<<gqkv, 256>>>(pXh, pWh + 0 * WSZ, bq, pQh);
    gemm_h<true, true><<<gqkv, 256>>>(pXh, pWh + 1 * WSZ, bk, pKh);
    gemm_h<true, true><<<gqkv, 256>>>(pXh, pWh + 2 * WSZ, bv, pVh);

    // 2. fused attention: p~ store + Z + ctx
    cudaFuncSetAttribute(attn_fused, cudaFuncAttributeMaxDynamicSharedMemorySize, FA_SMEM);
    attn_fused<<<dim3(SS / 128, BB * HH), 256, FA_SMEM>>>(pQh, pKh, pVh, pPh, pC);

    // 3. attn mean -> second half of d_out
    mean_kernel<<<dim3(SS, BB), 256>>>(pPh, out + (size_t)BB * SS * EE);

    // 4. out = ctx @ Wo + bo (fp32 A staging, fp32 out)
    gemm_h<false, false><<<gqkv, 256>>>(pC, pWh + 3 * WSZ, bo, out);

    (void)in_sizes; (void)n_in; (void)out_size;
}

// round 9
// speedup vs baseline: 1.7978x; 1.0017x over previous
#include <cuda_runtime.h>
#include <cuda_fp16.h>
#include <cstdint>
#include <cstddef>

#define BB 2
#define SS 2048
#define EE 1024
#define HH 16
#define HID 256
#define N3 3072

// ---------------- scratch (device globals: allocation-free) ----------------
__device__ __half g_Xh[(size_t)BB * SS * EE];
__device__ __half g_W3[(size_t)EE * N3];        // interleaved [k][Wq|Wk|Wv]
__device__ __half g_Who[(size_t)EE * EE];
__device__ float  g_b3[N3];
__device__ __half g_QKV[(size_t)BB * SS * N3];  // [b,s][q|k|v]
__device__ __half g_CTXh[(size_t)BB * SS * EE];
__device__ __half g_Ph[(size_t)BB * HH * SS * SS];   // 268 MB p~ = exp(s-8)
__device__ float  g_invZ[(size_t)BB * HH * SS];
__device__ float  g_gate[BB * HH];

// ---------------- helpers ----------------
__device__ __forceinline__ float fast_exp(float x) {
    float y = x * 1.4426950408889634f;
    float n = rintf(y);
    float t = (y - n) * 0.6931471805599453f;
    float p = 1.0f + t * (1.0f + t * (0.5f + t * (0.16666667f +
              t * (0.041666668f + t * 0.008333334f))));
    n = fmaxf(n, -126.0f);
    return p * __int_as_float(((int)n + 127) << 23);
}

__device__ __forceinline__ void mma_f16(float* d, const uint32_t* a, const uint32_t* b) {
    asm volatile("mma.sync.aligned.m16n8k16.row.col.f32.f16.f16.f32 "
                 "{%0,%1,%2,%3}, {%4,%5,%6,%7}, {%8,%9}, {%0,%1,%2,%3};"
                 : "+f"(d[0]), "+f"(d[1]), "+f"(d[2]), "+f"(d[3])
                 : "r"(a[0]), "r"(a[1]), "r"(a[2]), "r"(a[3]),
                   "r"(b[0]), "r"(b[1]));
}

__device__ __forceinline__ void ldsm_x4(uint32_t* r, uint32_t addr) {
    asm volatile("ldmatrix.sync.aligned.m8n8.x4.shared.b16 {%0,%1,%2,%3}, [%4];"
                 : "=r"(r[0]), "=r"(r[1]), "=r"(r[2]), "=r"(r[3]) : "r"(addr));
}
__device__ __forceinline__ void ldsm_x4_t(uint32_t* r, uint32_t addr) {
    asm volatile("ldmatrix.sync.aligned.m8n8.x4.trans.shared.b16 {%0,%1,%2,%3}, [%4];"
                 : "=r"(r[0]), "=r"(r[1]), "=r"(r[2]), "=r"(r[3]) : "r"(addr));
}

__device__ __forceinline__ void cp_async16(uint32_t smem, const void* g) {
    asm volatile("cp.async.cg.shared.global [%0], [%1], 16;" :: "r"(smem), "l"(g));
}
__device__ __forceinline__ void cp_commit() { asm volatile("cp.async.commit_group;"); }
__device__ __forceinline__ void cp_wait0()  { asm volatile("cp.async.wait_group 0;"); }
__device__ __forceinline__ void cp_wait1()  { asm volatile("cp.async.wait_group 1;"); }

__device__ __forceinline__ uint32_t h2u(__half2 h) { return *(uint32_t*)&h; }

// ================= prep: f2h conversions + gate + bias combine ==============
__global__ __launch_bounds__(256)
void prep(const float* __restrict__ x,
          const float* __restrict__ Wq, const float* __restrict__ Wk,
          const float* __restrict__ Wv, const float* __restrict__ Wo,
          const float* __restrict__ bq, const float* __restrict__ bk,
          const float* __restrict__ bv,
          const float* __restrict__ sf,
          const float* __restrict__ Ws1, const float* __restrict__ bs1,
          const float* __restrict__ Ws2, const float* __restrict__ bs2)
{
    const int bid = blockIdx.x, tid = threadIdx.x;
    if (bid == 0) {
        __shared__ float h1[BB][HID];
        for (int b = 0; b < BB; ++b) {
            float acc = bs1[tid];
            for (int e = 0; e < EE; ++e)
                acc += sf[b * EE + e] * Ws1[(size_t)e * HID + tid];
            h1[b][tid] = fmaxf(acc, 0.0f);
        }
        __syncthreads();
        if (tid < BB * HH) {
            int b = tid / HH, h = tid % HH;
            float acc = bs2[h];
            for (int k = 0; k < HID; ++k)
                acc += h1[b][k] * Ws2[k * HH + h];
            g_gate[b * HH + h] = (1.0f / (1.0f + __expf(-acc))) * 0.125f;
        }
        for (int i = tid; i < EE; i += 256) {
            g_b3[i] = bq[i]; g_b3[EE + i] = bk[i]; g_b3[2 * EE + i] = bv[i];
        }
        return;
    }
    int t = (bid - 1) * 256 + tid;
    if (t < 1048576) {                    // X: 4M floats
        float4 v = ((const float4*)x)[t];
        ((__half2*)g_Xh)[2 * t]     = __floats2half2_rn(v.x, v.y);
        ((__half2*)g_Xh)[2 * t + 1] = __floats2half2_rn(v.z, v.w);
        return;
    }
    t -= 1048576;
    if (t < 3 * 262144) {                 // Wq/Wk/Wv interleave into [k][3N]
        int which = t / 262144;
        int u = t - which * 262144;
        const float* W = (which == 0) ? Wq : ((which == 1) ? Wk : Wv);
        float4 v = ((const float4*)W)[u];
        int k = u >> 8, n4 = u & 255;
        size_t d = (size_t)k * N3 + which * EE + n4 * 4;
        *(__half2*)&g_W3[d]     = __floats2half2_rn(v.x, v.y);
        *(__half2*)&g_W3[d + 2] = __floats2half2_rn(v.z, v.w);
        return;
    }
    t -= 3 * 262144;
    if (t < 262144) {                     // Wo
        float4 v = ((const float4*)Wo)[t];
        ((__half2*)g_Who)[2 * t]     = __floats2half2_rn(v.x, v.y);
        ((__half2*)g_Who)[2 * t + 1] = __floats2half2_rn(v.z, v.w);
    }
}

// ======= fp16 MMA GEMM body 128x128x32: C = A[M,1024] @ B[1024,N] + bias ====
// A fp16 row-stride 1024. B/C row stride = ldbc. OUT_HALF: C fp16 else fp32.
template<bool OUT_HALF>
__device__ __forceinline__ void gemm_body(
    const __half* __restrict__ Ah, const __half* __restrict__ Bh,
    const float* __restrict__ bias, void* __restrict__ Cp,
    int ldbc, int bx, int by)
{
    constexpr int SA = 40;
    constexpr int SB = 136;
    __shared__ __half As[2][128 * SA];
    __shared__ __half Bs[2][32 * SB];

    const int tid = threadIdx.x;
    const int lane = tid & 31, warp = tid >> 5;
    const int wr = warp & 1, wc = warp >> 1;
    const int lr = lane >> 2, lc = lane & 3;
    const int bm = by * 128, bn = bx * 128;

    const uint32_t AsB[2] = { (uint32_t)__cvta_generic_to_shared(&As[0][0]),
                              (uint32_t)__cvta_generic_to_shared(&As[1][0]) };
    const uint32_t BsB[2] = { (uint32_t)__cvta_generic_to_shared(&Bs[0][0]),
                              (uint32_t)__cvta_generic_to_shared(&Bs[1][0]) };

    const int brow0 = tid >> 4, bch0 = tid & 15;
    const int arow0 = tid >> 2, ach0 = tid & 3;

    auto issue = [&](int kt, int buf) {
        cp_async16(AsB[buf] + (uint32_t)((arow0 * SA + ach0 * 8) * 2),
                   Ah + (size_t)(bm + arow0) * EE + kt * 32 + ach0 * 8);
        cp_async16(AsB[buf] + (uint32_t)(((arow0 + 64) * SA + ach0 * 8) * 2),
                   Ah + (size_t)(bm + arow0 + 64) * EE + kt * 32 + ach0 * 8);
        cp_async16(BsB[buf] + (uint32_t)((brow0 * SB + bch0 * 8) * 2),
                   Bh + (size_t)(kt * 32 + brow0) * ldbc + bn + bch0 * 8);
        cp_async16(BsB[buf] + (uint32_t)(((brow0 + 16) * SB + bch0 * 8) * 2),
                   Bh + (size_t)(kt * 32 + brow0 + 16) * ldbc + bn + bch0 * 8);
        cp_commit();
    };

    float acc[4][4][4];
#pragma unroll
    for (int i = 0; i < 4; ++i)
#pragma unroll
        for (int j = 0; j < 4; ++j)
#pragma unroll
            for (int r = 0; r < 4; ++r) acc[i][j][r] = 0.0f;

    const int a_row_l = wr * 64 + (lane & 15);
    const int a_koff = (lane >> 4) * 8;
    const int b_krow = (lane & 7) + ((lane >> 3) & 1) * 8;
    const int b_noff = (lane >> 4) * 8;

    const int nk = EE / 32;
    issue(0, 0);

    for (int kt = 0; kt < nk; ++kt) {
        const int buf = kt & 1;
        if (kt + 1 < nk) { issue(kt + 1, buf ^ 1); cp_wait1(); }
        else cp_wait0();
        __syncthreads();

#pragma unroll
        for (int ks = 0; ks < 2; ++ks) {
            const int k0 = ks * 16;
            uint32_t af[4][4], bf[4][2];
#pragma unroll
            for (int mf = 0; mf < 4; ++mf)
                ldsm_x4(af[mf], AsB[buf] +
                        (uint32_t)(((a_row_l + mf * 16) * SA + k0 + a_koff) * 2));
#pragma unroll
            for (int np = 0; np < 2; ++np) {
                uint32_t r4[4];
                int n0 = wc * 32 + np * 16;
                ldsm_x4_t(r4, BsB[buf] +
                          (uint32_t)(((k0 + b_krow) * SB + n0 + b_noff) * 2));
                bf[np * 2][0] = r4[0]; bf[np * 2][1] = r4[1];
                bf[np * 2 + 1][0] = r4[2]; bf[np * 2 + 1][1] = r4[3];
            }
#pragma unroll
            for (int mf = 0; mf < 4; ++mf)
#pragma unroll
                for (int nf = 0; nf < 4; ++nf)
                    mma_f16(acc[mf][nf], af[mf], bf[nf]);
        }
        __syncthreads();
    }

#pragma unroll
    for (int nf = 0; nf < 4; ++nf) {
        int col = bn + wc * 32 + nf * 8 + lc * 2;
        float b0 = bias[col], b1 = bias[col + 1];
#pragma unroll
        for (int mf = 0; mf < 4; ++mf) {
            int row = bm + wr * 64 + mf * 16 + lr;
            if (OUT_HALF) {
                __half* Ch = (__half*)Cp;
                *(__half2*)&Ch[(size_t)row * ldbc + col] =
                    __floats2half2_rn(acc[mf][nf][0] + b0, acc[mf][nf][1] + b1);
                *(__half2*)&Ch[(size_t)(row + 8) * ldbc + col] =
                    __floats2half2_rn(acc[mf][nf][2] + b0, acc[mf][nf][3] + b1);
            } else {
                float* Cf = (float*)Cp;
                *(float2*)&Cf[(size_t)row * ldbc + col] =
                    make_float2(acc[mf][nf][0] + b0, acc[mf][nf][1] + b1);
                *(float2*)&Cf[(size_t)(row + 8) * ldbc + col] =
                    make_float2(acc[mf][nf][2] + b0, acc[mf][nf][3] + b1);
            }
        }
    }
}

// ---------------- QKV: one GEMM, N = 3072 ----------------
__global__ __launch_bounds__(256)
void gemm_qkv(const __half* __restrict__ Xh, const __half* __restrict__ W3,
              const float* __restrict__ b3, __half* __restrict__ QKV)
{
    gemm_body<true>(Xh, W3, b3, QKV, N3, blockIdx.x, blockIdx.y);
}

// ===== fused attention: scores + exp + p~ store + Z + PV ====================
#define FA_ST 72
#define FA_SMEM (5 * 128 * FA_ST * 2)

__global__ __launch_bounds__(256)
void attn_fused(const __half* __restrict__ QKV, __half* __restrict__ Ph,
                __half* __restrict__ Ch)
{
    extern __shared__ __half sm[];
    const uint32_t QsB  = (uint32_t)__cvta_generic_to_shared(sm);
    const uint32_t KsB[2] = { QsB + 128 * FA_ST * 2, QsB + 2 * 128 * FA_ST * 2 };
    const uint32_t VsB[2] = { QsB + 3 * 128 * FA_ST * 2, QsB + 4 * 128 * FA_ST * 2 };

    const int tid = threadIdx.x;
    const int lane = tid & 31, warp = tid >> 5;
    const int lr = lane >> 2, lc = lane & 3;
    const int bh = blockIdx.y, b = bh >> 4, h = bh & 15;
    const int mi = blockIdx.x * 128;

    // Q load (group 0)
#pragma unroll
    for (int i = 0; i < 4; ++i) {
        int c = tid + i * 256;
        int row = c >> 3, ch = c & 7;
        cp_async16(QsB + (uint32_t)((row * FA_ST + ch * 8) * 2),
                   QKV + (size_t)(b * SS + mi + row) * N3 + h * 64 + ch * 8);
    }
    cp_commit();

    auto issueKV = [&](int jt, int buf) {
#pragma unroll
        for (int i = 0; i < 4; ++i) {
            int c = tid + i * 256;
            int row = c >> 3, ch = c & 7;
            size_t base = (size_t)(b * SS + jt * 128 + row) * N3 + h * 64 + ch * 8;
            cp_async16(KsB[buf] + (uint32_t)((row * FA_ST + ch * 8) * 2),
                       QKV + base + 1024);
            cp_async16(VsB[buf] + (uint32_t)((row * FA_ST + ch * 8) * 2),
                       QKV + base + 2048);
        }
        cp_commit();
    };
    issueKV(0, 0);

    const float g = g_gate[bh];
    const int a_row  = warp * 16 + (lane & 15);
    const int a_koff = (lane >> 4) * 8;
    const int b1_nrow = (lane & 7) + (lane >> 4) * 8;
    const int b1_koff = ((lane >> 3) & 1) * 8;
    const int b2_krow = (lane & 7) + ((lane >> 3) & 1) * 8;
    const int b2_noff = (lane >> 4) * 8;

    // hoist Q fragments (wait group0 only: <=1 pending)
    cp_wait1();
    __syncthreads();
    uint32_t qf[4][4];
#pragma unroll
    for (int ks = 0; ks < 4; ++ks)
        ldsm_x4(qf[ks], QsB + (uint32_t)((a_row * FA_ST + ks * 16 + a_koff) * 2));

    float ctx[8][4];
#pragma unroll
    for (int i = 0; i < 8; ++i)
#pragma unroll
        for (int r = 0; r < 4; ++r) ctx[i][r] = 0.0f;
    float zs0 = 0.0f, zs1 = 0.0f;

    const int grow = mi + warp * 16 + lr;
    __half* Prow0 = Ph + ((size_t)bh * SS + grow) * SS;
    __half* Prow1 = Ph + ((size_t)bh * SS + grow + 8) * SS;

    for (int jt = 0; jt < 16; ++jt) {
        const int buf = jt & 1;
        if (jt + 1 < 16) { issueKV(jt + 1, buf ^ 1); cp_wait1(); }
        else cp_wait0();
        __syncthreads();

        float acc[16][4];
#pragma unroll
        for (int i = 0; i < 16; ++i)
#pragma unroll
            for (int r = 0; r < 4; ++r) acc[i][r] = 0.0f;

#pragma unroll
        for (int ks = 0; ks < 4; ++ks) {
#pragma unroll
            for (int np = 0; np < 8; ++np) {
                uint32_t r4[4];
                ldsm_x4(r4, KsB[buf] +
                        (uint32_t)(((np * 16 + b1_nrow) * FA_ST + ks * 16 + b1_koff) * 2));
                mma_f16(acc[np * 2], qf[ks], r4);
                mma_f16(acc[np * 2 + 1], qf[ks], r4 + 2);
            }
        }

        const int jc = jt * 128;
#pragma unroll
        for (int kp = 0; kp < 8; ++kp) {
            float pa0 = fminf(fast_exp(fmaf(acc[2 * kp][0], g, -8.0f)), 60000.0f);
            float pa1 = fminf(fast_exp(fmaf(acc[2 * kp][1], g, -8.0f)), 60000.0f);
            float pb0 = fminf(fast_exp(fmaf(acc[2 * kp][2], g, -8.0f)), 60000.0f);
            float pb1 = fminf(fast_exp(fmaf(acc[2 * kp][3], g, -8.0f)), 60000.0f);
            float pc0 = fminf(fast_exp(fmaf(acc[2 * kp + 1][0], g, -8.0f)), 60000.0f);
            float pc1 = fminf(fast_exp(fmaf(acc[2 * kp + 1][1], g, -8.0f)), 60000.0f);
            float pd0 = fminf(fast_exp(fmaf(acc[2 * kp + 1][2], g, -8.0f)), 60000.0f);
            float pd1 = fminf(fast_exp(fmaf(acc[2 * kp + 1][3], g, -8.0f)), 60000.0f);
            __half2 wa = __floats2half2_rn(pa0, pa1);
            __half2 wb = __floats2half2_rn(pb0, pb1);
            __half2 wc2 = __floats2half2_rn(pc0, pc1);
            __half2 wd = __floats2half2_rn(pd0, pd1);

            int col = jc + 16 * kp + 2 * lc;
            *(__half2*)&Prow0[col]     = wa;
            *(__half2*)&Prow1[col]     = wb;
            *(__half2*)&Prow0[col + 8] = wc2;
            *(__half2*)&Prow1[col + 8] = wd;

            float2 qa = __half22float2(wa), qb = __half22float2(wb);
            float2 qc = __half22float2(wc2), qd = __half22float2(wd);
            zs0 += qa.x + qa.y + qc.x + qc.y;
            zs1 += qb.x + qb.y + qd.x + qd.y;

            uint32_t af2[4] = { h2u(wa), h2u(wb), h2u(wc2), h2u(wd) };
#pragma unroll
            for (int np = 0; np < 4; ++np) {
                uint32_t r4[4];
                ldsm_x4_t(r4, VsB[buf] +
                          (uint32_t)(((kp * 16 + b2_krow) * FA_ST + np * 16 + b2_noff) * 2));
                mma_f16(ctx[np * 2], af2, r4);
                mma_f16(ctx[np * 2 + 1], af2, r4 + 2);
            }
        }
        __syncthreads();
    }

    zs0 += __shfl_xor_sync(0xffffffffu, zs0, 1);
    zs0 += __shfl_xor_sync(0xffffffffu, zs0, 2);
    zs1 += __shfl_xor_sync(0xffffffffu, zs1, 1);
    zs1 += __shfl_xor_sync(0xffffffffu, zs1, 2);
    float iz0 = 1.0f / zs0, iz1 = 1.0f / zs1;
    if (lc == 0) {
        g_invZ[(size_t)bh * SS + grow]     = iz0;
        g_invZ[(size_t)bh * SS + grow + 8] = iz1;
    }

    __half* Cc = Ch + (size_t)b * SS * EE + h * 64;
#pragma unroll
    for (int np = 0; np < 8; ++np) {
        int n = np * 8 + 2 * lc;
        *(__half2*)&Cc[(size_t)grow * EE + n] =
            __floats2half2_rn(ctx[np][0] * iz0, ctx[np][1] * iz0);
        *(__half2*)&Cc[(size_t)(grow + 8) * EE + n] =
            __floats2half2_rn(ctx[np][2] * iz1, ctx[np][3] * iz1);
    }
}

// ===== tail: out-proj GEMM (blocks 0..255) || head-mean (blocks 256..4351) ==
__global__ __launch_bounds__(256)
void tail_kernel(const __half* __restrict__ Ch, const __half* __restrict__ Who,
                 const float* __restrict__ bo, float* __restrict__ out,
                 const __half* __restrict__ Ph, float* __restrict__ om)
{
    const int bid = blockIdx.x;
    if (bid < 256) {
        gemm_body<false>(Ch, Who, bo, out, EE, bid & 7, bid >> 3);
        return;
    }
    const int id = bid - 256;
    const int i = id & (SS - 1), b = id >> 11;
    const int tid = threadIdx.x;

    float2 m[4];
#pragma unroll
    for (int r = 0; r < 4; ++r) m[r] = make_float2(0.0f, 0.0f);

    for (int h = 0; h < HH; ++h) {
        const __half2* row2 = (const __half2*)(Ph + ((size_t)(b * HH + h) * SS + i) * SS);
        float w = g_invZ[(size_t)(b * HH + h) * SS + i] * 0.0625f;
#pragma unroll
        for (int r = 0; r < 4; ++r) {
            float2 v = __half22float2(row2[tid + 256 * r]);
            m[r].x = fmaf(w, v.x, m[r].x);
            m[r].y = fmaf(w, v.y, m[r].y);
        }
    }
    float2* o2 = (float2*)(om + (size_t)(b * SS + i) * SS);
#pragma unroll
    for (int r = 0; r < 4; ++r) o2[tid + 256 * r] = m[r];
}

// ---------------- launch ----------------
extern "C" void kernel_launch(void* const* d_in, const int* in_sizes, int n_in,
                              void* d_out, int out_size)
{
    const float* x   = (const float*)d_in[0];
    const float* sf  = (const float*)d_in[1];
    const float* Wq  = (const float*)d_in[2];
    const float* bq  = (const float*)d_in[3];
    const float* Wk  = (const float*)d_in[4];
    const float* bk  = (const float*)d_in[5];
    const float* Wv  = (const float*)d_in[6];
    const float* bv  = (const float*)d_in[7];
    const float* Ws1 = (const float*)d_in[8];
    const float* bs1 = (const float*)d_in[9];
    const float* Ws2 = (const float*)d_in[10];
    const float* bs2 = (const float*)d_in[11];
    const float* Wo  = (const float*)d_in[12];
    const float* bo  = (const float*)d_in[13];
    float* out = (float*)d_out;

    __half *pXh, *pW3, *pWho, *pQKV, *pCh, *pPh;
    float *pb3;
    cudaGetSymbolAddress((void**)&pXh, g_Xh);
    cudaGetSymbolAddress((void**)&pW3, g_W3);
    cudaGetSymbolAddress((void**)&pWho, g_Who);
    cudaGetSymbolAddress((void**)&pb3, g_b3);
    cudaGetSymbolAddress((void**)&pQKV, g_QKV);
    cudaGetSymbolAddress((void**)&pCh, g_CTXh);
    cudaGetSymbolAddress((void**)&pPh, g_Ph);

    // 0. prep: conversions + interleave + gate + bias combine
    prep<<<1 + 4096 + 3072 + 1024, 256>>>(x, Wq, Wk, Wv, Wo, bq, bk, bv,
                                          sf, Ws1, bs1, Ws2, bs2);

    // 1. fused QKV projection: [4096,1024] @ [1024,3072]
    gemm_qkv<<<dim3(N3 / 128, (BB * SS) / 128), 256>>>(pXh, pW3, pb3, pQKV);

    // 2. fused attention: p~ store + Z + ctx(fp16)
    cudaFuncSetAttribute(attn_fused, cudaFuncAttributeMaxDynamicSharedMemorySize, FA_SMEM);
    attn_fused<<<dim3(SS / 128, BB * HH), 256, FA_SMEM>>>(pQKV, pPh, pCh);

    // 3. tail: out-proj GEMM || head-mean (grid-partitioned co-execution)
    tail_kernel<<<256 + BB * SS, 256>>>(pCh, pWho, bo, out, pPh,
                                        out + (size_t)BB * SS * EE);

    (void)in_sizes; (void)n_in; (void)out_size;
}

// round 10
// speedup vs baseline: 1.9907x; 1.1073x over previous
#include <cuda_runtime.h>
#include <cuda_fp16.h>
#include <cstdint>
#include <cstddef>

#define BB 2
#define SS 2048
#define EE 1024
#define HH 16
#define HID 256
#define N3 3072

// ---------------- scratch (device globals: allocation-free) ----------------
__device__ __half g_Xh[(size_t)BB * SS * EE];
__device__ __half g_W3[(size_t)EE * N3];        // interleaved [k][Wq|Wk|Wv]
__device__ __half g_Who[(size_t)EE * EE];
__device__ float  g_b3[N3];
__device__ __half g_QKV[(size_t)BB * SS * N3];  // [b,s][q|k|v]
__device__ __half g_CTXh[(size_t)BB * SS * EE];
__device__ __half g_Ph[(size_t)BB * HH * SS * SS];   // 268 MB p~ = exp(s-8)
__device__ float  g_invZ[(size_t)BB * HH * SS];
__device__ float  g_gate[BB * HH];

// ---------------- helpers ----------------
__device__ __forceinline__ float ex2(float x) {
    float r; asm("ex2.approx.f32 %0, %1;" : "=f"(r) : "f"(x)); return r;
}

__device__ __forceinline__ void mma_f16(float* d, const uint32_t* a, const uint32_t* b) {
    asm volatile("mma.sync.aligned.m16n8k16.row.col.f32.f16.f16.f32 "
                 "{%0,%1,%2,%3}, {%4,%5,%6,%7}, {%8,%9}, {%0,%1,%2,%3};"
                 : "+f"(d[0]), "+f"(d[1]), "+f"(d[2]), "+f"(d[3])
                 : "r"(a[0]), "r"(a[1]), "r"(a[2]), "r"(a[3]),
                   "r"(b[0]), "r"(b[1]));
}

__device__ __forceinline__ void ldsm_x4(uint32_t* r, uint32_t addr) {
    asm volatile("ldmatrix.sync.aligned.m8n8.x4.shared.b16 {%0,%1,%2,%3}, [%4];"
                 : "=r"(r[0]), "=r"(r[1]), "=r"(r[2]), "=r"(r[3]) : "r"(addr));
}
__device__ __forceinline__ void ldsm_x4_t(uint32_t* r, uint32_t addr) {
    asm volatile("ldmatrix.sync.aligned.m8n8.x4.trans.shared.b16 {%0,%1,%2,%3}, [%4];"
                 : "=r"(r[0]), "=r"(r[1]), "=r"(r[2]), "=r"(r[3]) : "r"(addr));
}

__device__ __forceinline__ void cp_async16(uint32_t smem, const void* g) {
    asm volatile("cp.async.cg.shared.global [%0], [%1], 16;" :: "r"(smem), "l"(g));
}
__device__ __forceinline__ void cp_commit() { asm volatile("cp.async.commit_group;"); }
__device__ __forceinline__ void cp_wait0()  { asm volatile("cp.async.wait_group 0;"); }
__device__ __forceinline__ void cp_wait1()  { asm volatile("cp.async.wait_group 1;"); }

__device__ __forceinline__ uint32_t h2u(__half2 h) { return *(uint32_t*)&h; }

// ================= prep: f2h conversions + gate + bias combine ==============
__global__ __launch_bounds__(256)
void prep(const float* __restrict__ x,
          const float* __restrict__ Wq, const float* __restrict__ Wk,
          const float* __restrict__ Wv, const float* __restrict__ Wo,
          const float* __restrict__ bq, const float* __restrict__ bk,
          const float* __restrict__ bv,
          const float* __restrict__ sf,
          const float* __restrict__ Ws1, const float* __restrict__ bs1,
          const float* __restrict__ Ws2, const float* __restrict__ bs2)
{
    const int bid = blockIdx.x, tid = threadIdx.x;
    if (bid == 0) {
        __shared__ float h1[BB][HID];
        for (int b = 0; b < BB; ++b) {
            float acc = bs1[tid];
            for (int e = 0; e < EE; ++e)
                acc += sf[b * EE + e] * Ws1[(size_t)e * HID + tid];
            h1[b][tid] = fmaxf(acc, 0.0f);
        }
        __syncthreads();
        if (tid < BB * HH) {
            int b = tid / HH, h = tid % HH;
            float acc = bs2[h];
            for (int k = 0; k < HID; ++k)
                acc += h1[b][k] * Ws2[k * HH + h];
            g_gate[b * HH + h] = (1.0f / (1.0f + __expf(-acc))) * 0.125f;
        }
        for (int i = tid; i < EE; i += 256) {
            g_b3[i] = bq[i]; g_b3[EE + i] = bk[i]; g_b3[2 * EE + i] = bv[i];
        }
        return;
    }
    int t = (bid - 1) * 256 + tid;
    if (t < 1048576) {                    // X: 4M floats
        float4 v = ((const float4*)x)[t];
        ((__half2*)g_Xh)[2 * t]     = __floats2half2_rn(v.x, v.y);
        ((__half2*)g_Xh)[2 * t + 1] = __floats2half2_rn(v.z, v.w);
        return;
    }
    t -= 1048576;
    if (t < 3 * 262144) {                 // Wq/Wk/Wv interleave into [k][3N]
        int which = t / 262144;
        int u = t - which * 262144;
        const float* W = (which == 0) ? Wq : ((which == 1) ? Wk : Wv);
        float4 v = ((const float4*)W)[u];
        int k = u >> 8, n4 = u & 255;
        size_t d = (size_t)k * N3 + which * EE + n4 * 4;
        *(__half2*)&g_W3[d]     = __floats2half2_rn(v.x, v.y);
        *(__half2*)&g_W3[d + 2] = __floats2half2_rn(v.z, v.w);
        return;
    }
    t -= 3 * 262144;
    if (t < 262144) {                     // Wo
        float4 v = ((const float4*)Wo)[t];
        ((__half2*)g_Who)[2 * t]     = __floats2half2_rn(v.x, v.y);
        ((__half2*)g_Who)[2 * t + 1] = __floats2half2_rn(v.z, v.w);
    }
}

// ======= fp16 MMA GEMM body 128x128x32: C = A[M,1024] @ B[1024,N] + bias ====
template<bool OUT_HALF>
__device__ __forceinline__ void gemm_body(
    const __half* __restrict__ Ah, const __half* __restrict__ Bh,
    const float* __restrict__ bias, void* __restrict__ Cp,
    int ldbc, int bx, int by)
{
    constexpr int SA = 40;
    constexpr int SB = 136;
    __shared__ __half As[2][128 * SA];
    __shared__ __half Bs[2][32 * SB];

    const int tid = threadIdx.x;
    const int lane = tid & 31, warp = tid >> 5;
    const int wr = warp & 1, wc = warp >> 1;
    const int lr = lane >> 2, lc = lane & 3;
    const int bm = by * 128, bn = bx * 128;

    const uint32_t AsB[2] = { (uint32_t)__cvta_generic_to_shared(&As[0][0]),
                              (uint32_t)__cvta_generic_to_shared(&As[1][0]) };
    const uint32_t BsB[2] = { (uint32_t)__cvta_generic_to_shared(&Bs[0][0]),
                              (uint32_t)__cvta_generic_to_shared(&Bs[1][0]) };

    const int brow0 = tid >> 4, bch0 = tid & 15;
    const int arow0 = tid >> 2, ach0 = tid & 3;

    auto issue = [&](int kt, int buf) {
        cp_async16(AsB[buf] + (uint32_t)((arow0 * SA + ach0 * 8) * 2),
                   Ah + (size_t)(bm + arow0) * EE + kt * 32 + ach0 * 8);
        cp_async16(AsB[buf] + (uint32_t)(((arow0 + 64) * SA + ach0 * 8) * 2),
                   Ah + (size_t)(bm + arow0 + 64) * EE + kt * 32 + ach0 * 8);
        cp_async16(BsB[buf] + (uint32_t)((brow0 * SB + bch0 * 8) * 2),
                   Bh + (size_t)(kt * 32 + brow0) * ldbc + bn + bch0 * 8);
        cp_async16(BsB[buf] + (uint32_t)(((brow0 + 16) * SB + bch0 * 8) * 2),
                   Bh + (size_t)(kt * 32 + brow0 + 16) * ldbc + bn + bch0 * 8);
        cp_commit();
    };

    float acc[4][4][4];
#pragma unroll
    for (int i = 0; i < 4; ++i)
#pragma unroll
        for (int j = 0; j < 4; ++j)
#pragma unroll
            for (int r = 0; r < 4; ++r) acc[i][j][r] = 0.0f;

    const int a_row_l = wr * 64 + (lane & 15);
    const int a_koff = (lane >> 4) * 8;
    const int b_krow = (lane & 7) + ((lane >> 3) & 1) * 8;
    const int b_noff = (lane >> 4) * 8;

    const int nk = EE / 32;
    issue(0, 0);

    for (int kt = 0; kt < nk; ++kt) {
        const int buf = kt & 1;
        if (kt + 1 < nk) { issue(kt + 1, buf ^ 1); cp_wait1(); }
        else cp_wait0();
        __syncthreads();

#pragma unroll
        for (int ks = 0; ks < 2; ++ks) {
            const int k0 = ks * 16;
            uint32_t af[4][4], bf[4][2];
#pragma unroll
            for (int mf = 0; mf < 4; ++mf)
                ldsm_x4(af[mf], AsB[buf] +
                        (uint32_t)(((a_row_l + mf * 16) * SA + k0 + a_koff) * 2));
#pragma unroll
            for (int np = 0; np < 2; ++np) {
                uint32_t r4[4];
                int n0 = wc * 32 + np * 16;
                ldsm_x4_t(r4, BsB[buf] +
                          (uint32_t)(((k0 + b_krow) * SB + n0 + b_noff) * 2));
                bf[np * 2][0] = r4[0]; bf[np * 2][1] = r4[1];
                bf[np * 2 + 1][0] = r4[2]; bf[np * 2 + 1][1] = r4[3];
            }
#pragma unroll
            for (int mf = 0; mf < 4; ++mf)
#pragma unroll
                for (int nf = 0; nf < 4; ++nf)
                    mma_f16(acc[mf][nf], af[mf], bf[nf]);
        }
        __syncthreads();
    }

#pragma unroll
    for (int nf = 0; nf < 4; ++nf) {
        int col = bn + wc * 32 + nf * 8 + lc * 2;
        float b0 = bias[col], b1 = bias[col + 1];
#pragma unroll
        for (int mf = 0; mf < 4; ++mf) {
            int row = bm + wr * 64 + mf * 16 + lr;
            if (OUT_HALF) {
                __half* Ch = (__half*)Cp;
                *(__half2*)&Ch[(size_t)row * ldbc + col] =
                    __floats2half2_rn(acc[mf][nf][0] + b0, acc[mf][nf][1] + b1);
                *(__half2*)&Ch[(size_t)(row + 8) * ldbc + col] =
                    __floats2half2_rn(acc[mf][nf][2] + b0, acc[mf][nf][3] + b1);
            } else {
                float* Cf = (float*)Cp;
                *(float2*)&Cf[(size_t)row * ldbc + col] =
                    make_float2(acc[mf][nf][0] + b0, acc[mf][nf][1] + b1);
                *(float2*)&Cf[(size_t)(row + 8) * ldbc + col] =
                    make_float2(acc[mf][nf][2] + b0, acc[mf][nf][3] + b1);
            }
        }
    }
}

// ---------------- QKV: one GEMM, N = 3072 ----------------
__global__ __launch_bounds__(256)
void gemm_qkv(const __half* __restrict__ Xh, const __half* __restrict__ W3,
              const float* __restrict__ b3, __half* __restrict__ QKV)
{
    gemm_body<true>(Xh, W3, b3, QKV, N3, blockIdx.x, blockIdx.y);
}

// ===== fused attention: scores + exp + p~ store + Z + PV ====================
#define FA_ST 72
#define FA_SMEM (5 * 128 * FA_ST * 2)

__global__ __launch_bounds__(256)
void attn_fused(const __half* __restrict__ QKV, __half* __restrict__ Ph,
                __half* __restrict__ Ch)
{
    extern __shared__ __half sm[];
    const uint32_t QsB  = (uint32_t)__cvta_generic_to_shared(sm);
    const uint32_t KsB[2] = { QsB + 128 * FA_ST * 2, QsB + 2 * 128 * FA_ST * 2 };
    const uint32_t VsB[2] = { QsB + 3 * 128 * FA_ST * 2, QsB + 4 * 128 * FA_ST * 2 };

    const int tid = threadIdx.x;
    const int lane = tid & 31, warp = tid >> 5;
    const int lr = lane >> 2, lc = lane & 3;
    const int bh = blockIdx.y, b = bh >> 4, h = bh & 15;
    const int mi = blockIdx.x * 128;

    // Q load (group 0)
#pragma unroll
    for (int i = 0; i < 4; ++i) {
        int c = tid + i * 256;
        int row = c >> 3, ch = c & 7;
        cp_async16(QsB + (uint32_t)((row * FA_ST + ch * 8) * 2),
                   QKV + (size_t)(b * SS + mi + row) * N3 + h * 64 + ch * 8);
    }
    cp_commit();

    auto issueKV = [&](int jt, int buf) {
#pragma unroll
        for (int i = 0; i < 4; ++i) {
            int c = tid + i * 256;
            int row = c >> 3, ch = c & 7;
            size_t base = (size_t)(b * SS + jt * 128 + row) * N3 + h * 64 + ch * 8;
            cp_async16(KsB[buf] + (uint32_t)((row * FA_ST + ch * 8) * 2),
                       QKV + base + 1024);
            cp_async16(VsB[buf] + (uint32_t)((row * FA_ST + ch * 8) * 2),
                       QKV + base + 2048);
        }
        cp_commit();
    };
    issueKV(0, 0);

    // exp(s*g - 8) = ex2(s * g2 + C8), g2 = g*log2e, C8 = -8*log2e
    const float g2 = g_gate[bh] * 1.4426950408889634f;
    const float C8 = -11.541560327111708f;

    const int a_row  = warp * 16 + (lane & 15);
    const int a_koff = (lane >> 4) * 8;
    const int b1_nrow = (lane & 7) + (lane >> 4) * 8;
    const int b1_koff = ((lane >> 3) & 1) * 8;
    const int b2_krow = (lane & 7) + ((lane >> 3) & 1) * 8;
    const int b2_noff = (lane >> 4) * 8;

    // hoist Q fragments
    cp_wait1();
    __syncthreads();
    uint32_t qf[4][4];
#pragma unroll
    for (int ks = 0; ks < 4; ++ks)
        ldsm_x4(qf[ks], QsB + (uint32_t)((a_row * FA_ST + ks * 16 + a_koff) * 2));

    float ctx[8][4];
#pragma unroll
    for (int i = 0; i < 8; ++i)
#pragma unroll
        for (int r = 0; r < 4; ++r) ctx[i][r] = 0.0f;
    float zs0 = 0.0f, zs1 = 0.0f;

    const int grow = mi + warp * 16 + lr;
    __half* Prow0 = Ph + ((size_t)bh * SS + grow) * SS;
    __half* Prow1 = Ph + ((size_t)bh * SS + grow + 8) * SS;

    for (int jt = 0; jt < 16; ++jt) {
        const int buf = jt & 1;
        if (jt + 1 < 16) { issueKV(jt + 1, buf ^ 1); cp_wait1(); }
        else cp_wait0();
        __syncthreads();

        float acc[16][4];
#pragma unroll
        for (int i = 0; i < 16; ++i)
#pragma unroll
            for (int r = 0; r < 4; ++r) acc[i][r] = 0.0f;

#pragma unroll
        for (int ks = 0; ks < 4; ++ks) {
#pragma unroll
            for (int np = 0; np < 8; ++np) {
                uint32_t r4[4];
                ldsm_x4(r4, KsB[buf] +
                        (uint32_t)(((np * 16 + b1_nrow) * FA_ST + ks * 16 + b1_koff) * 2));
                mma_f16(acc[np * 2], qf[ks], r4);
                mma_f16(acc[np * 2 + 1], qf[ks], r4 + 2);
            }
        }

        const int jc = jt * 128;
#pragma unroll
        for (int kp = 0; kp < 8; ++kp) {
            float pa0 = fminf(ex2(fmaf(acc[2 * kp][0], g2, C8)), 60000.0f);
            float pa1 = fminf(ex2(fmaf(acc[2 * kp][1], g2, C8)), 60000.0f);
            float pb0 = fminf(ex2(fmaf(acc[2 * kp][2], g2, C8)), 60000.0f);
            float pb1 = fminf(ex2(fmaf(acc[2 * kp][3], g2, C8)), 60000.0f);
            float pc0 = fminf(ex2(fmaf(acc[2 * kp + 1][0], g2, C8)), 60000.0f);
            float pc1 = fminf(ex2(fmaf(acc[2 * kp + 1][1], g2, C8)), 60000.0f);
            float pd0 = fminf(ex2(fmaf(acc[2 * kp + 1][2], g2, C8)), 60000.0f);
            float pd1 = fminf(ex2(fmaf(acc[2 * kp + 1][3], g2, C8)), 60000.0f);
            __half2 wa = __floats2half2_rn(pa0, pa1);
            __half2 wb = __floats2half2_rn(pb0, pb1);
            __half2 wc2 = __floats2half2_rn(pc0, pc1);
            __half2 wd = __floats2half2_rn(pd0, pd1);

            int col = jc + 16 * kp + 2 * lc;
            *(__half2*)&Prow0[col]     = wa;
            *(__half2*)&Prow1[col]     = wb;
            *(__half2*)&Prow0[col + 8] = wc2;
            *(__half2*)&Prow1[col + 8] = wd;

            float2 qa = __half22float2(wa), qb = __half22float2(wb);
            float2 qc = __half22float2(wc2), qd = __half22float2(wd);
            zs0 += qa.x + qa.y + qc.x + qc.y;
            zs1 += qb.x + qb.y + qd.x + qd.y;

            uint32_t af2[4] = { h2u(wa), h2u(wb), h2u(wc2), h2u(wd) };
#pragma unroll
            for (int np = 0; np < 4; ++np) {
                uint32_t r4[4];
                ldsm_x4_t(r4, VsB[buf] +
                          (uint32_t)(((kp * 16 + b2_krow) * FA_ST + np * 16 + b2_noff) * 2));
                mma_f16(ctx[np * 2], af2, r4);
                mma_f16(ctx[np * 2 + 1], af2, r4 + 2);
            }
        }
        __syncthreads();
    }

    zs0 += __shfl_xor_sync(0xffffffffu, zs0, 1);
    zs0 += __shfl_xor_sync(0xffffffffu, zs0, 2);
    zs1 += __shfl_xor_sync(0xffffffffu, zs1, 1);
    zs1 += __shfl_xor_sync(0xffffffffu, zs1, 2);
    float iz0 = 1.0f / zs0, iz1 = 1.0f / zs1;
    if (lc == 0) {
        g_invZ[(size_t)bh * SS + grow]     = iz0;
        g_invZ[(size_t)bh * SS + grow + 8] = iz1;
    }

    __half* Cc = Ch + (size_t)b * SS * EE + h * 64;
#pragma unroll
    for (int np = 0; np < 8; ++np) {
        int n = np * 8 + 2 * lc;
        *(__half2*)&Cc[(size_t)grow * EE + n] =
            __floats2half2_rn(ctx[np][0] * iz0, ctx[np][1] * iz0);
        *(__half2*)&Cc[(size_t)(grow + 8) * EE + n] =
            __floats2half2_rn(ctx[np][2] * iz1, ctx[np][3] * iz1);
    }
}

// ===== tail: out-proj GEMM (blocks 0..255) || head-mean (blocks 256..4351) ==
__global__ __launch_bounds__(256)
void tail_kernel(const __half* __restrict__ Ch, const __half* __restrict__ Who,
                 const float* __restrict__ bo, float* __restrict__ out,
                 const __half* __restrict__ Ph, float* __restrict__ om)
{
    const int bid = blockIdx.x;
    if (bid < 256) {
        gemm_body<false>(Ch, Who, bo, out, EE, bid & 7, bid >> 3);
        return;
    }
    const int id = bid - 256;
    const int i = id & (SS - 1), b = id >> 11;
    const int tid = threadIdx.x;

    float2 m[4];
#pragma unroll
    for (int r = 0; r < 4; ++r) m[r] = make_float2(0.0f, 0.0f);

    for (int h = 0; h < HH; ++h) {
        const uint4 v = *(const uint4*)(Ph + ((size_t)(b * HH + h) * SS + i) * SS + tid * 8);
        float w = g_invZ[(size_t)(b * HH + h) * SS + i] * 0.0625f;
        float2 f0 = __half22float2(*(const __half2*)&v.x);
        float2 f1 = __half22float2(*(const __half2*)&v.y);
        float2 f2 = __half22float2(*(const __half2*)&v.z);
        float2 f3 = __half22float2(*(const __half2*)&v.w);
        m[0].x = fmaf(w, f0.x, m[0].x); m[0].y = fmaf(w, f0.y, m[0].y);
        m[1].x = fmaf(w, f1.x, m[1].x); m[1].y = fmaf(w, f1.y, m[1].y);
        m[2].x = fmaf(w, f2.x, m[2].x); m[2].y = fmaf(w, f2.y, m[2].y);
        m[3].x = fmaf(w, f3.x, m[3].x); m[3].y = fmaf(w, f3.y, m[3].y);
    }
    float* o = om + (size_t)(b * SS + i) * SS + tid * 8;
    *(float4*)o       = make_float4(m[0].x, m[0].y, m[1].x, m[1].y);
    *(float4*)(o + 4) = make_float4(m[2].x, m[2].y, m[3].x, m[3].y);
}

// ---------------- launch ----------------
extern "C" void kernel_launch(void* const* d_in, const int* in_sizes, int n_in,
                              void* d_out, int out_size)
{
    const float* x   = (const float*)d_in[0];
    const float* sf  = (const float*)d_in[1];
    const float* Wq  = (const float*)d_in[2];
    const float* bq  = (const float*)d_in[3];
    const float* Wk  = (const float*)d_in[4];
    const float* bk  = (const float*)d_in[5];
    const float* Wv  = (const float*)d_in[6];
    const float* bv  = (const float*)d_in[7];
    const float* Ws1 = (const float*)d_in[8];
    const float* bs1 = (const float*)d_in[9];
    const float* Ws2 = (const float*)d_in[10];
    const float* bs2 = (const float*)d_in[11];
    const float* Wo  = (const float*)d_in[12];
    const float* bo  = (const float*)d_in[13];
    float* out = (float*)d_out;

    __half *pXh, *pW3, *pWho, *pQKV, *pCh, *pPh;
    float *pb3;
    cudaGetSymbolAddress((void**)&pXh, g_Xh);
    cudaGetSymbolAddress((void**)&pW3, g_W3);
    cudaGetSymbolAddress((void**)&pWho, g_Who);
    cudaGetSymbolAddress((void**)&pb3, g_b3);
    cudaGetSymbolAddress((void**)&pQKV, g_QKV);
    cudaGetSymbolAddress((void**)&pCh, g_CTXh);
    cudaGetSymbolAddress((void**)&pPh, g_Ph);

    // 0. prep: conversions + interleave + gate + bias combine
    prep<<<1 + 4096 + 3072 + 1024, 256>>>(x, Wq, Wk, Wv, Wo, bq, bk, bv,
                                          sf, Ws1, bs1, Ws2, bs2);

    // 1. fused QKV projection: [4096,1024] @ [1024,3072]
    gemm_qkv<<<dim3(N3 / 128, (BB * SS) / 128), 256>>>(pXh, pW3, pb3, pQKV);

    // 2. fused attention: p~ store + Z + ctx(fp16)
    cudaFuncSetAttribute(attn_fused, cudaFuncAttributeMaxDynamicSharedMemorySize, FA_SMEM);
    attn_fused<<<dim3(SS / 128, BB * HH), 256, FA_SMEM>>>(pQKV, pPh, pCh);

    // 3. tail: out-proj GEMM || head-mean (grid-partitioned co-execution)
    tail_kernel<<<256 + BB * SS, 256>>>(pCh, pWho, bo, out, pPh,
                                        out + (size_t)BB * SS * EE);

    (void)in_sizes; (void)n_in; (void)out_size;
}

// round 11
// speedup vs baseline: 2.0075x; 1.0085x over previous
#include <cuda_runtime.h>
#include <cuda_fp16.h>
#include <cstdint>
#include <cstddef>

#define BB 2
#define SS 2048
#define EE 1024
#define HH 16
#define HID 256
#define N3 3072

// ---------------- scratch (device globals: allocation-free) ----------------
__device__ __half g_Xh[(size_t)BB * SS * EE];
__device__ __half g_W3[(size_t)EE * N3];        // interleaved [k][Wq|Wk|Wv]
__device__ __half g_Who[(size_t)EE * EE];
__device__ float  g_b3[N3];
__device__ __half g_QKV[(size_t)BB * SS * N3];  // [b,s][q|k|v]
__device__ __half g_CTXh[(size_t)BB * SS * EE];
__device__ __half g_Ph[(size_t)BB * HH * SS * SS];   // 268 MB p~ = exp(s-8)
__device__ float  g_invZ[(size_t)BB * HH * SS];
__device__ float  g_gate[BB * HH];

// ---------------- helpers ----------------
__device__ __forceinline__ float ex2(float x) {
    float r; asm("ex2.approx.f32 %0, %1;" : "=f"(r) : "f"(x)); return r;
}

__device__ __forceinline__ void mma_f16(float* d, const uint32_t* a, const uint32_t* b) {
    asm volatile("mma.sync.aligned.m16n8k16.row.col.f32.f16.f16.f32 "
                 "{%0,%1,%2,%3}, {%4,%5,%6,%7}, {%8,%9}, {%0,%1,%2,%3};"
                 : "+f"(d[0]), "+f"(d[1]), "+f"(d[2]), "+f"(d[3])
                 : "r"(a[0]), "r"(a[1]), "r"(a[2]), "r"(a[3]),
                   "r"(b[0]), "r"(b[1]));
}

__device__ __forceinline__ void ldsm_x4(uint32_t* r, uint32_t addr) {
    asm volatile("ldmatrix.sync.aligned.m8n8.x4.shared.b16 {%0,%1,%2,%3}, [%4];"
                 : "=r"(r[0]), "=r"(r[1]), "=r"(r[2]), "=r"(r[3]) : "r"(addr));
}
__device__ __forceinline__ void ldsm_x4_t(uint32_t* r, uint32_t addr) {
    asm volatile("ldmatrix.sync.aligned.m8n8.x4.trans.shared.b16 {%0,%1,%2,%3}, [%4];"
                 : "=r"(r[0]), "=r"(r[1]), "=r"(r[2]), "=r"(r[3]) : "r"(addr));
}

__device__ __forceinline__ void cp_async16(uint32_t smem, const void* g) {
    asm volatile("cp.async.cg.shared.global [%0], [%1], 16;" :: "r"(smem), "l"(g));
}
__device__ __forceinline__ void cp_commit() { asm volatile("cp.async.commit_group;"); }
__device__ __forceinline__ void cp_wait0()  { asm volatile("cp.async.wait_group 0;"); }
__device__ __forceinline__ void cp_wait1()  { asm volatile("cp.async.wait_group 1;"); }

__device__ __forceinline__ uint32_t h2u(__half2 h) { return *(uint32_t*)&h; }

// ================= prep: f2h conversions + gate + bias combine ==============
__global__ __launch_bounds__(256)
void prep(const float* __restrict__ x,
          const float* __restrict__ Wq, const float* __restrict__ Wk,
          const float* __restrict__ Wv, const float* __restrict__ Wo,
          const float* __restrict__ bq, const float* __restrict__ bk,
          const float* __restrict__ bv,
          const float* __restrict__ sf,
          const float* __restrict__ Ws1, const float* __restrict__ bs1,
          const float* __restrict__ Ws2, const float* __restrict__ bs2)
{
    const int bid = blockIdx.x, tid = threadIdx.x;
    if (bid == 0) {
        __shared__ float h1[BB][HID];
        for (int b = 0; b < BB; ++b) {
            float acc = bs1[tid];
            for (int e = 0; e < EE; ++e)
                acc += sf[b * EE + e] * Ws1[(size_t)e * HID + tid];
            h1[b][tid] = fmaxf(acc, 0.0f);
        }
        __syncthreads();
        if (tid < BB * HH) {
            int b = tid / HH, h = tid % HH;
            float acc = bs2[h];
            for (int k = 0; k < HID; ++k)
                acc += h1[b][k] * Ws2[k * HH + h];
            g_gate[b * HH + h] = (1.0f / (1.0f + __expf(-acc))) * 0.125f;
        }
        for (int i = tid; i < EE; i += 256) {
            g_b3[i] = bq[i]; g_b3[EE + i] = bk[i]; g_b3[2 * EE + i] = bv[i];
        }
        return;
    }
    int t = (bid - 1) * 256 + tid;
    if (t < 1048576) {                    // X: 4M floats
        float4 v = ((const float4*)x)[t];
        ((__half2*)g_Xh)[2 * t]     = __floats2half2_rn(v.x, v.y);
        ((__half2*)g_Xh)[2 * t + 1] = __floats2half2_rn(v.z, v.w);
        return;
    }
    t -= 1048576;
    if (t < 3 * 262144) {                 // Wq/Wk/Wv interleave into [k][3N]
        int which = t / 262144;
        int u = t - which * 262144;
        const float* W = (which == 0) ? Wq : ((which == 1) ? Wk : Wv);
        float4 v = ((const float4*)W)[u];
        int k = u >> 8, n4 = u & 255;
        size_t d = (size_t)k * N3 + which * EE + n4 * 4;
        *(__half2*)&g_W3[d]     = __floats2half2_rn(v.x, v.y);
        *(__half2*)&g_W3[d + 2] = __floats2half2_rn(v.z, v.w);
        return;
    }
    t -= 3 * 262144;
    if (t < 262144) {                     // Wo
        float4 v = ((const float4*)Wo)[t];
        ((__half2*)g_Who)[2 * t]     = __floats2half2_rn(v.x, v.y);
        ((__half2*)g_Who)[2 * t + 1] = __floats2half2_rn(v.z, v.w);
    }
}

// ======= fp16 MMA GEMM body 128x128x32: C = A[M,1024] @ B[1024,N] + bias ====
template<bool OUT_HALF>
__device__ __forceinline__ void gemm_body(
    const __half* __restrict__ Ah, const __half* __restrict__ Bh,
    const float* __restrict__ bias, void* __restrict__ Cp,
    int ldbc, int bx, int by)
{
    constexpr int SA = 40;
    constexpr int SB = 136;
    __shared__ __half As[2][128 * SA];
    __shared__ __half Bs[2][32 * SB];

    const int tid = threadIdx.x;
    const int lane = tid & 31, warp = tid >> 5;
    const int wr = warp & 1, wc = warp >> 1;
    const int lr = lane >> 2, lc = lane & 3;
    const int bm = by * 128, bn = bx * 128;

    const uint32_t AsB[2] = { (uint32_t)__cvta_generic_to_shared(&As[0][0]),
                              (uint32_t)__cvta_generic_to_shared(&As[1][0]) };
    const uint32_t BsB[2] = { (uint32_t)__cvta_generic_to_shared(&Bs[0][0]),
                              (uint32_t)__cvta_generic_to_shared(&Bs[1][0]) };

    const int brow0 = tid >> 4, bch0 = tid & 15;
    const int arow0 = tid >> 2, ach0 = tid & 3;

    auto issue = [&](int kt, int buf) {
        cp_async16(AsB[buf] + (uint32_t)((arow0 * SA + ach0 * 8) * 2),
                   Ah + (size_t)(bm + arow0) * EE + kt * 32 + ach0 * 8);
        cp_async16(AsB[buf] + (uint32_t)(((arow0 + 64) * SA + ach0 * 8) * 2),
                   Ah + (size_t)(bm + arow0 + 64) * EE + kt * 32 + ach0 * 8);
        cp_async16(BsB[buf] + (uint32_t)((brow0 * SB + bch0 * 8) * 2),
                   Bh + (size_t)(kt * 32 + brow0) * ldbc + bn + bch0 * 8);
        cp_async16(BsB[buf] + (uint32_t)(((brow0 + 16) * SB + bch0 * 8) * 2),
                   Bh + (size_t)(kt * 32 + brow0 + 16) * ldbc + bn + bch0 * 8);
        cp_commit();
    };

    float acc[4][4][4];
#pragma unroll
    for (int i = 0; i < 4; ++i)
#pragma unroll
        for (int j = 0; j < 4; ++j)
#pragma unroll
            for (int r = 0; r < 4; ++r) acc[i][j][r] = 0.0f;

    const int a_row_l = wr * 64 + (lane & 15);
    const int a_koff = (lane >> 4) * 8;
    const int b_krow = (lane & 7) + ((lane >> 3) & 1) * 8;
    const int b_noff = (lane >> 4) * 8;

    const int nk = EE / 32;
    issue(0, 0);

    for (int kt = 0; kt < nk; ++kt) {
        const int buf = kt & 1;
        if (kt + 1 < nk) { issue(kt + 1, buf ^ 1); cp_wait1(); }
        else cp_wait0();
        __syncthreads();

#pragma unroll
        for (int ks = 0; ks < 2; ++ks) {
            const int k0 = ks * 16;
            uint32_t af[4][4], bf[4][2];
#pragma unroll
            for (int mf = 0; mf < 4; ++mf)
                ldsm_x4(af[mf], AsB[buf] +
                        (uint32_t)(((a_row_l + mf * 16) * SA + k0 + a_koff) * 2));
#pragma unroll
            for (int np = 0; np < 2; ++np) {
                uint32_t r4[4];
                int n0 = wc * 32 + np * 16;
                ldsm_x4_t(r4, BsB[buf] +
                          (uint32_t)(((k0 + b_krow) * SB + n0 + b_noff) * 2));
                bf[np * 2][0] = r4[0]; bf[np * 2][1] = r4[1];
                bf[np * 2 + 1][0] = r4[2]; bf[np * 2 + 1][1] = r4[3];
            }
#pragma unroll
            for (int mf = 0; mf < 4; ++mf)
#pragma unroll
                for (int nf = 0; nf < 4; ++nf)
                    mma_f16(acc[mf][nf], af[mf], bf[nf]);
        }
        __syncthreads();
    }

#pragma unroll
    for (int nf = 0; nf < 4; ++nf) {
        int col = bn + wc * 32 + nf * 8 + lc * 2;
        float b0 = bias[col], b1 = bias[col + 1];
#pragma unroll
        for (int mf = 0; mf < 4; ++mf) {
            int row = bm + wr * 64 + mf * 16 + lr;
            if (OUT_HALF) {
                __half* Ch = (__half*)Cp;
                *(__half2*)&Ch[(size_t)row * ldbc + col] =
                    __floats2half2_rn(acc[mf][nf][0] + b0, acc[mf][nf][1] + b1);
                *(__half2*)&Ch[(size_t)(row + 8) * ldbc + col] =
                    __floats2half2_rn(acc[mf][nf][2] + b0, acc[mf][nf][3] + b1);
            } else {
                float* Cf = (float*)Cp;
                *(float2*)&Cf[(size_t)row * ldbc + col] =
                    make_float2(acc[mf][nf][0] + b0, acc[mf][nf][1] + b1);
                *(float2*)&Cf[(size_t)(row + 8) * ldbc + col] =
                    make_float2(acc[mf][nf][2] + b0, acc[mf][nf][3] + b1);
            }
        }
    }
}

// ---------------- QKV: one GEMM, N = 3072 ----------------
__global__ __launch_bounds__(256)
void gemm_qkv(const __half* __restrict__ Xh, const __half* __restrict__ W3,
              const float* __restrict__ b3, __half* __restrict__ QKV)
{
    gemm_body<true>(Xh, W3, b3, QKV, N3, blockIdx.x, blockIdx.y);
}

// ===== fused attention: scores + exp + p~ store + Z + PV ====================
// 2 CTAs/SM: n-split halves keep live regs <= 128.
#define FA_ST 72
#define FA_SMEM (5 * 128 * FA_ST * 2)

__global__ __launch_bounds__(256, 2)
void attn_fused(const __half* __restrict__ QKV, __half* __restrict__ Ph,
                __half* __restrict__ Ch)
{
    extern __shared__ __half sm[];
    const uint32_t QsB  = (uint32_t)__cvta_generic_to_shared(sm);
    const uint32_t KsB[2] = { QsB + 128 * FA_ST * 2, QsB + 2 * 128 * FA_ST * 2 };
    const uint32_t VsB[2] = { QsB + 3 * 128 * FA_ST * 2, QsB + 4 * 128 * FA_ST * 2 };

    const int tid = threadIdx.x;
    const int lane = tid & 31, warp = tid >> 5;
    const int lr = lane >> 2, lc = lane & 3;
    const int bh = blockIdx.y, b = bh >> 4, h = bh & 15;
    const int mi = blockIdx.x * 128;

    // Q load (group 0)
#pragma unroll
    for (int i = 0; i < 4; ++i) {
        int c = tid + i * 256;
        int row = c >> 3, ch = c & 7;
        cp_async16(QsB + (uint32_t)((row * FA_ST + ch * 8) * 2),
                   QKV + (size_t)(b * SS + mi + row) * N3 + h * 64 + ch * 8);
    }
    cp_commit();

    auto issueKV = [&](int jt, int buf) {
#pragma unroll
        for (int i = 0; i < 4; ++i) {
            int c = tid + i * 256;
            int row = c >> 3, ch = c & 7;
            size_t base = (size_t)(b * SS + jt * 128 + row) * N3 + h * 64 + ch * 8;
            cp_async16(KsB[buf] + (uint32_t)((row * FA_ST + ch * 8) * 2),
                       QKV + base + 1024);
            cp_async16(VsB[buf] + (uint32_t)((row * FA_ST + ch * 8) * 2),
                       QKV + base + 2048);
        }
        cp_commit();
    };
    issueKV(0, 0);

    // exp(s*g - 8) = ex2(s * g2 + C8), g2 = g*log2e, C8 = -8*log2e
    const float g2 = g_gate[bh] * 1.4426950408889634f;
    const float C8 = -11.541560327111708f;

    const int a_row  = warp * 16 + (lane & 15);
    const int a_koff = (lane >> 4) * 8;
    const int b1_nrow = (lane & 7) + (lane >> 4) * 8;
    const int b1_koff = ((lane >> 3) & 1) * 8;
    const int b2_krow = (lane & 7) + ((lane >> 3) & 1) * 8;
    const int b2_noff = (lane >> 4) * 8;

    // hoist Q fragments
    cp_wait1();
    __syncthreads();
    uint32_t qf[4][4];
#pragma unroll
    for (int ks = 0; ks < 4; ++ks)
        ldsm_x4(qf[ks], QsB + (uint32_t)((a_row * FA_ST + ks * 16 + a_koff) * 2));

    float ctx[8][4];
#pragma unroll
    for (int i = 0; i < 8; ++i)
#pragma unroll
        for (int r = 0; r < 4; ++r) ctx[i][r] = 0.0f;
    float zs0 = 0.0f, zs1 = 0.0f;

    const int grow = mi + warp * 16 + lr;
    __half* Prow0 = Ph + ((size_t)bh * SS + grow) * SS;
    __half* Prow1 = Ph + ((size_t)bh * SS + grow + 8) * SS;

    for (int jt = 0; jt < 16; ++jt) {
        const int buf = jt & 1;
        if (jt + 1 < 16) { issueKV(jt + 1, buf ^ 1); cp_wait1(); }
        else cp_wait0();
        __syncthreads();

        // process 128 keys in two 64-wide halves (keeps live regs <= 128)
#pragma unroll
        for (int hf = 0; hf < 2; ++hf) {
            float acc[8][4];
#pragma unroll
            for (int i = 0; i < 8; ++i)
#pragma unroll
                for (int r = 0; r < 4; ++r) acc[i][r] = 0.0f;

#pragma unroll
            for (int ks = 0; ks < 4; ++ks) {
#pragma unroll
                for (int np = 0; np < 4; ++np) {
                    uint32_t r4[4];
                    ldsm_x4(r4, KsB[buf] +
                            (uint32_t)(((hf * 64 + np * 16 + b1_nrow) * FA_ST +
                                        ks * 16 + b1_koff) * 2));
                    mma_f16(acc[np * 2], qf[ks], r4);
                    mma_f16(acc[np * 2 + 1], qf[ks], r4 + 2);
                }
            }

            const int jc = jt * 128 + hf * 64;
#pragma unroll
            for (int kp = 0; kp < 4; ++kp) {
                float pa0 = fminf(ex2(fmaf(acc[2 * kp][0], g2, C8)), 60000.0f);
                float pa1 = fminf(ex2(fmaf(acc[2 * kp][1], g2, C8)), 60000.0f);
                float pb0 = fminf(ex2(fmaf(acc[2 * kp][2], g2, C8)), 60000.0f);
                float pb1 = fminf(ex2(fmaf(acc[2 * kp][3], g2, C8)), 60000.0f);
                float pc0 = fminf(ex2(fmaf(acc[2 * kp + 1][0], g2, C8)), 60000.0f);
                float pc1 = fminf(ex2(fmaf(acc[2 * kp + 1][1], g2, C8)), 60000.0f);
                float pd0 = fminf(ex2(fmaf(acc[2 * kp + 1][2], g2, C8)), 60000.0f);
                float pd1 = fminf(ex2(fmaf(acc[2 * kp + 1][3], g2, C8)), 60000.0f);
                __half2 wa = __floats2half2_rn(pa0, pa1);
                __half2 wb = __floats2half2_rn(pb0, pb1);
                __half2 wc2 = __floats2half2_rn(pc0, pc1);
                __half2 wd = __floats2half2_rn(pd0, pd1);

                int col = jc + 16 * kp + 2 * lc;
                *(__half2*)&Prow0[col]     = wa;
                *(__half2*)&Prow1[col]     = wb;
                *(__half2*)&Prow0[col + 8] = wc2;
                *(__half2*)&Prow1[col + 8] = wd;

                float2 qa = __half22float2(wa), qb = __half22float2(wb);
                float2 qc = __half22float2(wc2), qd = __half22float2(wd);
                zs0 += qa.x + qa.y + qc.x + qc.y;
                zs1 += qb.x + qb.y + qd.x + qd.y;

                uint32_t af2[4] = { h2u(wa), h2u(wb), h2u(wc2), h2u(wd) };
#pragma unroll
                for (int np = 0; np < 4; ++np) {
                    uint32_t r4[4];
                    ldsm_x4_t(r4, VsB[buf] +
                              (uint32_t)(((hf * 64 + kp * 16 + b2_krow) * FA_ST +
                                          np * 16 + b2_noff) * 2));
                    mma_f16(ctx[np * 2], af2, r4);
                    mma_f16(ctx[np * 2 + 1], af2, r4 + 2);
                }
            }
        }
        __syncthreads();
    }

    zs0 += __shfl_xor_sync(0xffffffffu, zs0, 1);
    zs0 += __shfl_xor_sync(0xffffffffu, zs0, 2);
    zs1 += __shfl_xor_sync(0xffffffffu, zs1, 1);
    zs1 += __shfl_xor_sync(0xffffffffu, zs1, 2);
    float iz0 = 1.0f / zs0, iz1 = 1.0f / zs1;
    if (lc == 0) {
        g_invZ[(size_t)bh * SS + grow]     = iz0;
        g_invZ[(size_t)bh * SS + grow + 8] = iz1;
    }

    __half* Cc = Ch + (size_t)b * SS * EE + h * 64;
#pragma unroll
    for (int np = 0; np < 8; ++np) {
        int n = np * 8 + 2 * lc;
        *(__half2*)&Cc[(size_t)grow * EE + n] =
            __floats2half2_rn(ctx[np][0] * iz0, ctx[np][1] * iz0);
        *(__half2*)&Cc[(size_t)(grow + 8) * EE + n] =
            __floats2half2_rn(ctx[np][2] * iz1, ctx[np][3] * iz1);
    }
}

// ===== tail: out-proj GEMM (blocks 0..255) || head-mean (blocks 256..4351) ==
__global__ __launch_bounds__(256)
void tail_kernel(const __half* __restrict__ Ch, const __half* __restrict__ Who,
                 const float* __restrict__ bo, float* __restrict__ out,
                 const __half* __restrict__ Ph, float* __restrict__ om)
{
    const int bid = blockIdx.x;
    if (bid < 256) {
        gemm_body<false>(Ch, Who, bo, out, EE, bid & 7, bid >> 3);
        return;
    }
    const int id = bid - 256;
    const int i = id & (SS - 1), b = id >> 11;
    const int tid = threadIdx.x;

    float2 m[4];
#pragma unroll
    for (int r = 0; r < 4; ++r) m[r] = make_float2(0.0f, 0.0f);

    for (int h = 0; h < HH; ++h) {
        const uint4 v = *(const uint4*)(Ph + ((size_t)(b * HH + h) * SS + i) * SS + tid * 8);
        float w = g_invZ[(size_t)(b * HH + h) * SS + i] * 0.0625f;
        float2 f0 = __half22float2(*(const __half2*)&v.x);
        float2 f1 = __half22float2(*(const __half2*)&v.y);
        float2 f2 = __half22float2(*(const __half2*)&v.z);
        float2 f3 = __half22float2(*(const __half2*)&v.w);
        m[0].x = fmaf(w, f0.x, m[0].x); m[0].y = fmaf(w, f0.y, m[0].y);
        m[1].x = fmaf(w, f1.x, m[1].x); m[1].y = fmaf(w, f1.y, m[1].y);
        m[2].x = fmaf(w, f2.x, m[2].x); m[2].y = fmaf(w, f2.y, m[2].y);
        m[3].x = fmaf(w, f3.x, m[3].x); m[3].y = fmaf(w, f3.y, m[3].y);
    }
    float* o = om + (size_t)(b * SS + i) * SS + tid * 8;
    *(float4*)o       = make_float4(m[0].x, m[0].y, m[1].x, m[1].y);
    *(float4*)(o + 4) = make_float4(m[2].x, m[2].y, m[3].x, m[3].y);
}

// ---------------- launch ----------------
extern "C" void kernel_launch(void* const* d_in, const int* in_sizes, int n_in,
                              void* d_out, int out_size)
{
    const float* x   = (const float*)d_in[0];
    const float* sf  = (const float*)d_in[1];
    const float* Wq  = (const float*)d_in[2];
    const float* bq  = (const float*)d_in[3];
    const float* Wk  = (const float*)d_in[4];
    const float* bk  = (const float*)d_in[5];
    const float* Wv  = (const float*)d_in[6];
    const float* bv  = (const float*)d_in[7];
    const float* Ws1 = (const float*)d_in[8];
    const float* bs1 = (const float*)d_in[9];
    const float* Ws2 = (const float*)d_in[10];
    const float* bs2 = (const float*)d_in[11];
    const float* Wo  = (const float*)d_in[12];
    const float* bo  = (const float*)d_in[13];
    float* out = (float*)d_out;

    __half *pXh, *pW3, *pWho, *pQKV, *pCh, *pPh;
    float *pb3;
    cudaGetSymbolAddress((void**)&pXh, g_Xh);
    cudaGetSymbolAddress((void**)&pW3, g_W3);
    cudaGetSymbolAddress((void**)&pWho, g_Who);
    cudaGetSymbolAddress((void**)&pb3, g_b3);
    cudaGetSymbolAddress((void**)&pQKV, g_QKV);
    cudaGetSymbolAddress((void**)&pCh, g_CTXh);
    cudaGetSymbolAddress((void**)&pPh, g_Ph);

    // 0. prep: conversions + interleave + gate + bias combine
    prep<<<1 + 4096 + 3072 + 1024, 256>>>(x, Wq, Wk, Wv, Wo, bq, bk, bv,
                                          sf, Ws1, bs1, Ws2, bs2);

    // 1. fused QKV projection: [4096,1024] @ [1024,3072]
    gemm_qkv<<<dim3(N3 / 128, (BB * SS) / 128), 256>>>(pXh, pW3, pb3, pQKV);

    // 2. fused attention: p~ store + Z + ctx(fp16), 2 CTAs/SM
    cudaFuncSetAttribute(attn_fused, cudaFuncAttributeMaxDynamicSharedMemorySize, FA_SMEM);
    attn_fused<<<dim3(SS / 128, BB * HH), 256, FA_SMEM>>>(pQKV, pPh, pCh);

    // 3. tail: out-proj GEMM || head-mean (grid-partitioned co-execution)
    tail_kernel<<<256 + BB * SS, 256>>>(pCh, pWho, bo, out, pPh,
                                        out + (size_t)BB * SS * EE);

    (void)in_sizes; (void)n_in; (void)out_size;
}

// round 12
// speedup vs baseline: 2.1096x; 1.0508x over previous
#include <cuda_runtime.h>
#include <cuda_fp16.h>
#include <cstdint>
#include <cstddef>

#define BB 2
#define SS 2048
#define EE 1024
#define HH 16
#define HID 256
#define N3 3072

// ---------------- scratch (device globals: allocation-free) ----------------
__device__ __half g_Xh[(size_t)BB * SS * EE];
__device__ __half g_W3[(size_t)EE * N3];        // interleaved [k][Wq|Wk|Wv]
__device__ __half g_Who[(size_t)EE * EE];
__device__ float  g_b3[N3];
__device__ __half g_QKV[(size_t)BB * SS * N3];  // [b,s][q|k|v]
__device__ __half g_CTXh[(size_t)BB * SS * EE];
// p~ stored in PERMUTED block-16 layout:
// P'[row][blk16][s], s = 4*((c&7)>>1) + (c&1) + ((c&8)?2:0), c = col within block
__device__ __half g_Ph[(size_t)BB * HH * SS * SS];
__device__ float  g_invZ[(size_t)BB * HH * SS];
__device__ float  g_gate[BB * HH];

// ---------------- helpers ----------------
__device__ __forceinline__ float ex2(float x) {
    float r; asm("ex2.approx.f32 %0, %1;" : "=f"(r) : "f"(x)); return r;
}

__device__ __forceinline__ void mma_f16(float* d, const uint32_t* a, const uint32_t* b) {
    asm volatile("mma.sync.aligned.m16n8k16.row.col.f32.f16.f16.f32 "
                 "{%0,%1,%2,%3}, {%4,%5,%6,%7}, {%8,%9}, {%0,%1,%2,%3};"
                 : "+f"(d[0]), "+f"(d[1]), "+f"(d[2]), "+f"(d[3])
                 : "r"(a[0]), "r"(a[1]), "r"(a[2]), "r"(a[3]),
                   "r"(b[0]), "r"(b[1]));
}

__device__ __forceinline__ void ldsm_x4(uint32_t* r, uint32_t addr) {
    asm volatile("ldmatrix.sync.aligned.m8n8.x4.shared.b16 {%0,%1,%2,%3}, [%4];"
                 : "=r"(r[0]), "=r"(r[1]), "=r"(r[2]), "=r"(r[3]) : "r"(addr));
}
__device__ __forceinline__ void ldsm_x4_t(uint32_t* r, uint32_t addr) {
    asm volatile("ldmatrix.sync.aligned.m8n8.x4.trans.shared.b16 {%0,%1,%2,%3}, [%4];"
                 : "=r"(r[0]), "=r"(r[1]), "=r"(r[2]), "=r"(r[3]) : "r"(addr));
}

__device__ __forceinline__ void cp_async16(uint32_t smem, const void* g) {
    asm volatile("cp.async.cg.shared.global [%0], [%1], 16;" :: "r"(smem), "l"(g));
}
__device__ __forceinline__ void cp_commit() { asm volatile("cp.async.commit_group;"); }
__device__ __forceinline__ void cp_wait0()  { asm volatile("cp.async.wait_group 0;"); }
__device__ __forceinline__ void cp_wait1()  { asm volatile("cp.async.wait_group 1;"); }

__device__ __forceinline__ uint32_t h2u(__half2 h) { return *(uint32_t*)&h; }

// ================= prep: f2h conversions + gate + bias combine ==============
__global__ __launch_bounds__(256)
void prep(const float* __restrict__ x,
          const float* __restrict__ Wq, const float* __restrict__ Wk,
          const float* __restrict__ Wv, const float* __restrict__ Wo,
          const float* __restrict__ bq, const float* __restrict__ bk,
          const float* __restrict__ bv,
          const float* __restrict__ sf,
          const float* __restrict__ Ws1, const float* __restrict__ bs1,
          const float* __restrict__ Ws2, const float* __restrict__ bs2)
{
    const int bid = blockIdx.x, tid = threadIdx.x;
    if (bid == 0) {
        __shared__ float h1[BB][HID];
        for (int b = 0; b < BB; ++b) {
            float acc = bs1[tid];
            for (int e = 0; e < EE; ++e)
                acc += sf[b * EE + e] * Ws1[(size_t)e * HID + tid];
            h1[b][tid] = fmaxf(acc, 0.0f);
        }
        __syncthreads();
        if (tid < BB * HH) {
            int b = tid / HH, h = tid % HH;
            float acc = bs2[h];
            for (int k = 0; k < HID; ++k)
                acc += h1[b][k] * Ws2[k * HH + h];
            g_gate[b * HH + h] = (1.0f / (1.0f + __expf(-acc))) * 0.125f;
        }
        for (int i = tid; i < EE; i += 256) {
            g_b3[i] = bq[i]; g_b3[EE + i] = bk[i]; g_b3[2 * EE + i] = bv[i];
        }
        return;
    }
    int t = (bid - 1) * 256 + tid;
    if (t < 1048576) {                    // X: 4M floats
        float4 v = ((const float4*)x)[t];
        ((__half2*)g_Xh)[2 * t]     = __floats2half2_rn(v.x, v.y);
        ((__half2*)g_Xh)[2 * t + 1] = __floats2half2_rn(v.z, v.w);
        return;
    }
    t -= 1048576;
    if (t < 3 * 262144) {                 // Wq/Wk/Wv interleave into [k][3N]
        int which = t / 262144;
        int u = t - which * 262144;
        const float* W = (which == 0) ? Wq : ((which == 1) ? Wk : Wv);
        float4 v = ((const float4*)W)[u];
        int k = u >> 8, n4 = u & 255;
        size_t d = (size_t)k * N3 + which * EE + n4 * 4;
        *(__half2*)&g_W3[d]     = __floats2half2_rn(v.x, v.y);
        *(__half2*)&g_W3[d + 2] = __floats2half2_rn(v.z, v.w);
        return;
    }
    t -= 3 * 262144;
    if (t < 262144) {                     // Wo
        float4 v = ((const float4*)Wo)[t];
        ((__half2*)g_Who)[2 * t]     = __floats2half2_rn(v.x, v.y);
        ((__half2*)g_Who)[2 * t + 1] = __floats2half2_rn(v.z, v.w);
    }
}

// ======= fp16 MMA GEMM body 128x128x32: C = A[M,1024] @ B[1024,N] + bias ====
template<bool OUT_HALF>
__device__ __forceinline__ void gemm_body(
    const __half* __restrict__ Ah, const __half* __restrict__ Bh,
    const float* __restrict__ bias, void* __restrict__ Cp,
    int ldbc, int bx, int by)
{
    constexpr int SA = 40;
    constexpr int SB = 136;
    __shared__ __half As[2][128 * SA];
    __shared__ __half Bs[2][32 * SB];

    const int tid = threadIdx.x;
    const int lane = tid & 31, warp = tid >> 5;
    const int wr = warp & 1, wc = warp >> 1;
    const int lr = lane >> 2, lc = lane & 3;
    const int bm = by * 128, bn = bx * 128;

    const uint32_t AsB[2] = { (uint32_t)__cvta_generic_to_shared(&As[0][0]),
                              (uint32_t)__cvta_generic_to_shared(&As[1][0]) };
    const uint32_t BsB[2] = { (uint32_t)__cvta_generic_to_shared(&Bs[0][0]),
                              (uint32_t)__cvta_generic_to_shared(&Bs[1][0]) };

    const int brow0 = tid >> 4, bch0 = tid & 15;
    const int arow0 = tid >> 2, ach0 = tid & 3;

    auto issue = [&](int kt, int buf) {
        cp_async16(AsB[buf] + (uint32_t)((arow0 * SA + ach0 * 8) * 2),
                   Ah + (size_t)(bm + arow0) * EE + kt * 32 + ach0 * 8);
        cp_async16(AsB[buf] + (uint32_t)(((arow0 + 64) * SA + ach0 * 8) * 2),
                   Ah + (size_t)(bm + arow0 + 64) * EE + kt * 32 + ach0 * 8);
        cp_async16(BsB[buf] + (uint32_t)((brow0 * SB + bch0 * 8) * 2),
                   Bh + (size_t)(kt * 32 + brow0) * ldbc + bn + bch0 * 8);
        cp_async16(BsB[buf] + (uint32_t)(((brow0 + 16) * SB + bch0 * 8) * 2),
                   Bh + (size_t)(kt * 32 + brow0 + 16) * ldbc + bn + bch0 * 8);
        cp_commit();
    };

    float acc[4][4][4];
#pragma unroll
    for (int i = 0; i < 4; ++i)
#pragma unroll
        for (int j = 0; j < 4; ++j)
#pragma unroll
            for (int r = 0; r < 4; ++r) acc[i][j][r] = 0.0f;

    const int a_row_l = wr * 64 + (lane & 15);
    const int a_koff = (lane >> 4) * 8;
    const int b_krow = (lane & 7) + ((lane >> 3) & 1) * 8;
    const int b_noff = (lane >> 4) * 8;

    const int nk = EE / 32;
    issue(0, 0);

    for (int kt = 0; kt < nk; ++kt) {
        const int buf = kt & 1;
        if (kt + 1 < nk) { issue(kt + 1, buf ^ 1); cp_wait1(); }
        else cp_wait0();
        __syncthreads();

#pragma unroll
        for (int ks = 0; ks < 2; ++ks) {
            const int k0 = ks * 16;
            uint32_t af[4][4], bf[4][2];
#pragma unroll
            for (int mf = 0; mf < 4; ++mf)
                ldsm_x4(af[mf], AsB[buf] +
                        (uint32_t)(((a_row_l + mf * 16) * SA + k0 + a_koff) * 2));
#pragma unroll
            for (int np = 0; np < 2; ++np) {
                uint32_t r4[4];
                int n0 = wc * 32 + np * 16;
                ldsm_x4_t(r4, BsB[buf] +
                          (uint32_t)(((k0 + b_krow) * SB + n0 + b_noff) * 2));
                bf[np * 2][0] = r4[0]; bf[np * 2][1] = r4[1];
                bf[np * 2 + 1][0] = r4[2]; bf[np * 2 + 1][1] = r4[3];
            }
#pragma unroll
            for (int mf = 0; mf < 4; ++mf)
#pragma unroll
                for (int nf = 0; nf < 4; ++nf)
                    mma_f16(acc[mf][nf], af[mf], bf[nf]);
        }
        __syncthreads();
    }

#pragma unroll
    for (int nf = 0; nf < 4; ++nf) {
        int col = bn + wc * 32 + nf * 8 + lc * 2;
        float b0 = bias[col], b1 = bias[col + 1];
#pragma unroll
        for (int mf = 0; mf < 4; ++mf) {
            int row = bm + wr * 64 + mf * 16 + lr;
            if (OUT_HALF) {
                __half* Ch = (__half*)Cp;
                *(__half2*)&Ch[(size_t)row * ldbc + col] =
                    __floats2half2_rn(acc[mf][nf][0] + b0, acc[mf][nf][1] + b1);
                *(__half2*)&Ch[(size_t)(row + 8) * ldbc + col] =
                    __floats2half2_rn(acc[mf][nf][2] + b0, acc[mf][nf][3] + b1);
            } else {
                float* Cf = (float*)Cp;
                *(float2*)&Cf[(size_t)row * ldbc + col] =
                    make_float2(acc[mf][nf][0] + b0, acc[mf][nf][1] + b1);
                *(float2*)&Cf[(size_t)(row + 8) * ldbc + col] =
                    make_float2(acc[mf][nf][2] + b0, acc[mf][nf][3] + b1);
            }
        }
    }
}

// ---------------- QKV: one GEMM, N = 3072 ----------------
__global__ __launch_bounds__(256)
void gemm_qkv(const __half* __restrict__ Xh, const __half* __restrict__ W3,
              const float* __restrict__ b3, __half* __restrict__ QKV)
{
    gemm_body<true>(Xh, W3, b3, QKV, N3, blockIdx.x, blockIdx.y);
}

// ===== fused attention: scores + exp + p~ store (permuted) + Z + PV =========
#define FA_ST 72
#define FA_SMEM (5 * 128 * FA_ST * 2)

__global__ __launch_bounds__(256, 2)
void attn_fused(const __half* __restrict__ QKV, __half* __restrict__ Ph,
                __half* __restrict__ Ch)
{
    extern __shared__ __half sm[];
    const uint32_t QsB  = (uint32_t)__cvta_generic_to_shared(sm);
    const uint32_t KsB[2] = { QsB + 128 * FA_ST * 2, QsB + 2 * 128 * FA_ST * 2 };
    const uint32_t VsB[2] = { QsB + 3 * 128 * FA_ST * 2, QsB + 4 * 128 * FA_ST * 2 };

    const int tid = threadIdx.x;
    const int lane = tid & 31, warp = tid >> 5;
    const int lr = lane >> 2, lc = lane & 3;
    const int bh = blockIdx.y, b = bh >> 4, h = bh & 15;
    const int mi = blockIdx.x * 128;

    // Q load (group 0)
#pragma unroll
    for (int i = 0; i < 4; ++i) {
        int c = tid + i * 256;
        int row = c >> 3, ch = c & 7;
        cp_async16(QsB + (uint32_t)((row * FA_ST + ch * 8) * 2),
                   QKV + (size_t)(b * SS + mi + row) * N3 + h * 64 + ch * 8);
    }
    cp_commit();

    auto issueKV = [&](int jt, int buf) {
#pragma unroll
        for (int i = 0; i < 4; ++i) {
            int c = tid + i * 256;
            int row = c >> 3, ch = c & 7;
            size_t base = (size_t)(b * SS + jt * 128 + row) * N3 + h * 64 + ch * 8;
            cp_async16(KsB[buf] + (uint32_t)((row * FA_ST + ch * 8) * 2),
                       QKV + base + 1024);
            cp_async16(VsB[buf] + (uint32_t)((row * FA_ST + ch * 8) * 2),
                       QKV + base + 2048);
        }
        cp_commit();
    };
    issueKV(0, 0);

    // exp(s*g - 8) = ex2(s * g2 + C8)
    const float g2 = g_gate[bh] * 1.4426950408889634f;
    const float C8 = -11.541560327111708f;

    const int a_row  = warp * 16 + (lane & 15);
    const int a_koff = (lane >> 4) * 8;
    const int b1_nrow = (lane & 7) + (lane >> 4) * 8;
    const int b1_koff = ((lane >> 3) & 1) * 8;
    const int b2_krow = (lane & 7) + ((lane >> 3) & 1) * 8;
    const int b2_noff = (lane >> 4) * 8;

    // hoist Q fragments
    cp_wait1();
    __syncthreads();
    uint32_t qf[4][4];
#pragma unroll
    for (int ks = 0; ks < 4; ++ks)
        ldsm_x4(qf[ks], QsB + (uint32_t)((a_row * FA_ST + ks * 16 + a_koff) * 2));

    float ctx[8][4];
#pragma unroll
    for (int i = 0; i < 8; ++i)
#pragma unroll
        for (int r = 0; r < 4; ++r) ctx[i][r] = 0.0f;
    float zs0 = 0.0f, zs1 = 0.0f;

    const int grow = mi + warp * 16 + lr;
    __half* Prow0 = Ph + ((size_t)bh * SS + grow) * SS;
    __half* Prow1 = Ph + ((size_t)bh * SS + grow + 8) * SS;

    for (int jt = 0; jt < 16; ++jt) {
        const int buf = jt & 1;
        if (jt + 1 < 16) { issueKV(jt + 1, buf ^ 1); cp_wait1(); }
        else cp_wait0();
        __syncthreads();

#pragma unroll
        for (int hf = 0; hf < 2; ++hf) {
            float acc[8][4];
#pragma unroll
            for (int i = 0; i < 8; ++i)
#pragma unroll
                for (int r = 0; r < 4; ++r) acc[i][r] = 0.0f;

#pragma unroll
            for (int ks = 0; ks < 4; ++ks) {
#pragma unroll
                for (int np = 0; np < 4; ++np) {
                    uint32_t r4[4];
                    ldsm_x4(r4, KsB[buf] +
                            (uint32_t)(((hf * 64 + np * 16 + b1_nrow) * FA_ST +
                                        ks * 16 + b1_koff) * 2));
                    mma_f16(acc[np * 2], qf[ks], r4);
                    mma_f16(acc[np * 2 + 1], qf[ks], r4 + 2);
                }
            }

            const int jc = jt * 128 + hf * 64;
#pragma unroll
            for (int kp = 0; kp < 4; ++kp) {
                // p~ = exp(s*g - 8); no clamp: g<=0.125 bounds arg <= -4
                float pa0 = ex2(fmaf(acc[2 * kp][0], g2, C8));
                float pa1 = ex2(fmaf(acc[2 * kp][1], g2, C8));
                float pb0 = ex2(fmaf(acc[2 * kp][2], g2, C8));
                float pb1 = ex2(fmaf(acc[2 * kp][3], g2, C8));
                float pc0 = ex2(fmaf(acc[2 * kp + 1][0], g2, C8));
                float pc1 = ex2(fmaf(acc[2 * kp + 1][1], g2, C8));
                float pd0 = ex2(fmaf(acc[2 * kp + 1][2], g2, C8));
                float pd1 = ex2(fmaf(acc[2 * kp + 1][3], g2, C8));
                __half2 wa = __floats2half2_rn(pa0, pa1);   // row lr,   cols 2lc,2lc+1
                __half2 wb = __floats2half2_rn(pb0, pb1);   // row lr+8
                __half2 wc2 = __floats2half2_rn(pc0, pc1);  // row lr,   cols 2lc+8,+9
                __half2 wd = __floats2half2_rn(pd0, pd1);   // row lr+8

                // permuted block-16 store: s = 4*lc + {0,1,2,3} <-> cols {2lc,2lc+1,2lc+8,2lc+9}
                int poff = jc + 16 * kp + 4 * lc;
                *(uint2*)&Prow0[poff] = make_uint2(h2u(wa), h2u(wc2));
                *(uint2*)&Prow1[poff] = make_uint2(h2u(wb), h2u(wd));

                zs0 += (pa0 + pa1) + (pc0 + pc1);
                zs1 += (pb0 + pb1) + (pd0 + pd1);

                uint32_t af2[4] = { h2u(wa), h2u(wb), h2u(wc2), h2u(wd) };
#pragma unroll
                for (int np = 0; np < 4; ++np) {
                    uint32_t r4[4];
                    ldsm_x4_t(r4, VsB[buf] +
                              (uint32_t)(((hf * 64 + kp * 16 + b2_krow) * FA_ST +
                                          np * 16 + b2_noff) * 2));
                    mma_f16(ctx[np * 2], af2, r4);
                    mma_f16(ctx[np * 2 + 1], af2, r4 + 2);
                }
            }
        }
        __syncthreads();
    }

    zs0 += __shfl_xor_sync(0xffffffffu, zs0, 1);
    zs0 += __shfl_xor_sync(0xffffffffu, zs0, 2);
    zs1 += __shfl_xor_sync(0xffffffffu, zs1, 1);
    zs1 += __shfl_xor_sync(0xffffffffu, zs1, 2);
    float iz0 = 1.0f / zs0, iz1 = 1.0f / zs1;
    if (lc == 0) {
        g_invZ[(size_t)bh * SS + grow]     = iz0;
        g_invZ[(size_t)bh * SS + grow + 8] = iz1;
    }

    __half* Cc = Ch + (size_t)b * SS * EE + h * 64;
#pragma unroll
    for (int np = 0; np < 8; ++np) {
        int n = np * 8 + 2 * lc;
        *(__half2*)&Cc[(size_t)grow * EE + n] =
            __floats2half2_rn(ctx[np][0] * iz0, ctx[np][1] * iz0);
        *(__half2*)&Cc[(size_t)(grow + 8) * EE + n] =
            __floats2half2_rn(ctx[np][2] * iz1, ctx[np][3] * iz1);
    }
}

// ===== tail: out-proj GEMM (blocks 0..255) || head-mean (blocks 256..2303) ==
// Mean reads the PERMUTED P layout and unpermutes before writing.
__global__ __launch_bounds__(256)
void tail_kernel(const __half* __restrict__ Ch, const __half* __restrict__ Who,
                 const float* __restrict__ bo, float* __restrict__ out,
                 const __half* __restrict__ Ph, float* __restrict__ om)
{
    const int bid = blockIdx.x;
    if (bid < 256) {
        gemm_body<false>(Ch, Who, bo, out, EE, bid & 7, bid >> 3);
        return;
    }
    // mean: 2048 blocks; each handles 2 rows; 128 threads per row, 1 block16 each
    const int id = bid - 256;                 // 0..2047
    const int b = id >> 10;                   // SS/2 = 1024 row-pairs per batch
    const int ipair = id & 1023;
    const int tid = threadIdx.x;
    const int row = ipair * 2 + (tid >> 7);   // local row in batch
    const int blk = tid & 127;                // block16 index (128 per row)

    float acc[16];
#pragma unroll
    for (int s = 0; s < 16; ++s) acc[s] = 0.0f;

    for (int hh = 0; hh < HH; ++hh) {
        const __half* base = Ph + ((size_t)(b * HH + hh) * SS + row) * SS + blk * 16;
        uint4 v0 = *(const uint4*)base;
        uint4 v1 = *(const uint4*)(base + 8);
        float w = g_invZ[(size_t)(b * HH + hh) * SS + row] * 0.0625f;
        const uint32_t* vv = (const uint32_t*)&v0;
#pragma unroll
        for (int q = 0; q < 4; ++q) {
            float2 f = __half22float2(*(const __half2*)&vv[q]);
            acc[2 * q]     = fmaf(w, f.x, acc[2 * q]);
            acc[2 * q + 1] = fmaf(w, f.y, acc[2 * q + 1]);
        }
        const uint32_t* vw = (const uint32_t*)&v1;
#pragma unroll
        for (int q = 0; q < 4; ++q) {
            float2 f = __half22float2(*(const __half2*)&vw[q]);
            acc[8 + 2 * q]     = fmaf(w, f.x, acc[8 + 2 * q]);
            acc[8 + 2 * q + 1] = fmaf(w, f.y, acc[8 + 2 * q + 1]);
        }
    }

    // unpermute: actual col c -> stored s = 4*((c&7)>>1) + (c&1) + ((c&8)?2:0)
    float o[16];
#pragma unroll
    for (int c = 0; c < 16; ++c)
        o[c] = acc[4 * ((c & 7) >> 1) + (c & 1) + ((c & 8) ? 2 : 0)];

    float* op = om + (size_t)(b * SS + row) * SS + blk * 16;
    *(float4*)&op[0]  = make_float4(o[0],  o[1],  o[2],  o[3]);
    *(float4*)&op[4]  = make_float4(o[4],  o[5],  o[6],  o[7]);
    *(float4*)&op[8]  = make_float4(o[8],  o[9],  o[10], o[11]);
    *(float4*)&op[12] = make_float4(o[12], o[13], o[14], o[15]);
}

// ---------------- launch ----------------
extern "C" void kernel_launch(void* const* d_in, const int* in_sizes, int n_in,
                              void* d_out, int out_size)
{
    const float* x   = (const float*)d_in[0];
    const float* sf  = (const float*)d_in[1];
    const float* Wq  = (const float*)d_in[2];
    const float* bq  = (const float*)d_in[3];
    const float* Wk  = (const float*)d_in[4];
    const float* bk  = (const float*)d_in[5];
    const float* Wv  = (const float*)d_in[6];
    const float* bv  = (const float*)d_in[7];
    const float* Ws1 = (const float*)d_in[8];
    const float* bs1 = (const float*)d_in[9];
    const float* Ws2 = (const float*)d_in[10];
    const float* bs2 = (const float*)d_in[11];
    const float* Wo  = (const float*)d_in[12];
    const float* bo  = (const float*)d_in[13];
    float* out = (float*)d_out;

    __half *pXh, *pW3, *pWho, *pQKV, *pCh, *pPh;
    float *pb3;
    cudaGetSymbolAddress((void**)&pXh, g_Xh);
    cudaGetSymbolAddress((void**)&pW3, g_W3);
    cudaGetSymbolAddress((void**)&pWho, g_Who);
    cudaGetSymbolAddress((void**)&pb3, g_b3);
    cudaGetSymbolAddress((void**)&pQKV, g_QKV);
    cudaGetSymbolAddress((void**)&pCh, g_CTXh);
    cudaGetSymbolAddress((void**)&pPh, g_Ph);

    // 0. prep: conversions + interleave + gate + bias combine
    prep<<<1 + 4096 + 3072 + 1024, 256>>>(x, Wq, Wk, Wv, Wo, bq, bk, bv,
                                          sf, Ws1, bs1, Ws2, bs2);

    // 1. fused QKV projection: [4096,1024] @ [1024,3072]
    gemm_qkv<<<dim3(N3 / 128, (BB * SS) / 128), 256>>>(pXh, pW3, pb3, pQKV);

    // 2. fused attention: permuted p~ store + Z + ctx(fp16)
    cudaFuncSetAttribute(attn_fused, cudaFuncAttributeMaxDynamicSharedMemorySize, FA_SMEM);
    attn_fused<<<dim3(SS / 128, BB * HH), 256, FA_SMEM>>>(pQKV, pPh, pCh);

    // 3. tail: out-proj GEMM || head-mean (grid-partitioned co-execution)
    tail_kernel<<<256 + (BB * SS) / 2, 256>>>(pCh, pWho, bo, out, pPh,
                                              out + (size_t)BB * SS * EE);

    (void)in_sizes; (void)n_in; (void)out_size;
}

// round 13
// speedup vs baseline: 2.1489x; 1.0186x over previous
#include <cuda_runtime.h>
#include <cuda_fp16.h>
#include <cstdint>
#include <cstddef>

#define BB 2
#define SS 2048
#define EE 1024
#define HH 16
#define HID 256
#define N3 3072

// ---------------- scratch (device globals: allocation-free) ----------------
__device__ __half g_Xh[(size_t)BB * SS * EE];
__device__ __half g_W3[(size_t)EE * N3];        // interleaved [k][Wq|Wk|Wv]
__device__ __half g_Who[(size_t)EE * EE];
__device__ float  g_b3[N3];
__device__ __half g_QKV[(size_t)BB * SS * N3];  // [b,s][q|k|v]
__device__ __half g_CTXh[(size_t)BB * SS * EE];
// p~ stored in PERMUTED block-32 layout:
// within each 32-col block, actual col c stored at
// s = 8*((c&7)>>1) + 4*((c>>4)&1) + 2*((c>>3)&1) + (c&1)
__device__ __half g_Ph[(size_t)BB * HH * SS * SS];
__device__ float  g_invZ[(size_t)BB * HH * SS];
__device__ float  g_gate[BB * HH];

// ---------------- helpers ----------------
__device__ __forceinline__ float ex2(float x) {
    float r; asm("ex2.approx.f32 %0, %1;" : "=f"(r) : "f"(x)); return r;
}

__device__ __forceinline__ void mma_f16(float* d, const uint32_t* a, const uint32_t* b) {
    asm volatile("mma.sync.aligned.m16n8k16.row.col.f32.f16.f16.f32 "
                 "{%0,%1,%2,%3}, {%4,%5,%6,%7}, {%8,%9}, {%0,%1,%2,%3};"
                 : "+f"(d[0]), "+f"(d[1]), "+f"(d[2]), "+f"(d[3])
                 : "r"(a[0]), "r"(a[1]), "r"(a[2]), "r"(a[3]),
                   "r"(b[0]), "r"(b[1]));
}

__device__ __forceinline__ void ldsm_x4(uint32_t* r, uint32_t addr) {
    asm volatile("ldmatrix.sync.aligned.m8n8.x4.shared.b16 {%0,%1,%2,%3}, [%4];"
                 : "=r"(r[0]), "=r"(r[1]), "=r"(r[2]), "=r"(r[3]) : "r"(addr));
}
__device__ __forceinline__ void ldsm_x4_t(uint32_t* r, uint32_t addr) {
    asm volatile("ldmatrix.sync.aligned.m8n8.x4.trans.shared.b16 {%0,%1,%2,%3}, [%4];"
                 : "=r"(r[0]), "=r"(r[1]), "=r"(r[2]), "=r"(r[3]) : "r"(addr));
}

__device__ __forceinline__ void cp_async16(uint32_t smem, const void* g) {
    asm volatile("cp.async.cg.shared.global [%0], [%1], 16;" :: "r"(smem), "l"(g));
}
__device__ __forceinline__ void cp_commit() { asm volatile("cp.async.commit_group;"); }
__device__ __forceinline__ void cp_wait0()  { asm volatile("cp.async.wait_group 0;"); }
__device__ __forceinline__ void cp_wait1()  { asm volatile("cp.async.wait_group 1;"); }

__device__ __forceinline__ uint32_t h2u(__half2 h) { return *(uint32_t*)&h; }

// ================= prep: f2h conversions + gate + bias combine ==============
__global__ __launch_bounds__(256)
void prep(const float* __restrict__ x,
          const float* __restrict__ Wq, const float* __restrict__ Wk,
          const float* __restrict__ Wv, const float* __restrict__ Wo,
          const float* __restrict__ bq, const float* __restrict__ bk,
          const float* __restrict__ bv,
          const float* __restrict__ sf,
          const float* __restrict__ Ws1, const float* __restrict__ bs1,
          const float* __restrict__ Ws2, const float* __restrict__ bs2)
{
    const int bid = blockIdx.x, tid = threadIdx.x;
    if (bid == 0) {
        __shared__ float h1[BB][HID];
        for (int b = 0; b < BB; ++b) {
            float acc = bs1[tid];
            for (int e = 0; e < EE; ++e)
                acc += sf[b * EE + e] * Ws1[(size_t)e * HID + tid];
            h1[b][tid] = fmaxf(acc, 0.0f);
        }
        __syncthreads();
        if (tid < BB * HH) {
            int b = tid / HH, h = tid % HH;
            float acc = bs2[h];
            for (int k = 0; k < HID; ++k)
                acc += h1[b][k] * Ws2[k * HH + h];
            g_gate[b * HH + h] = (1.0f / (1.0f + __expf(-acc))) * 0.125f;
        }
        for (int i = tid; i < EE; i += 256) {
            g_b3[i] = bq[i]; g_b3[EE + i] = bk[i]; g_b3[2 * EE + i] = bv[i];
        }
        return;
    }
    int t = (bid - 1) * 256 + tid;
    if (t < 1048576) {                    // X: 4M floats
        float4 v = ((const float4*)x)[t];
        ((__half2*)g_Xh)[2 * t]     = __floats2half2_rn(v.x, v.y);
        ((__half2*)g_Xh)[2 * t + 1] = __floats2half2_rn(v.z, v.w);
        return;
    }
    t -= 1048576;
    if (t < 3 * 262144) {                 // Wq/Wk/Wv interleave into [k][3N]
        int which = t / 262144;
        int u = t - which * 262144;
        const float* W = (which == 0) ? Wq : ((which == 1) ? Wk : Wv);
        float4 v = ((const float4*)W)[u];
        int k = u >> 8, n4 = u & 255;
        size_t d = (size_t)k * N3 + which * EE + n4 * 4;
        *(__half2*)&g_W3[d]     = __floats2half2_rn(v.x, v.y);
        *(__half2*)&g_W3[d + 2] = __floats2half2_rn(v.z, v.w);
        return;
    }
    t -= 3 * 262144;
    if (t < 262144) {                     // Wo
        float4 v = ((const float4*)Wo)[t];
        ((__half2*)g_Who)[2 * t]     = __floats2half2_rn(v.x, v.y);
        ((__half2*)g_Who)[2 * t + 1] = __floats2half2_rn(v.z, v.w);
    }
}

// ======= fp16 MMA GEMM body 128x128x32: C = A[M,1024] @ B[1024,N] + bias ====
template<bool OUT_HALF>
__device__ __forceinline__ void gemm_body(
    const __half* __restrict__ Ah, const __half* __restrict__ Bh,
    const float* __restrict__ bias, void* __restrict__ Cp,
    int ldbc, int bx, int by)
{
    constexpr int SA = 40;
    constexpr int SB = 136;
    __shared__ __half As[2][128 * SA];
    __shared__ __half Bs[2][32 * SB];

    const int tid = threadIdx.x;
    const int lane = tid & 31, warp = tid >> 5;
    const int wr = warp & 1, wc = warp >> 1;
    const int lr = lane >> 2, lc = lane & 3;
    const int bm = by * 128, bn = bx * 128;

    const uint32_t AsB[2] = { (uint32_t)__cvta_generic_to_shared(&As[0][0]),
                              (uint32_t)__cvta_generic_to_shared(&As[1][0]) };
    const uint32_t BsB[2] = { (uint32_t)__cvta_generic_to_shared(&Bs[0][0]),
                              (uint32_t)__cvta_generic_to_shared(&Bs[1][0]) };

    const int brow0 = tid >> 4, bch0 = tid & 15;
    const int arow0 = tid >> 2, ach0 = tid & 3;

    auto issue = [&](int kt, int buf) {
        cp_async16(AsB[buf] + (uint32_t)((arow0 * SA + ach0 * 8) * 2),
                   Ah + (size_t)(bm + arow0) * EE + kt * 32 + ach0 * 8);
        cp_async16(AsB[buf] + (uint32_t)(((arow0 + 64) * SA + ach0 * 8) * 2),
                   Ah + (size_t)(bm + arow0 + 64) * EE + kt * 32 + ach0 * 8);
        cp_async16(BsB[buf] + (uint32_t)((brow0 * SB + bch0 * 8) * 2),
                   Bh + (size_t)(kt * 32 + brow0) * ldbc + bn + bch0 * 8);
        cp_async16(BsB[buf] + (uint32_t)(((brow0 + 16) * SB + bch0 * 8) * 2),
                   Bh + (size_t)(kt * 32 + brow0 + 16) * ldbc + bn + bch0 * 8);
        cp_commit();
    };

    float acc[4][4][4];
#pragma unroll
    for (int i = 0; i < 4; ++i)
#pragma unroll
        for (int j = 0; j < 4; ++j)
#pragma unroll
            for (int r = 0; r < 4; ++r) acc[i][j][r] = 0.0f;

    const int a_row_l = wr * 64 + (lane & 15);
    const int a_koff = (lane >> 4) * 8;
    const int b_krow = (lane & 7) + ((lane >> 3) & 1) * 8;
    const int b_noff = (lane >> 4) * 8;

    const int nk = EE / 32;
    issue(0, 0);

    for (int kt = 0; kt < nk; ++kt) {
        const int buf = kt & 1;
        if (kt + 1 < nk) { issue(kt + 1, buf ^ 1); cp_wait1(); }
        else cp_wait0();
        __syncthreads();

#pragma unroll
        for (int ks = 0; ks < 2; ++ks) {
            const int k0 = ks * 16;
            uint32_t af[4][4], bf[4][2];
#pragma unroll
            for (int mf = 0; mf < 4; ++mf)
                ldsm_x4(af[mf], AsB[buf] +
                        (uint32_t)(((a_row_l + mf * 16) * SA + k0 + a_koff) * 2));
#pragma unroll
            for (int np = 0; np < 2; ++np) {
                uint32_t r4[4];
                int n0 = wc * 32 + np * 16;
                ldsm_x4_t(r4, BsB[buf] +
                          (uint32_t)(((k0 + b_krow) * SB + n0 + b_noff) * 2));
                bf[np * 2][0] = r4[0]; bf[np * 2][1] = r4[1];
                bf[np * 2 + 1][0] = r4[2]; bf[np * 2 + 1][1] = r4[3];
            }
#pragma unroll
            for (int mf = 0; mf < 4; ++mf)
#pragma unroll
                for (int nf = 0; nf < 4; ++nf)
                    mma_f16(acc[mf][nf], af[mf], bf[nf]);
        }
        __syncthreads();
    }

#pragma unroll
    for (int nf = 0; nf < 4; ++nf) {
        int col = bn + wc * 32 + nf * 8 + lc * 2;
        float b0 = bias[col], b1 = bias[col + 1];
#pragma unroll
        for (int mf = 0; mf < 4; ++mf) {
            int row = bm + wr * 64 + mf * 16 + lr;
            if (OUT_HALF) {
                __half* Ch = (__half*)Cp;
                *(__half2*)&Ch[(size_t)row * ldbc + col] =
                    __floats2half2_rn(acc[mf][nf][0] + b0, acc[mf][nf][1] + b1);
                *(__half2*)&Ch[(size_t)(row + 8) * ldbc + col] =
                    __floats2half2_rn(acc[mf][nf][2] + b0, acc[mf][nf][3] + b1);
            } else {
                float* Cf = (float*)Cp;
                *(float2*)&Cf[(size_t)row * ldbc + col] =
                    make_float2(acc[mf][nf][0] + b0, acc[mf][nf][1] + b1);
                *(float2*)&Cf[(size_t)(row + 8) * ldbc + col] =
                    make_float2(acc[mf][nf][2] + b0, acc[mf][nf][3] + b1);
            }
        }
    }
}

// ---------------- QKV: one GEMM, N = 3072 ----------------
__global__ __launch_bounds__(256)
void gemm_qkv(const __half* __restrict__ Xh, const __half* __restrict__ W3,
              const float* __restrict__ b3, __half* __restrict__ QKV)
{
    gemm_body<true>(Xh, W3, b3, QKV, N3, blockIdx.x, blockIdx.y);
}

// ===== fused attention: quarter-pipelined scores+exp+store+Z+PV =============
#define FA_ST 72
#define FA_SMEM (5 * 128 * FA_ST * 2)

__global__ __launch_bounds__(256, 2)
void attn_fused(const __half* __restrict__ QKV, __half* __restrict__ Ph,
                __half* __restrict__ Ch)
{
    extern __shared__ __half sm[];
    const uint32_t QsB  = (uint32_t)__cvta_generic_to_shared(sm);
    const uint32_t KsB[2] = { QsB + 128 * FA_ST * 2, QsB + 2 * 128 * FA_ST * 2 };
    const uint32_t VsB[2] = { QsB + 3 * 128 * FA_ST * 2, QsB + 4 * 128 * FA_ST * 2 };

    const int tid = threadIdx.x;
    const int lane = tid & 31, warp = tid >> 5;
    const int lr = lane >> 2, lc = lane & 3;
    const int bh = blockIdx.y, b = bh >> 4, h = bh & 15;
    const int mi = blockIdx.x * 128;

    // Q load (group 0)
#pragma unroll
    for (int i = 0; i < 4; ++i) {
        int c = tid + i * 256;
        int row = c >> 3, ch = c & 7;
        cp_async16(QsB + (uint32_t)((row * FA_ST + ch * 8) * 2),
                   QKV + (size_t)(b * SS + mi + row) * N3 + h * 64 + ch * 8);
    }
    cp_commit();

    auto issueKV = [&](int jt, int buf) {
#pragma unroll
        for (int i = 0; i < 4; ++i) {
            int c = tid + i * 256;
            int row = c >> 3, ch = c & 7;
            size_t base = (size_t)(b * SS + jt * 128 + row) * N3 + h * 64 + ch * 8;
            cp_async16(KsB[buf] + (uint32_t)((row * FA_ST + ch * 8) * 2),
                       QKV + base + 1024);
            cp_async16(VsB[buf] + (uint32_t)((row * FA_ST + ch * 8) * 2),
                       QKV + base + 2048);
        }
        cp_commit();
    };
    issueKV(0, 0);

    // exp(s*g - 8) = ex2(s * g2 + C8)
    const float g2 = g_gate[bh] * 1.4426950408889634f;
    const float C8 = -11.541560327111708f;

    const int a_row  = warp * 16 + (lane & 15);
    const int a_koff = (lane >> 4) * 8;
    const int b1_nrow = (lane & 7) + (lane >> 4) * 8;
    const int b1_koff = ((lane >> 3) & 1) * 8;
    const int b2_krow = (lane & 7) + ((lane >> 3) & 1) * 8;
    const int b2_noff = (lane >> 4) * 8;

    // hoist Q fragments
    cp_wait1();
    __syncthreads();
    uint32_t qf[4][4];
#pragma unroll
    for (int ks = 0; ks < 4; ++ks)
        ldsm_x4(qf[ks], QsB + (uint32_t)((a_row * FA_ST + ks * 16 + a_koff) * 2));

    float ctx[8][4];
#pragma unroll
    for (int i = 0; i < 8; ++i)
#pragma unroll
        for (int r = 0; r < 4; ++r) ctx[i][r] = 0.0f;
    float zs0 = 0.0f, zs1 = 0.0f;

    const int grow = mi + warp * 16 + lr;
    __half* Prow0 = Ph + ((size_t)bh * SS + grow) * SS;
    __half* Prow1 = Ph + ((size_t)bh * SS + grow + 8) * SS;

    // MMA1 over one 32-col quarter
    auto mma1_q = [&](int buf, int q, float (&acc)[4][4]) {
#pragma unroll
        for (int i = 0; i < 4; ++i)
#pragma unroll
            for (int r = 0; r < 4; ++r) acc[i][r] = 0.0f;
#pragma unroll
        for (int ks = 0; ks < 4; ++ks)
#pragma unroll
            for (int np = 0; np < 2; ++np) {
                uint32_t r4[4];
                ldsm_x4(r4, KsB[buf] +
                        (uint32_t)(((q * 32 + np * 16 + b1_nrow) * FA_ST +
                                    ks * 16 + b1_koff) * 2));
                mma_f16(acc[np * 2], qf[ks], r4);
                mma_f16(acc[np * 2 + 1], qf[ks], r4 + 2);
            }
    };

    // exp + permuted store + Z + MMA2 for one quarter
    auto epi_q = [&](int buf, int jt, int q, float (&acc)[4][4]) {
        uint32_t r0v[4], r1v[4];
#pragma unroll
        for (int np = 0; np < 2; ++np) {
            float pa0 = ex2(fmaf(acc[np * 2][0], g2, C8));
            float pa1 = ex2(fmaf(acc[np * 2][1], g2, C8));
            float pb0 = ex2(fmaf(acc[np * 2][2], g2, C8));
            float pb1 = ex2(fmaf(acc[np * 2][3], g2, C8));
            float pc0 = ex2(fmaf(acc[np * 2 + 1][0], g2, C8));
            float pc1 = ex2(fmaf(acc[np * 2 + 1][1], g2, C8));
            float pd0 = ex2(fmaf(acc[np * 2 + 1][2], g2, C8));
            float pd1 = ex2(fmaf(acc[np * 2 + 1][3], g2, C8));
            __half2 wa = __floats2half2_rn(pa0, pa1);
            __half2 wb = __floats2half2_rn(pb0, pb1);
            __half2 wc2 = __floats2half2_rn(pc0, pc1);
            __half2 wd = __floats2half2_rn(pd0, pd1);
            zs0 += (pa0 + pa1) + (pc0 + pc1);
            zs1 += (pb0 + pb1) + (pd0 + pd1);
            r0v[np * 2] = h2u(wa); r0v[np * 2 + 1] = h2u(wc2);
            r1v[np * 2] = h2u(wb); r1v[np * 2 + 1] = h2u(wd);

            uint32_t af2[4] = { h2u(wa), h2u(wb), h2u(wc2), h2u(wd) };
#pragma unroll
            for (int n2 = 0; n2 < 4; ++n2) {
                uint32_t r4[4];
                ldsm_x4_t(r4, VsB[buf] +
                          (uint32_t)(((q * 32 + np * 16 + b2_krow) * FA_ST +
                                      n2 * 16 + b2_noff) * 2));
                mma_f16(ctx[n2 * 2], af2, r4);
                mma_f16(ctx[n2 * 2 + 1], af2, r4 + 2);
            }
        }
        int poff = jt * 128 + q * 32 + 8 * lc;
        *(uint4*)&Prow0[poff] = make_uint4(r0v[0], r0v[1], r0v[2], r0v[3]);
        *(uint4*)&Prow1[poff] = make_uint4(r1v[0], r1v[1], r1v[2], r1v[3]);
    };

    for (int jt = 0; jt < 16; ++jt) {
        const int buf = jt & 1;
        if (jt + 1 < 16) { issueKV(jt + 1, buf ^ 1); cp_wait1(); }
        else cp_wait0();
        __syncthreads();

        // software pipeline: MMA1(q+1) in flight during epilogue(q)
        float accA[4][4], accB[4][4];
        mma1_q(buf, 0, accA);
        mma1_q(buf, 1, accB);
        epi_q(buf, jt, 0, accA);
        mma1_q(buf, 2, accA);
        epi_q(buf, jt, 1, accB);
        mma1_q(buf, 3, accB);
        epi_q(buf, jt, 2, accA);
        epi_q(buf, jt, 3, accB);

        __syncthreads();
    }

    zs0 += __shfl_xor_sync(0xffffffffu, zs0, 1);
    zs0 += __shfl_xor_sync(0xffffffffu, zs0, 2);
    zs1 += __shfl_xor_sync(0xffffffffu, zs1, 1);
    zs1 += __shfl_xor_sync(0xffffffffu, zs1, 2);
    float iz0 = 1.0f / zs0, iz1 = 1.0f / zs1;
    if (lc == 0) {
        g_invZ[(size_t)bh * SS + grow]     = iz0;
        g_invZ[(size_t)bh * SS + grow + 8] = iz1;
    }

    __half* Cc = Ch + (size_t)b * SS * EE + h * 64;
#pragma unroll
    for (int np = 0; np < 8; ++np) {
        int n = np * 8 + 2 * lc;
        *(__half2*)&Cc[(size_t)grow * EE + n] =
            __floats2half2_rn(ctx[np][0] * iz0, ctx[np][1] * iz0);
        *(__half2*)&Cc[(size_t)(grow + 8) * EE + n] =
            __floats2half2_rn(ctx[np][2] * iz1, ctx[np][3] * iz1);
    }
}

// ===== tail: out-proj GEMM (blocks 0..255) || head-mean (blocks 256..1279) ==
// Mean reads the PERMUTED block-32 P layout and unpermutes before writing.
__global__ __launch_bounds__(256)
void tail_kernel(const __half* __restrict__ Ch, const __half* __restrict__ Who,
                 const float* __restrict__ bo, float* __restrict__ out,
                 const __half* __restrict__ Ph, float* __restrict__ om)
{
    const int bid = blockIdx.x;
    if (bid < 256) {
        gemm_body<false>(Ch, Who, bo, out, EE, bid & 7, bid >> 3);
        return;
    }
    // mean: 1024 blocks; each block = 4 rows; thread -> (row, 32-col block)
    const int id = bid - 256;                 // 0..1023
    const int tid = threadIdx.x;
    const int grow = id * 4 + (tid >> 6);     // global row 0..4095
    const int b = grow >> 11, i = grow & (SS - 1);
    const int blk = tid & 63;                 // 32-col block index

    float acc[32];
#pragma unroll
    for (int s = 0; s < 32; ++s) acc[s] = 0.0f;

    for (int hh = 0; hh < HH; ++hh) {
        const __half* base = Ph + ((size_t)(b * HH + hh) * SS + i) * SS + blk * 32;
        float w = g_invZ[(size_t)(b * HH + hh) * SS + i] * 0.0625f;
#pragma unroll
        for (int qq = 0; qq < 4; ++qq) {
            uint4 v = *(const uint4*)(base + qq * 8);
            const uint32_t* vv = (const uint32_t*)&v;
#pragma unroll
            for (int w2 = 0; w2 < 4; ++w2) {
                float2 f = __half22float2(*(const __half2*)&vv[w2]);
                acc[qq * 8 + 2 * w2]     = fmaf(w, f.x, acc[qq * 8 + 2 * w2]);
                acc[qq * 8 + 2 * w2 + 1] = fmaf(w, f.y, acc[qq * 8 + 2 * w2 + 1]);
            }
        }
    }

    // unpermute: col c stored at s = 8*((c&7)>>1) + 4*((c>>4)&1) + 2*((c>>3)&1) + (c&1)
    float o[32];
#pragma unroll
    for (int c = 0; c < 32; ++c)
        o[c] = acc[8 * ((c & 7) >> 1) + 4 * ((c >> 4) & 1) + 2 * ((c >> 3) & 1) + (c & 1)];

    float* op = om + (size_t)(b * SS + i) * SS + blk * 32;
#pragma unroll
    for (int qq = 0; qq < 8; ++qq)
        *(float4*)&op[qq * 4] = make_float4(o[qq * 4], o[qq * 4 + 1],
                                            o[qq * 4 + 2], o[qq * 4 + 3]);
}

// ---------------- launch ----------------
extern "C" void kernel_launch(void* const* d_in, const int* in_sizes, int n_in,
                              void* d_out, int out_size)
{
    const float* x   = (const float*)d_in[0];
    const float* sf  = (const float*)d_in[1];
    const float* Wq  = (const float*)d_in[2];
    const float* bq  = (const float*)d_in[3];
    const float* Wk  = (const float*)d_in[4];
    const float* bk  = (const float*)d_in[5];
    const float* Wv  = (const float*)d_in[6];
    const float* bv  = (const float*)d_in[7];
    const float* Ws1 = (const float*)d_in[8];
    const float* bs1 = (const float*)d_in[9];
    const float* Ws2 = (const float*)d_in[10];
    const float* bs2 = (const float*)d_in[11];
    const float* Wo  = (const float*)d_in[12];
    const float* bo  = (const float*)d_in[13];
    float* out = (float*)d_out;

    __half *pXh, *pW3, *pWho, *pQKV, *pCh, *pPh;
    float *pb3;
    cudaGetSymbolAddress((void**)&pXh, g_Xh);
    cudaGetSymbolAddress((void**)&pW3, g_W3);
    cudaGetSymbolAddress((void**)&pWho, g_Who);
    cudaGetSymbolAddress((void**)&pb3, g_b3);
    cudaGetSymbolAddress((void**)&pQKV, g_QKV);
    cudaGetSymbolAddress((void**)&pCh, g_CTXh);
    cudaGetSymbolAddress((void**)&pPh, g_Ph);

    // 0. prep: conversions + interleave + gate + bias combine
    prep<<<1 + 4096 + 3072 + 1024, 256>>>(x, Wq, Wk, Wv, Wo, bq, bk, bv,
                                          sf, Ws1, bs1, Ws2, bs2);

    // 1. fused QKV projection: [4096,1024] @ [1024,3072]
    gemm_qkv<<<dim3(N3 / 128, (BB * SS) / 128), 256>>>(pXh, pW3, pb3, pQKV);

    // 2. fused attention: quarter-pipelined, permuted p~ store
    cudaFuncSetAttribute(attn_fused, cudaFuncAttributeMaxDynamicSharedMemorySize, FA_SMEM);
    attn_fused<<<dim3(SS / 128, BB * HH), 256, FA_SMEM>>>(pQKV, pPh, pCh);

    // 3. tail: out-proj GEMM || head-mean (grid-partitioned co-execution)
    tail_kernel<<<256 + (BB * SS) / 4, 256>>>(pCh, pWho, bo, out, pPh,
                                              out + (size_t)BB * SS * EE);

    (void)in_sizes; (void)n_in; (void)out_size;
}

// round 14
// speedup vs baseline: 2.1911x; 1.0196x over previous
#include <cuda_runtime.h>
#include <cuda_fp16.h>
#include <cstdint>
#include <cstddef>

#define BB 2
#define SS 2048
#define EE 1024
#define HH 16
#define HID 256
#define N3 3072

// ---------------- scratch (device globals: allocation-free) ----------------
__device__ __half g_Xh[(size_t)BB * SS * EE];
__device__ __half g_W3[(size_t)EE * N3];        // interleaved [k][Wq|Wk|Wv]
__device__ __half g_Who[(size_t)EE * EE];
__device__ float  g_b3[N3];
__device__ __half g_QKV[(size_t)BB * SS * N3];  // [b,s][q|k|v]
__device__ __half g_CTXh[(size_t)BB * SS * EE];
// p~ stored in PERMUTED block-32 layout:
// within each 32-col block, actual col c stored at
// s = 8*((c&7)>>1) + 4*((c>>4)&1) + 2*((c>>3)&1) + (c&1)
__device__ __half g_Ph[(size_t)BB * HH * SS * SS];
__device__ float  g_invZ[(size_t)BB * HH * SS];
__device__ float  g_gate[BB * HH];

// ---------------- helpers ----------------
__device__ __forceinline__ float ex2(float x) {
    float r; asm("ex2.approx.f32 %0, %1;" : "=f"(r) : "f"(x)); return r;
}

__device__ __forceinline__ void mma_f16(float* d, const uint32_t* a, const uint32_t* b) {
    asm volatile("mma.sync.aligned.m16n8k16.row.col.f32.f16.f16.f32 "
                 "{%0,%1,%2,%3}, {%4,%5,%6,%7}, {%8,%9}, {%0,%1,%2,%3};"
                 : "+f"(d[0]), "+f"(d[1]), "+f"(d[2]), "+f"(d[3])
                 : "r"(a[0]), "r"(a[1]), "r"(a[2]), "r"(a[3]),
                   "r"(b[0]), "r"(b[1]));
}

__device__ __forceinline__ void ldsm_x4(uint32_t* r, uint32_t addr) {
    asm volatile("ldmatrix.sync.aligned.m8n8.x4.shared.b16 {%0,%1,%2,%3}, [%4];"
                 : "=r"(r[0]), "=r"(r[1]), "=r"(r[2]), "=r"(r[3]) : "r"(addr));
}
__device__ __forceinline__ void ldsm_x4_t(uint32_t* r, uint32_t addr) {
    asm volatile("ldmatrix.sync.aligned.m8n8.x4.trans.shared.b16 {%0,%1,%2,%3}, [%4];"
                 : "=r"(r[0]), "=r"(r[1]), "=r"(r[2]), "=r"(r[3]) : "r"(addr));
}

__device__ __forceinline__ void cp_async16(uint32_t smem, const void* g) {
    asm volatile("cp.async.cg.shared.global [%0], [%1], 16;" :: "r"(smem), "l"(g));
}
__device__ __forceinline__ void cp_commit() { asm volatile("cp.async.commit_group;"); }
__device__ __forceinline__ void cp_wait0()  { asm volatile("cp.async.wait_group 0;"); }
__device__ __forceinline__ void cp_wait1()  { asm volatile("cp.async.wait_group 1;"); }

__device__ __forceinline__ uint32_t h2u(__half2 h) { return *(uint32_t*)&h; }

// ================= prep: f2h conversions + gate + bias combine ==============
__global__ __launch_bounds__(256)
void prep(const float* __restrict__ x,
          const float* __restrict__ Wq, const float* __restrict__ Wk,
          const float* __restrict__ Wv, const float* __restrict__ Wo,
          const float* __restrict__ bq, const float* __restrict__ bk,
          const float* __restrict__ bv,
          const float* __restrict__ sf,
          const float* __restrict__ Ws1, const float* __restrict__ bs1,
          const float* __restrict__ Ws2, const float* __restrict__ bs2)
{
    const int bid = blockIdx.x, tid = threadIdx.x;
    if (bid == 0) {
        __shared__ float h1[BB][HID];
        for (int b = 0; b < BB; ++b) {
            float acc = bs1[tid];
            for (int e = 0; e < EE; ++e)
                acc += sf[b * EE + e] * Ws1[(size_t)e * HID + tid];
            h1[b][tid] = fmaxf(acc, 0.0f);
        }
        __syncthreads();
        if (tid < BB * HH) {
            int b = tid / HH, h = tid % HH;
            float acc = bs2[h];
            for (int k = 0; k < HID; ++k)
                acc += h1[b][k] * Ws2[k * HH + h];
            g_gate[b * HH + h] = (1.0f / (1.0f + __expf(-acc))) * 0.125f;
        }
        for (int i = tid; i < EE; i += 256) {
            g_b3[i] = bq[i]; g_b3[EE + i] = bk[i]; g_b3[2 * EE + i] = bv[i];
        }
        return;
    }
    int t = (bid - 1) * 256 + tid;
    if (t < 1048576) {                    // X: 4M floats
        float4 v = ((const float4*)x)[t];
        ((__half2*)g_Xh)[2 * t]     = __floats2half2_rn(v.x, v.y);
        ((__half2*)g_Xh)[2 * t + 1] = __floats2half2_rn(v.z, v.w);
        return;
    }
    t -= 1048576;
    if (t < 3 * 262144) {                 // Wq/Wk/Wv interleave into [k][3N]
        int which = t / 262144;
        int u = t - which * 262144;
        const float* W = (which == 0) ? Wq : ((which == 1) ? Wk : Wv);
        float4 v = ((const float4*)W)[u];
        int k = u >> 8, n4 = u & 255;
        size_t d = (size_t)k * N3 + which * EE + n4 * 4;
        *(__half2*)&g_W3[d]     = __floats2half2_rn(v.x, v.y);
        *(__half2*)&g_W3[d + 2] = __floats2half2_rn(v.z, v.w);
        return;
    }
    t -= 3 * 262144;
    if (t < 262144) {                     // Wo
        float4 v = ((const float4*)Wo)[t];
        ((__half2*)g_Who)[2 * t]     = __floats2half2_rn(v.x, v.y);
        ((__half2*)g_Who)[2 * t + 1] = __floats2half2_rn(v.z, v.w);
    }
}

// ======= fp16 MMA GEMM body 128x128x32 (static smem, used by tail) =========
template<bool OUT_HALF>
__device__ __forceinline__ void gemm_body(
    const __half* __restrict__ Ah, const __half* __restrict__ Bh,
    const float* __restrict__ bias, void* __restrict__ Cp,
    int ldbc, int bx, int by)
{
    constexpr int SA = 40;
    constexpr int SB = 136;
    __shared__ __half As[2][128 * SA];
    __shared__ __half Bs[2][32 * SB];

    const int tid = threadIdx.x;
    const int lane = tid & 31, warp = tid >> 5;
    const int wr = warp & 1, wc = warp >> 1;
    const int lr = lane >> 2, lc = lane & 3;
    const int bm = by * 128, bn = bx * 128;

    const uint32_t AsB[2] = { (uint32_t)__cvta_generic_to_shared(&As[0][0]),
                              (uint32_t)__cvta_generic_to_shared(&As[1][0]) };
    const uint32_t BsB[2] = { (uint32_t)__cvta_generic_to_shared(&Bs[0][0]),
                              (uint32_t)__cvta_generic_to_shared(&Bs[1][0]) };

    const int brow0 = tid >> 4, bch0 = tid & 15;
    const int arow0 = tid >> 2, ach0 = tid & 3;

    auto issue = [&](int kt, int buf) {
        cp_async16(AsB[buf] + (uint32_t)((arow0 * SA + ach0 * 8) * 2),
                   Ah + (size_t)(bm + arow0) * EE + kt * 32 + ach0 * 8);
        cp_async16(AsB[buf] + (uint32_t)(((arow0 + 64) * SA + ach0 * 8) * 2),
                   Ah + (size_t)(bm + arow0 + 64) * EE + kt * 32 + ach0 * 8);
        cp_async16(BsB[buf] + (uint32_t)((brow0 * SB + bch0 * 8) * 2),
                   Bh + (size_t)(kt * 32 + brow0) * ldbc + bn + bch0 * 8);
        cp_async16(BsB[buf] + (uint32_t)(((brow0 + 16) * SB + bch0 * 8) * 2),
                   Bh + (size_t)(kt * 32 + brow0 + 16) * ldbc + bn + bch0 * 8);
        cp_commit();
    };

    float acc[4][4][4];
#pragma unroll
    for (int i = 0; i < 4; ++i)
#pragma unroll
        for (int j = 0; j < 4; ++j)
#pragma unroll
            for (int r = 0; r < 4; ++r) acc[i][j][r] = 0.0f;

    const int a_row_l = wr * 64 + (lane & 15);
    const int a_koff = (lane >> 4) * 8;
    const int b_krow = (lane & 7) + ((lane >> 3) & 1) * 8;
    const int b_noff = (lane >> 4) * 8;

    const int nk = EE / 32;
    issue(0, 0);

    for (int kt = 0; kt < nk; ++kt) {
        const int buf = kt & 1;
        if (kt + 1 < nk) { issue(kt + 1, buf ^ 1); cp_wait1(); }
        else cp_wait0();
        __syncthreads();

#pragma unroll
        for (int ks = 0; ks < 2; ++ks) {
            const int k0 = ks * 16;
            uint32_t af[4][4], bf[4][2];
#pragma unroll
            for (int mf = 0; mf < 4; ++mf)
                ldsm_x4(af[mf], AsB[buf] +
                        (uint32_t)(((a_row_l + mf * 16) * SA + k0 + a_koff) * 2));
#pragma unroll
            for (int np = 0; np < 2; ++np) {
                uint32_t r4[4];
                int n0 = wc * 32 + np * 16;
                ldsm_x4_t(r4, BsB[buf] +
                          (uint32_t)(((k0 + b_krow) * SB + n0 + b_noff) * 2));
                bf[np * 2][0] = r4[0]; bf[np * 2][1] = r4[1];
                bf[np * 2 + 1][0] = r4[2]; bf[np * 2 + 1][1] = r4[3];
            }
#pragma unroll
            for (int mf = 0; mf < 4; ++mf)
#pragma unroll
                for (int nf = 0; nf < 4; ++nf)
                    mma_f16(acc[mf][nf], af[mf], bf[nf]);
        }
        __syncthreads();
    }

#pragma unroll
    for (int nf = 0; nf < 4; ++nf) {
        int col = bn + wc * 32 + nf * 8 + lc * 2;
        float b0 = bias[col], b1 = bias[col + 1];
#pragma unroll
        for (int mf = 0; mf < 4; ++mf) {
            int row = bm + wr * 64 + mf * 16 + lr;
            if (OUT_HALF) {
                __half* Ch = (__half*)Cp;
                *(__half2*)&Ch[(size_t)row * ldbc + col] =
                    __floats2half2_rn(acc[mf][nf][0] + b0, acc[mf][nf][1] + b1);
                *(__half2*)&Ch[(size_t)(row + 8) * ldbc + col] =
                    __floats2half2_rn(acc[mf][nf][2] + b0, acc[mf][nf][3] + b1);
            } else {
                float* Cf = (float*)Cp;
                *(float2*)&Cf[(size_t)row * ldbc + col] =
                    make_float2(acc[mf][nf][0] + b0, acc[mf][nf][1] + b1);
                *(float2*)&Cf[(size_t)(row + 8) * ldbc + col] =
                    make_float2(acc[mf][nf][2] + b0, acc[mf][nf][3] + b1);
            }
        }
    }
}

// ---------------- QKV GEMM: 128x128x64 tiles, dynamic smem ----------------
#define QK_SA 72
#define QK_SB 136
#define QK_ABYTES (128 * QK_SA * 2)
#define QK_BBYTES (64 * QK_SB * 2)
#define QK_SMEM (2 * QK_ABYTES + 2 * QK_BBYTES)

__global__ __launch_bounds__(256, 2)
void gemm_qkv64(const __half* __restrict__ Xh, const __half* __restrict__ W3,
                const float* __restrict__ b3, __half* __restrict__ QKV)
{
    extern __shared__ __half dsm[];
    const uint32_t base = (uint32_t)__cvta_generic_to_shared(dsm);
    const uint32_t AsB[2] = { base, base + QK_ABYTES };
    const uint32_t BsB[2] = { base + 2 * QK_ABYTES, base + 2 * QK_ABYTES + QK_BBYTES };

    const int tid = threadIdx.x;
    const int lane = tid & 31, warp = tid >> 5;
    const int wr = warp & 1, wc = warp >> 1;
    const int lr = lane >> 2, lc = lane & 3;
    const int bm = blockIdx.y * 128, bn = blockIdx.x * 128;

    auto issue = [&](int kt, int buf) {
        const int k0 = kt * 64;
#pragma unroll
        for (int i = 0; i < 4; ++i) {
            int id = tid + i * 256;
            int ar = id >> 3, ac = id & 7;
            cp_async16(AsB[buf] + (uint32_t)((ar * QK_SA + ac * 8) * 2),
                       Xh + (size_t)(bm + ar) * EE + k0 + ac * 8);
            int br = id >> 4, bc = id & 15;
            cp_async16(BsB[buf] + (uint32_t)((br * QK_SB + bc * 8) * 2),
                       W3 + (size_t)(k0 + br) * N3 + bn + bc * 8);
        }
        cp_commit();
    };

    float acc[4][4][4];
#pragma unroll
    for (int i = 0; i < 4; ++i)
#pragma unroll
        for (int j = 0; j < 4; ++j)
#pragma unroll
            for (int r = 0; r < 4; ++r) acc[i][j][r] = 0.0f;

    const int a_row_l = wr * 64 + (lane & 15);
    const int a_koff = (lane >> 4) * 8;
    const int b_krow = (lane & 7) + ((lane >> 3) & 1) * 8;
    const int b_noff = (lane >> 4) * 8;

    const int nk = EE / 64;   // 16
    issue(0, 0);

    for (int kt = 0; kt < nk; ++kt) {
        const int buf = kt & 1;
        if (kt + 1 < nk) { issue(kt + 1, buf ^ 1); cp_wait1(); }
        else cp_wait0();
        __syncthreads();

#pragma unroll
        for (int ks = 0; ks < 4; ++ks) {
            const int k0 = ks * 16;
            uint32_t af[4][4], bf[4][2];
#pragma unroll
            for (int mf = 0; mf < 4; ++mf)
                ldsm_x4(af[mf], AsB[buf] +
                        (uint32_t)(((a_row_l + mf * 16) * QK_SA + k0 + a_koff) * 2));
#pragma unroll
            for (int np = 0; np < 2; ++np) {
                uint32_t r4[4];
                int n0 = wc * 32 + np * 16;
                ldsm_x4_t(r4, BsB[buf] +
                          (uint32_t)(((k0 + b_krow) * QK_SB + n0 + b_noff) * 2));
                bf[np * 2][0] = r4[0]; bf[np * 2][1] = r4[1];
                bf[np * 2 + 1][0] = r4[2]; bf[np * 2 + 1][1] = r4[3];
            }
#pragma unroll
            for (int mf = 0; mf < 4; ++mf)
#pragma unroll
                for (int nf = 0; nf < 4; ++nf)
                    mma_f16(acc[mf][nf], af[mf], bf[nf]);
        }
        __syncthreads();
    }

#pragma unroll
    for (int nf = 0; nf < 4; ++nf) {
        int col = bn + wc * 32 + nf * 8 + lc * 2;
        float b0 = b3[col], b1 = b3[col + 1];
#pragma unroll
        for (int mf = 0; mf < 4; ++mf) {
            int row = bm + wr * 64 + mf * 16 + lr;
            *(__half2*)&QKV[(size_t)row * N3 + col] =
                __floats2half2_rn(acc[mf][nf][0] + b0, acc[mf][nf][1] + b1);
            *(__half2*)&QKV[(size_t)(row + 8) * N3 + col] =
                __floats2half2_rn(acc[mf][nf][2] + b0, acc[mf][nf][3] + b1);
        }
    }
}

// ===== fused attention: quarter-pipelined scores+exp+store+Z+PV =============
#define FA_ST 72
#define FA_SMEM (5 * 128 * FA_ST * 2)

__global__ __launch_bounds__(256, 2)
void attn_fused(const __half* __restrict__ QKV, __half* __restrict__ Ph,
                __half* __restrict__ Ch)
{
    extern __shared__ __half sm[];
    const uint32_t QsB  = (uint32_t)__cvta_generic_to_shared(sm);
    const uint32_t KsB[2] = { QsB + 128 * FA_ST * 2, QsB + 2 * 128 * FA_ST * 2 };
    const uint32_t VsB[2] = { QsB + 3 * 128 * FA_ST * 2, QsB + 4 * 128 * FA_ST * 2 };

    const int tid = threadIdx.x;
    const int lane = tid & 31, warp = tid >> 5;
    const int lr = lane >> 2, lc = lane & 3;
    const int bh = blockIdx.y, b = bh >> 4, h = bh & 15;
    const int mi = blockIdx.x * 128;

    // Q load (group 0)
#pragma unroll
    for (int i = 0; i < 4; ++i) {
        int c = tid + i * 256;
        int row = c >> 3, ch = c & 7;
        cp_async16(QsB + (uint32_t)((row * FA_ST + ch * 8) * 2),
                   QKV + (size_t)(b * SS + mi + row) * N3 + h * 64 + ch * 8);
    }
    cp_commit();

    auto issueKV = [&](int jt, int buf) {
#pragma unroll
        for (int i = 0; i < 4; ++i) {
            int c = tid + i * 256;
            int row = c >> 3, ch = c & 7;
            size_t base = (size_t)(b * SS + jt * 128 + row) * N3 + h * 64 + ch * 8;
            cp_async16(KsB[buf] + (uint32_t)((row * FA_ST + ch * 8) * 2),
                       QKV + base + 1024);
            cp_async16(VsB[buf] + (uint32_t)((row * FA_ST + ch * 8) * 2),
                       QKV + base + 2048);
        }
        cp_commit();
    };
    issueKV(0, 0);

    // exp(s*g - 8) = ex2(s * g2 + C8)
    const float g2 = g_gate[bh] * 1.4426950408889634f;
    const float C8 = -11.541560327111708f;

    const int a_row  = warp * 16 + (lane & 15);
    const int a_koff = (lane >> 4) * 8;
    const int b1_nrow = (lane & 7) + (lane >> 4) * 8;
    const int b1_koff = ((lane >> 3) & 1) * 8;
    const int b2_krow = (lane & 7) + ((lane >> 3) & 1) * 8;
    const int b2_noff = (lane >> 4) * 8;

    // hoist Q fragments
    cp_wait1();
    __syncthreads();
    uint32_t qf[4][4];
#pragma unroll
    for (int ks = 0; ks < 4; ++ks)
        ldsm_x4(qf[ks], QsB + (uint32_t)((a_row * FA_ST + ks * 16 + a_koff) * 2));

    float ctx[8][4];
#pragma unroll
    for (int i = 0; i < 8; ++i)
#pragma unroll
        for (int r = 0; r < 4; ++r) ctx[i][r] = 0.0f;
    float zs0 = 0.0f, zs1 = 0.0f;

    const int grow = mi + warp * 16 + lr;
    __half* Prow0 = Ph + ((size_t)bh * SS + grow) * SS;
    __half* Prow1 = Ph + ((size_t)bh * SS + grow + 8) * SS;

    auto mma1_q = [&](int buf, int q, float (&acc)[4][4]) {
#pragma unroll
        for (int i = 0; i < 4; ++i)
#pragma unroll
            for (int r = 0; r < 4; ++r) acc[i][r] = 0.0f;
#pragma unroll
        for (int ks = 0; ks < 4; ++ks)
#pragma unroll
            for (int np = 0; np < 2; ++np) {
                uint32_t r4[4];
                ldsm_x4(r4, KsB[buf] +
                        (uint32_t)(((q * 32 + np * 16 + b1_nrow) * FA_ST +
                                    ks * 16 + b1_koff) * 2));
                mma_f16(acc[np * 2], qf[ks], r4);
                mma_f16(acc[np * 2 + 1], qf[ks], r4 + 2);
            }
    };

    auto epi_q = [&](int buf, int jt, int q, float (&acc)[4][4]) {
        uint32_t r0v[4], r1v[4];
#pragma unroll
        for (int np = 0; np < 2; ++np) {
            float pa0 = ex2(fmaf(acc[np * 2][0], g2, C8));
            float pa1 = ex2(fmaf(acc[np * 2][1], g2, C8));
            float pb0 = ex2(fmaf(acc[np * 2][2], g2, C8));
            float pb1 = ex2(fmaf(acc[np * 2][3], g2, C8));
            float pc0 = ex2(fmaf(acc[np * 2 + 1][0], g2, C8));
            float pc1 = ex2(fmaf(acc[np * 2 + 1][1], g2, C8));
            float pd0 = ex2(fmaf(acc[np * 2 + 1][2], g2, C8));
            float pd1 = ex2(fmaf(acc[np * 2 + 1][3], g2, C8));
            __half2 wa = __floats2half2_rn(pa0, pa1);
            __half2 wb = __floats2half2_rn(pb0, pb1);
            __half2 wc2 = __floats2half2_rn(pc0, pc1);
            __half2 wd = __floats2half2_rn(pd0, pd1);
            zs0 += (pa0 + pa1) + (pc0 + pc1);
            zs1 += (pb0 + pb1) + (pd0 + pd1);
            r0v[np * 2] = h2u(wa); r0v[np * 2 + 1] = h2u(wc2);
            r1v[np * 2] = h2u(wb); r1v[np * 2 + 1] = h2u(wd);

            uint32_t af2[4] = { h2u(wa), h2u(wb), h2u(wc2), h2u(wd) };
#pragma unroll
            for (int n2 = 0; n2 < 4; ++n2) {
                uint32_t r4[4];
                ldsm_x4_t(r4, VsB[buf] +
                          (uint32_t)(((q * 32 + np * 16 + b2_krow) * FA_ST +
                                      n2 * 16 + b2_noff) * 2));
                mma_f16(ctx[n2 * 2], af2, r4);
                mma_f16(ctx[n2 * 2 + 1], af2, r4 + 2);
            }
        }
        int poff = jt * 128 + q * 32 + 8 * lc;
        *(uint4*)&Prow0[poff] = make_uint4(r0v[0], r0v[1], r0v[2], r0v[3]);
        *(uint4*)&Prow1[poff] = make_uint4(r1v[0], r1v[1], r1v[2], r1v[3]);
    };

    for (int jt = 0; jt < 16; ++jt) {
        const int buf = jt & 1;
        if (jt + 1 < 16) { issueKV(jt + 1, buf ^ 1); cp_wait1(); }
        else cp_wait0();
        __syncthreads();

        float accA[4][4], accB[4][4];
        mma1_q(buf, 0, accA);
        mma1_q(buf, 1, accB);
        epi_q(buf, jt, 0, accA);
        mma1_q(buf, 2, accA);
        epi_q(buf, jt, 1, accB);
        mma1_q(buf, 3, accB);
        epi_q(buf, jt, 2, accA);
        epi_q(buf, jt, 3, accB);

        __syncthreads();
    }

    zs0 += __shfl_xor_sync(0xffffffffu, zs0, 1);
    zs0 += __shfl_xor_sync(0xffffffffu, zs0, 2);
    zs1 += __shfl_xor_sync(0xffffffffu, zs1, 1);
    zs1 += __shfl_xor_sync(0xffffffffu, zs1, 2);
    float iz0 = 1.0f / zs0, iz1 = 1.0f / zs1;
    if (lc == 0) {
        g_invZ[(size_t)bh * SS + grow]     = iz0;
        g_invZ[(size_t)bh * SS + grow + 8] = iz1;
    }

    __half* Cc = Ch + (size_t)b * SS * EE + h * 64;
#pragma unroll
    for (int np = 0; np < 8; ++np) {
        int n = np * 8 + 2 * lc;
        *(__half2*)&Cc[(size_t)grow * EE + n] =
            __floats2half2_rn(ctx[np][0] * iz0, ctx[np][1] * iz0);
        *(__half2*)&Cc[(size_t)(grow + 8) * EE + n] =
            __floats2half2_rn(ctx[np][2] * iz1, ctx[np][3] * iz1);
    }
}

// ===== tail: out-proj GEMM (blocks 0..255) || head-mean (blocks 256..2303) ==
// Mean reads the PERMUTED block-32 P layout; each thread covers a 16-half
// half-block (hf = bit2 of actual col), 128 threads per row.
__global__ __launch_bounds__(256)
void tail_kernel(const __half* __restrict__ Ch, const __half* __restrict__ Who,
                 const float* __restrict__ bo, float* __restrict__ out,
                 const __half* __restrict__ Ph, float* __restrict__ om)
{
    const int bid = blockIdx.x;
    if (bid < 256) {
        gemm_body<false>(Ch, Who, bo, out, EE, bid & 7, bid >> 3);
        return;
    }
    const int id = bid - 256;                 // 0..2047
    const int tid = threadIdx.x;
    const int grow = id * 2 + (tid >> 7);     // global row 0..4095
    const int b = grow >> 11, i = grow & (SS - 1);
    const int j = tid & 127;
    const int blk = j >> 1, hf = j & 1;       // 32-col block, half-block

    float acc[16];
#pragma unroll
    for (int s = 0; s < 16; ++s) acc[s] = 0.0f;

    for (int hh = 0; hh < HH; ++hh) {
        const __half* base = Ph + ((size_t)(b * HH + hh) * SS + i) * SS
                               + blk * 32 + hf * 16;
        float w = g_invZ[(size_t)(b * HH + hh) * SS + i] * 0.0625f;
        uint4 v0 = *(const uint4*)base;
        uint4 v1 = *(const uint4*)(base + 8);
        const uint32_t* vv = (const uint32_t*)&v0;
#pragma unroll
        for (int q = 0; q < 4; ++q) {
            float2 f = __half22float2(*(const __half2*)&vv[q]);
            acc[2 * q]     = fmaf(w, f.x, acc[2 * q]);
            acc[2 * q + 1] = fmaf(w, f.y, acc[2 * q + 1]);
        }
        const uint32_t* vw = (const uint32_t*)&v1;
#pragma unroll
        for (int q = 0; q < 4; ++q) {
            float2 f = __half22float2(*(const __half2*)&vw[q]);
            acc[8 + 2 * q]     = fmaf(w, f.x, acc[8 + 2 * q]);
            acc[8 + 2 * q + 1] = fmaf(w, f.y, acc[8 + 2 * q + 1]);
        }
    }

    // unpermute within half-block: output col groups {0,8,16,24}+hf*4, 4 wide;
    // s_local(g,k) = 8*((k>>1)&1) + 4*((g>>4)&1) + 2*((g>>3)&1) + (k&1)
    float* op = om + (size_t)(b * SS + i) * SS + blk * 32 + hf * 4;
    *(float4*)&op[0]  = make_float4(acc[0], acc[1], acc[8],  acc[9]);
    *(float4*)&op[8]  = make_float4(acc[2], acc[3], acc[10], acc[11]);
    *(float4*)&op[16] = make_float4(acc[4], acc[5], acc[12], acc[13]);
    *(float4*)&op[24] = make_float4(acc[6], acc[7], acc[14], acc[15]);
}

// ---------------- launch ----------------
extern "C" void kernel_launch(void* const* d_in, const int* in_sizes, int n_in,
                              void* d_out, int out_size)
{
    const float* x   = (const float*)d_in[0];
    const float* sf  = (const float*)d_in[1];
    const float* Wq  = (const float*)d_in[2];
    const float* bq  = (const float*)d_in[3];
    const float* Wk  = (const float*)d_in[4];
    const float* bk  = (const float*)d_in[5];
    const float* Wv  = (const float*)d_in[6];
    const float* bv  = (const float*)d_in[7];
    const float* Ws1 = (const float*)d_in[8];
    const float* bs1 = (const float*)d_in[9];
    const float* Ws2 = (const float*)d_in[10];
    const float* bs2 = (const float*)d_in[11];
    const float* Wo  = (const float*)d_in[12];
    const float* bo  = (const float*)d_in[13];
    float* out = (float*)d_out;

    __half *pXh, *pW3, *pWho, *pQKV, *pCh, *pPh;
    float *pb3;
    cudaGetSymbolAddress((void**)&pXh, g_Xh);
    cudaGetSymbolAddress((void**)&pW3, g_W3);
    cudaGetSymbolAddress((void**)&pWho, g_Who);
    cudaGetSymbolAddress((void**)&pb3, g_b3);
    cudaGetSymbolAddress((void**)&pQKV, g_QKV);
    cudaGetSymbolAddress((void**)&pCh, g_CTXh);
    cudaGetSymbolAddress((void**)&pPh, g_Ph);

    // 0. prep: conversions + interleave + gate + bias combine
    prep<<<1 + 4096 + 3072 + 1024, 256>>>(x, Wq, Wk, Wv, Wo, bq, bk, bv,
                                          sf, Ws1, bs1, Ws2, bs2);

    // 1. fused QKV projection: [4096,1024] @ [1024,3072], BK=64
    cudaFuncSetAttribute(gemm_qkv64, cudaFuncAttributeMaxDynamicSharedMemorySize, QK_SMEM);
    gemm_qkv64<<<dim3(N3 / 128, (BB * SS) / 128), 256, QK_SMEM>>>(pXh, pW3, pb3, pQKV);

    // 2. fused attention: quarter-pipelined, permuted p~ store
    cudaFuncSetAttribute(attn_fused, cudaFuncAttributeMaxDynamicSharedMemorySize, FA_SMEM);
    attn_fused<<<dim3(SS / 128, BB * HH), 256, FA_SMEM>>>(pQKV, pPh, pCh);

    // 3. tail: out-proj GEMM || head-mean (grid-partitioned co-execution)
    tail_kernel<<<256 + (BB * SS) / 2, 256>>>(pCh, pWho, bo, out, pPh,
                                              out + (size_t)BB * SS * EE);

    (void)in_sizes; (void)n_in; (void)out_size;
}

// round 15
// speedup vs baseline: 2.2026x; 1.0053x over previous
#include <cuda_runtime.h>
#include <cuda_fp16.h>
#include <cstdint>
#include <cstddef>

#define BB 2
#define SS 2048
#define EE 1024
#define HH 16
#define HID 256
#define N3 3072

// ---------------- scratch (device globals: allocation-free) ----------------
__device__ __half g_Xh[(size_t)BB * SS * EE];
__device__ __half g_W3[(size_t)EE * N3];        // interleaved [k][Wq|Wk|Wv]
__device__ __half g_Who[(size_t)EE * EE];
__device__ float  g_b3[N3];
__device__ __half g_QKV[(size_t)BB * SS * N3];  // [b,s][q|k|v]
__device__ __half g_CTXh[(size_t)BB * SS * EE];
// p~ stored in PERMUTED block-32 layout:
// within each 32-col block, actual col c stored at
// s = 8*((c&7)>>1) + 4*((c>>4)&1) + 2*((c>>3)&1) + (c&1)
__device__ __half g_Ph[(size_t)BB * HH * SS * SS];
__device__ float  g_invZ[(size_t)BB * HH * SS];
__device__ float  g_gate[BB * HH];

// ---------------- helpers ----------------
__device__ __forceinline__ float ex2(float x) {
    float r; asm("ex2.approx.f32 %0, %1;" : "=f"(r) : "f"(x)); return r;
}

__device__ __forceinline__ void mma_f16(float* d, const uint32_t* a, const uint32_t* b) {
    asm volatile("mma.sync.aligned.m16n8k16.row.col.f32.f16.f16.f32 "
                 "{%0,%1,%2,%3}, {%4,%5,%6,%7}, {%8,%9}, {%0,%1,%2,%3};"
                 : "+f"(d[0]), "+f"(d[1]), "+f"(d[2]), "+f"(d[3])
                 : "r"(a[0]), "r"(a[1]), "r"(a[2]), "r"(a[3]),
                   "r"(b[0]), "r"(b[1]));
}

__device__ __forceinline__ void ldsm_x4(uint32_t* r, uint32_t addr) {
    asm volatile("ldmatrix.sync.aligned.m8n8.x4.shared.b16 {%0,%1,%2,%3}, [%4];"
                 : "=r"(r[0]), "=r"(r[1]), "=r"(r[2]), "=r"(r[3]) : "r"(addr));
}
__device__ __forceinline__ void ldsm_x4_t(uint32_t* r, uint32_t addr) {
    asm volatile("ldmatrix.sync.aligned.m8n8.x4.trans.shared.b16 {%0,%1,%2,%3}, [%4];"
                 : "=r"(r[0]), "=r"(r[1]), "=r"(r[2]), "=r"(r[3]) : "r"(addr));
}

__device__ __forceinline__ void cp_async16(uint32_t smem, const void* g) {
    asm volatile("cp.async.cg.shared.global [%0], [%1], 16;" :: "r"(smem), "l"(g));
}
__device__ __forceinline__ void cp_commit() { asm volatile("cp.async.commit_group;"); }
__device__ __forceinline__ void cp_wait0()  { asm volatile("cp.async.wait_group 0;"); }
__device__ __forceinline__ void cp_wait1()  { asm volatile("cp.async.wait_group 1;"); }

__device__ __forceinline__ uint32_t h2u(__half2 h) { return *(uint32_t*)&h; }

// ================= prep: f2h conversions + gate + bias combine ==============
__global__ __launch_bounds__(256)
void prep(const float* __restrict__ x,
          const float* __restrict__ Wq, const float* __restrict__ Wk,
          const float* __restrict__ Wv, const float* __restrict__ Wo,
          const float* __restrict__ bq, const float* __restrict__ bk,
          const float* __restrict__ bv,
          const float* __restrict__ sf,
          const float* __restrict__ Ws1, const float* __restrict__ bs1,
          const float* __restrict__ Ws2, const float* __restrict__ bs2)
{
    const int bid = blockIdx.x, tid = threadIdx.x;
    if (bid == 0) {
        __shared__ float h1[BB][HID];
        for (int b = 0; b < BB; ++b) {
            float acc = bs1[tid];
            for (int e = 0; e < EE; ++e)
                acc += sf[b * EE + e] * Ws1[(size_t)e * HID + tid];
            h1[b][tid] = fmaxf(acc, 0.0f);
        }
        __syncthreads();
        if (tid < BB * HH) {
            int b = tid / HH, h = tid % HH;
            float acc = bs2[h];
            for (int k = 0; k < HID; ++k)
                acc += h1[b][k] * Ws2[k * HH + h];
            g_gate[b * HH + h] = (1.0f / (1.0f + __expf(-acc))) * 0.125f;
        }
        for (int i = tid; i < EE; i += 256) {
            g_b3[i] = bq[i]; g_b3[EE + i] = bk[i]; g_b3[2 * EE + i] = bv[i];
        }
        return;
    }
    int t = (bid - 1) * 256 + tid;
    if (t < 1048576) {                    // X: 4M floats
        float4 v = ((const float4*)x)[t];
        ((__half2*)g_Xh)[2 * t]     = __floats2half2_rn(v.x, v.y);
        ((__half2*)g_Xh)[2 * t + 1] = __floats2half2_rn(v.z, v.w);
        return;
    }
    t -= 1048576;
    if (t < 3 * 262144) {                 // Wq/Wk/Wv interleave into [k][3N]
        int which = t / 262144;
        int u = t - which * 262144;
        const float* W = (which == 0) ? Wq : ((which == 1) ? Wk : Wv);
        float4 v = ((const float4*)W)[u];
        int k = u >> 8, n4 = u & 255;
        size_t d = (size_t)k * N3 + which * EE + n4 * 4;
        *(__half2*)&g_W3[d]     = __floats2half2_rn(v.x, v.y);
        *(__half2*)&g_W3[d + 2] = __floats2half2_rn(v.z, v.w);
        return;
    }
    t -= 3 * 262144;
    if (t < 262144) {                     // Wo
        float4 v = ((const float4*)Wo)[t];
        ((__half2*)g_Who)[2 * t]     = __floats2half2_rn(v.x, v.y);
        ((__half2*)g_Who)[2 * t + 1] = __floats2half2_rn(v.z, v.w);
    }
}

// ---------------- QKV GEMM: 128x128x64 tiles, dynamic smem ----------------
#define QK_SA 72
#define QK_SB 136
#define QK_ABYTES (128 * QK_SA * 2)
#define QK_BBYTES (64 * QK_SB * 2)
#define QK_SMEM (2 * QK_ABYTES + 2 * QK_BBYTES)

__global__ __launch_bounds__(256, 2)
void gemm_qkv64(const __half* __restrict__ Xh, const __half* __restrict__ W3,
                const float* __restrict__ b3, __half* __restrict__ QKV)
{
    extern __shared__ __half dsm[];
    const uint32_t base = (uint32_t)__cvta_generic_to_shared(dsm);
    const uint32_t AsB[2] = { base, base + QK_ABYTES };
    const uint32_t BsB[2] = { base + 2 * QK_ABYTES, base + 2 * QK_ABYTES + QK_BBYTES };

    const int tid = threadIdx.x;
    const int lane = tid & 31, warp = tid >> 5;
    const int wr = warp & 1, wc = warp >> 1;
    const int lr = lane >> 2, lc = lane & 3;
    const int bm = blockIdx.y * 128, bn = blockIdx.x * 128;

    auto issue = [&](int kt, int buf) {
        const int k0 = kt * 64;
#pragma unroll
        for (int i = 0; i < 4; ++i) {
            int id = tid + i * 256;
            int ar = id >> 3, ac = id & 7;
            cp_async16(AsB[buf] + (uint32_t)((ar * QK_SA + ac * 8) * 2),
                       Xh + (size_t)(bm + ar) * EE + k0 + ac * 8);
            int br = id >> 4, bc = id & 15;
            cp_async16(BsB[buf] + (uint32_t)((br * QK_SB + bc * 8) * 2),
                       W3 + (size_t)(k0 + br) * N3 + bn + bc * 8);
        }
        cp_commit();
    };

    float acc[4][4][4];
#pragma unroll
    for (int i = 0; i < 4; ++i)
#pragma unroll
        for (int j = 0; j < 4; ++j)
#pragma unroll
            for (int r = 0; r < 4; ++r) acc[i][j][r] = 0.0f;

    const int a_row_l = wr * 64 + (lane & 15);
    const int a_koff = (lane >> 4) * 8;
    const int b_krow = (lane & 7) + ((lane >> 3) & 1) * 8;
    const int b_noff = (lane >> 4) * 8;

    const int nk = EE / 64;   // 16
    issue(0, 0);

    for (int kt = 0; kt < nk; ++kt) {
        const int buf = kt & 1;
        if (kt + 1 < nk) { issue(kt + 1, buf ^ 1); cp_wait1(); }
        else cp_wait0();
        __syncthreads();

#pragma unroll
        for (int ks = 0; ks < 4; ++ks) {
            const int k0 = ks * 16;
            uint32_t af[4][4], bf[4][2];
#pragma unroll
            for (int mf = 0; mf < 4; ++mf)
                ldsm_x4(af[mf], AsB[buf] +
                        (uint32_t)(((a_row_l + mf * 16) * QK_SA + k0 + a_koff) * 2));
#pragma unroll
            for (int np = 0; np < 2; ++np) {
                uint32_t r4[4];
                int n0 = wc * 32 + np * 16;
                ldsm_x4_t(r4, BsB[buf] +
                          (uint32_t)(((k0 + b_krow) * QK_SB + n0 + b_noff) * 2));
                bf[np * 2][0] = r4[0]; bf[np * 2][1] = r4[1];
                bf[np * 2 + 1][0] = r4[2]; bf[np * 2 + 1][1] = r4[3];
            }
#pragma unroll
            for (int mf = 0; mf < 4; ++mf)
#pragma unroll
                for (int nf = 0; nf < 4; ++nf)
                    mma_f16(acc[mf][nf], af[mf], bf[nf]);
        }
        __syncthreads();
    }

#pragma unroll
    for (int nf = 0; nf < 4; ++nf) {
        int col = bn + wc * 32 + nf * 8 + lc * 2;
        float b0 = b3[col], b1 = b3[col + 1];
#pragma unroll
        for (int mf = 0; mf < 4; ++mf) {
            int row = bm + wr * 64 + mf * 16 + lr;
            *(__half2*)&QKV[(size_t)row * N3 + col] =
                __floats2half2_rn(acc[mf][nf][0] + b0, acc[mf][nf][1] + b1);
            *(__half2*)&QKV[(size_t)(row + 8) * N3 + col] =
                __floats2half2_rn(acc[mf][nf][2] + b0, acc[mf][nf][3] + b1);
        }
    }
}

// ===== fused attention: quarter-pipelined scores+exp+store+Z+PV =============
#define FA_ST 72
#define FA_SMEM (5 * 128 * FA_ST * 2)

__global__ __launch_bounds__(256, 2)
void attn_fused(const __half* __restrict__ QKV, __half* __restrict__ Ph,
                __half* __restrict__ Ch)
{
    extern __shared__ __half sm[];
    const uint32_t QsB  = (uint32_t)__cvta_generic_to_shared(sm);
    const uint32_t KsB[2] = { QsB + 128 * FA_ST * 2, QsB + 2 * 128 * FA_ST * 2 };
    const uint32_t VsB[2] = { QsB + 3 * 128 * FA_ST * 2, QsB + 4 * 128 * FA_ST * 2 };

    const int tid = threadIdx.x;
    const int lane = tid & 31, warp = tid >> 5;
    const int lr = lane >> 2, lc = lane & 3;
    const int bh = blockIdx.y, b = bh >> 4, h = bh & 15;
    const int mi = blockIdx.x * 128;

    // Q load (group 0)
#pragma unroll
    for (int i = 0; i < 4; ++i) {
        int c = tid + i * 256;
        int row = c >> 3, ch = c & 7;
        cp_async16(QsB + (uint32_t)((row * FA_ST + ch * 8) * 2),
                   QKV + (size_t)(b * SS + mi + row) * N3 + h * 64 + ch * 8);
    }
    cp_commit();

    auto issueKV = [&](int jt, int buf) {
#pragma unroll
        for (int i = 0; i < 4; ++i) {
            int c = tid + i * 256;
            int row = c >> 3, ch = c & 7;
            size_t base = (size_t)(b * SS + jt * 128 + row) * N3 + h * 64 + ch * 8;
            cp_async16(KsB[buf] + (uint32_t)((row * FA_ST + ch * 8) * 2),
                       QKV + base + 1024);
            cp_async16(VsB[buf] + (uint32_t)((row * FA_ST + ch * 8) * 2),
                       QKV + base + 2048);
        }
        cp_commit();
    };
    issueKV(0, 0);

    // exp(s*g - 8) = ex2(s * g2 + C8)
    const float g2 = g_gate[bh] * 1.4426950408889634f;
    const float C8 = -11.541560327111708f;

    const int a_row  = warp * 16 + (lane & 15);
    const int a_koff = (lane >> 4) * 8;
    const int b1_nrow = (lane & 7) + (lane >> 4) * 8;
    const int b1_koff = ((lane >> 3) & 1) * 8;
    const int b2_krow = (lane & 7) + ((lane >> 3) & 1) * 8;
    const int b2_noff = (lane >> 4) * 8;

    // hoist Q fragments
    cp_wait1();
    __syncthreads();
    uint32_t qf[4][4];
#pragma unroll
    for (int ks = 0; ks < 4; ++ks)
        ldsm_x4(qf[ks], QsB + (uint32_t)((a_row * FA_ST + ks * 16 + a_koff) * 2));

    float ctx[8][4];
#pragma unroll
    for (int i = 0; i < 8; ++i)
#pragma unroll
        for (int r = 0; r < 4; ++r) ctx[i][r] = 0.0f;
    float zs0 = 0.0f, zs1 = 0.0f;

    const int grow = mi + warp * 16 + lr;
    __half* Prow0 = Ph + ((size_t)bh * SS + grow) * SS;
    __half* Prow1 = Ph + ((size_t)bh * SS + grow + 8) * SS;

    auto mma1_q = [&](int buf, int q, float (&acc)[4][4]) {
#pragma unroll
        for (int i = 0; i < 4; ++i)
#pragma unroll
            for (int r = 0; r < 4; ++r) acc[i][r] = 0.0f;
#pragma unroll
        for (int ks = 0; ks < 4; ++ks)
#pragma unroll
            for (int np = 0; np < 2; ++np) {
                uint32_t r4[4];
                ldsm_x4(r4, KsB[buf] +
                        (uint32_t)(((q * 32 + np * 16 + b1_nrow) * FA_ST +
                                    ks * 16 + b1_koff) * 2));
                mma_f16(acc[np * 2], qf[ks], r4);
                mma_f16(acc[np * 2 + 1], qf[ks], r4 + 2);
            }
    };

    auto epi_q = [&](int buf, int jt, int q, float (&acc)[4][4]) {
        uint32_t r0v[4], r1v[4];
#pragma unroll
        for (int np = 0; np < 2; ++np) {
            float pa0 = ex2(fmaf(acc[np * 2][0], g2, C8));
            float pa1 = ex2(fmaf(acc[np * 2][1], g2, C8));
            float pb0 = ex2(fmaf(acc[np * 2][2], g2, C8));
            float pb1 = ex2(fmaf(acc[np * 2][3], g2, C8));
            float pc0 = ex2(fmaf(acc[np * 2 + 1][0], g2, C8));
            float pc1 = ex2(fmaf(acc[np * 2 + 1][1], g2, C8));
            float pd0 = ex2(fmaf(acc[np * 2 + 1][2], g2, C8));
            float pd1 = ex2(fmaf(acc[np * 2 + 1][3], g2, C8));
            __half2 wa = __floats2half2_rn(pa0, pa1);
            __half2 wb = __floats2half2_rn(pb0, pb1);
            __half2 wc2 = __floats2half2_rn(pc0, pc1);
            __half2 wd = __floats2half2_rn(pd0, pd1);
            zs0 += (pa0 + pa1) + (pc0 + pc1);
            zs1 += (pb0 + pb1) + (pd0 + pd1);
            r0v[np * 2] = h2u(wa); r0v[np * 2 + 1] = h2u(wc2);
            r1v[np * 2] = h2u(wb); r1v[np * 2 + 1] = h2u(wd);

            uint32_t af2[4] = { h2u(wa), h2u(wb), h2u(wc2), h2u(wd) };
#pragma unroll
            for (int n2 = 0; n2 < 4; ++n2) {
                uint32_t r4[4];
                ldsm_x4_t(r4, VsB[buf] +
                          (uint32_t)(((q * 32 + np * 16 + b2_krow) * FA_ST +
                                      n2 * 16 + b2_noff) * 2));
                mma_f16(ctx[n2 * 2], af2, r4);
                mma_f16(ctx[n2 * 2 + 1], af2, r4 + 2);
            }
        }
        int poff = jt * 128 + q * 32 + 8 * lc;
        *(uint4*)&Prow0[poff] = make_uint4(r0v[0], r0v[1], r0v[2], r0v[3]);
        *(uint4*)&Prow1[poff] = make_uint4(r1v[0], r1v[1], r1v[2], r1v[3]);
    };

    for (int jt = 0; jt < 16; ++jt) {
        const int buf = jt & 1;
        if (jt + 1 < 16) { issueKV(jt + 1, buf ^ 1); cp_wait1(); }
        else cp_wait0();
        __syncthreads();

        float accA[4][4], accB[4][4];
        mma1_q(buf, 0, accA);
        mma1_q(buf, 1, accB);
        epi_q(buf, jt, 0, accA);
        mma1_q(buf, 2, accA);
        epi_q(buf, jt, 1, accB);
        mma1_q(buf, 3, accB);
        epi_q(buf, jt, 2, accA);
        epi_q(buf, jt, 3, accB);

        __syncthreads();
    }

    zs0 += __shfl_xor_sync(0xffffffffu, zs0, 1);
    zs0 += __shfl_xor_sync(0xffffffffu, zs0, 2);
    zs1 += __shfl_xor_sync(0xffffffffu, zs1, 1);
    zs1 += __shfl_xor_sync(0xffffffffu, zs1, 2);
    float iz0 = 1.0f / zs0, iz1 = 1.0f / zs1;
    if (lc == 0) {
        g_invZ[(size_t)bh * SS + grow]     = iz0;
        g_invZ[(size_t)bh * SS + grow + 8] = iz1;
    }

    __half* Cc = Ch + (size_t)b * SS * EE + h * 64;
#pragma unroll
    for (int np = 0; np < 8; ++np) {
        int n = np * 8 + 2 * lc;
        *(__half2*)&Cc[(size_t)grow * EE + n] =
            __floats2half2_rn(ctx[np][0] * iz0, ctx[np][1] * iz0);
        *(__half2*)&Cc[(size_t)(grow + 8) * EE + n] =
            __floats2half2_rn(ctx[np][2] * iz1, ctx[np][3] * iz1);
    }
}

// ===== tail: out-proj GEMM 128x64 (blocks 0..511) || head-mean (512..2559) ==
// Smaller GEMM tile (acc 32/thread) + launch_bounds(256,3) -> 3 CTAs/SM so the
// memory-bound mean gets more warps. Mean math order identical to before.
__global__ __launch_bounds__(256, 3)
void tail_kernel(const __half* __restrict__ Ch, const __half* __restrict__ Who,
                 const float* __restrict__ bo, float* __restrict__ out,
                 const __half* __restrict__ Ph, float* __restrict__ om)
{
    constexpr int SA = 40;
    constexpr int SB = 72;
    __shared__ __half As[2][128 * SA];
    __shared__ __half Bs[2][32 * SB];

    const int bid = blockIdx.x;
    const int tid = threadIdx.x;

    if (bid < 512) {
        // ---- GEMM: C[4096,1024] = ctx @ Who + bo, tile 128x64 ----
        const int bx = bid & 15, by = bid >> 4;
        const int lane = tid & 31, warp = tid >> 5;
        const int wr = warp & 3, wc = warp >> 2;    // 4(M) x 2(N) warps
        const int lr = lane >> 2, lc = lane & 3;
        const int bm = by * 128, bn = bx * 64;

        const uint32_t AsB[2] = { (uint32_t)__cvta_generic_to_shared(&As[0][0]),
                                  (uint32_t)__cvta_generic_to_shared(&As[1][0]) };
        const uint32_t BsB[2] = { (uint32_t)__cvta_generic_to_shared(&Bs[0][0]),
                                  (uint32_t)__cvta_generic_to_shared(&Bs[1][0]) };

        const int arow0 = tid >> 2, ach0 = tid & 3;
        const int brow = tid >> 3, bch = tid & 7;

        auto issue = [&](int kt, int buf) {
            cp_async16(AsB[buf] + (uint32_t)((arow0 * SA + ach0 * 8) * 2),
                       Ch + (size_t)(bm + arow0) * EE + kt * 32 + ach0 * 8);
            cp_async16(AsB[buf] + (uint32_t)(((arow0 + 64) * SA + ach0 * 8) * 2),
                       Ch + (size_t)(bm + arow0 + 64) * EE + kt * 32 + ach0 * 8);
            cp_async16(BsB[buf] + (uint32_t)((brow * SB + bch * 8) * 2),
                       Who + (size_t)(kt * 32 + brow) * EE + bn + bch * 8);
            cp_commit();
        };

        float acc[2][4][4];
#pragma unroll
        for (int i = 0; i < 2; ++i)
#pragma unroll
            for (int j = 0; j < 4; ++j)
#pragma unroll
                for (int r = 0; r < 4; ++r) acc[i][j][r] = 0.0f;

        const int a_row_l = wr * 32 + (lane & 15);
        const int a_koff = (lane >> 4) * 8;
        const int b_krow = (lane & 7) + ((lane >> 3) & 1) * 8;
        const int b_noff = (lane >> 4) * 8;

        const int nk = EE / 32;   // 32
        issue(0, 0);

        for (int kt = 0; kt < nk; ++kt) {
            const int buf = kt & 1;
            if (kt + 1 < nk) { issue(kt + 1, buf ^ 1); cp_wait1(); }
            else cp_wait0();
            __syncthreads();

#pragma unroll
            for (int ks = 0; ks < 2; ++ks) {
                const int k0 = ks * 16;
                uint32_t af[2][4], bf[4][2];
#pragma unroll
                for (int mf = 0; mf < 2; ++mf)
                    ldsm_x4(af[mf], AsB[buf] +
                            (uint32_t)(((a_row_l + mf * 16) * SA + k0 + a_koff) * 2));
#pragma unroll
                for (int np = 0; np < 2; ++np) {
                    uint32_t r4[4];
                    int n0 = wc * 32 + np * 16;
                    ldsm_x4_t(r4, BsB[buf] +
                              (uint32_t)(((k0 + b_krow) * SB + n0 + b_noff) * 2));
                    bf[np * 2][0] = r4[0]; bf[np * 2][1] = r4[1];
                    bf[np * 2 + 1][0] = r4[2]; bf[np * 2 + 1][1] = r4[3];
                }
#pragma unroll
                for (int mf = 0; mf < 2; ++mf)
#pragma unroll
                    for (int nf = 0; nf < 4; ++nf)
                        mma_f16(acc[mf][nf], af[mf], bf[nf]);
            }
            __syncthreads();
        }

#pragma unroll
        for (int nf = 0; nf < 4; ++nf) {
            int col = bn + wc * 32 + nf * 8 + lc * 2;
            float b0 = bo[col], b1 = bo[col + 1];
#pragma unroll
            for (int mf = 0; mf < 2; ++mf) {
                int row = bm + wr * 32 + mf * 16 + lr;
                *(float2*)&out[(size_t)row * EE + col] =
                    make_float2(acc[mf][nf][0] + b0, acc[mf][nf][1] + b1);
                *(float2*)&out[(size_t)(row + 8) * EE + col] =
                    make_float2(acc[mf][nf][2] + b0, acc[mf][nf][3] + b1);
            }
        }
        return;
    }

    // ---- mean: blocks 512..2559; 2 rows per block, 128 threads per row ----
    const int id = bid - 512;                 // 0..2047
    const int grow = id * 2 + (tid >> 7);     // global row 0..4095
    const int b = grow >> 11, i = grow & (SS - 1);
    const int j = tid & 127;
    const int blk = j >> 1, hf = j & 1;       // 32-col block, half-block

    float acc[16];
#pragma unroll
    for (int s = 0; s < 16; ++s) acc[s] = 0.0f;

#pragma unroll
    for (int h4 = 0; h4 < HH; h4 += 4) {
        float w[4];
        uint4 v0[4], v1[4];
#pragma unroll
        for (int u = 0; u < 4; ++u) {
            const int hh = h4 + u;
            w[u] = g_invZ[(size_t)(b * HH + hh) * SS + i] * 0.0625f;
            const __half* base = Ph + ((size_t)(b * HH + hh) * SS + i) * SS
                                   + blk * 32 + hf * 16;
            v0[u] = *(const uint4*)base;
            v1[u] = *(const uint4*)(base + 8);
        }
#pragma unroll
        for (int u = 0; u < 4; ++u) {
            const uint32_t* vv = (const uint32_t*)&v0[u];
#pragma unroll
            for (int q = 0; q < 4; ++q) {
                float2 f = __half22float2(*(const __half2*)&vv[q]);
                acc[2 * q]     = fmaf(w[u], f.x, acc[2 * q]);
                acc[2 * q + 1] = fmaf(w[u], f.y, acc[2 * q + 1]);
            }
            const uint32_t* vw = (const uint32_t*)&v1[u];
#pragma unroll
            for (int q = 0; q < 4; ++q) {
                float2 f = __half22float2(*(const __half2*)&vw[q]);
                acc[8 + 2 * q]     = fmaf(w[u], f.x, acc[8 + 2 * q]);
                acc[8 + 2 * q + 1] = fmaf(w[u], f.y, acc[8 + 2 * q + 1]);
            }
        }
    }

    // unpermute within half-block (same map as R14)
    float* op = om + (size_t)(b * SS + i) * SS + blk * 32 + hf * 4;
    *(float4*)&op[0]  = make_float4(acc[0], acc[1], acc[8],  acc[9]);
    *(float4*)&op[8]  = make_float4(acc[2], acc[3], acc[10], acc[11]);
    *(float4*)&op[16] = make_float4(acc[4], acc[5], acc[12], acc[13]);
    *(float4*)&op[24] = make_float4(acc[6], acc[7], acc[14], acc[15]);
}

// ---------------- launch ----------------
extern "C" void kernel_launch(void* const* d_in, const int* in_sizes, int n_in,
                              void* d_out, int out_size)
{
    const float* x   = (const float*)d_in[0];
    const float* sf  = (const float*)d_in[1];
    const float* Wq  = (const float*)d_in[2];
    const float* bq  = (const float*)d_in[3];
    const float* Wk  = (const float*)d_in[4];
    const float* bk  = (const float*)d_in[5];
    const float* Wv  = (const float*)d_in[6];
    const float* bv  = (const float*)d_in[7];
    const float* Ws1 = (const float*)d_in[8];
    const float* bs1 = (const float*)d_in[9];
    const float* Ws2 = (const float*)d_in[10];
    const float* bs2 = (const float*)d_in[11];
    const float* Wo  = (const float*)d_in[12];
    const float* bo  = (const float*)d_in[13];
    float* out = (float*)d_out;

    __half *pXh, *pW3, *pWho, *pQKV, *pCh, *pPh;
    float *pb3;
    cudaGetSymbolAddress((void**)&pXh, g_Xh);
    cudaGetSymbolAddress((void**)&pW3, g_W3);
    cudaGetSymbolAddress((void**)&pWho, g_Who);
    cudaGetSymbolAddress((void**)&pb3, g_b3);
    cudaGetSymbolAddress((void**)&pQKV, g_QKV);
    cudaGetSymbolAddress((void**)&pCh, g_CTXh);
    cudaGetSymbolAddress((void**)&pPh, g_Ph);

    // 0. prep: conversions + interleave + gate + bias combine
    prep<<<1 + 4096 + 3072 + 1024, 256>>>(x, Wq, Wk, Wv, Wo, bq, bk, bv,
                                          sf, Ws1, bs1, Ws2, bs2);

    // 1. fused QKV projection: [4096,1024] @ [1024,3072], BK=64
    cudaFuncSetAttribute(gemm_qkv64, cudaFuncAttributeMaxDynamicSharedMemorySize, QK_SMEM);
    gemm_qkv64<<<dim3(N3 / 128, (BB * SS) / 128), 256, QK_SMEM>>>(pXh, pW3, pb3, pQKV);

    // 2. fused attention: quarter-pipelined, permuted p~ store
    cudaFuncSetAttribute(attn_fused, cudaFuncAttributeMaxDynamicSharedMemorySize, FA_SMEM);
    attn_fused<<<dim3(SS / 128, BB * HH), 256, FA_SMEM>>>(pQKV, pPh, pCh);

    // 3. tail: out-proj GEMM (512 blocks) || head-mean (2048 blocks)
    tail_kernel<<<512 + (BB * SS) / 2, 256>>>(pCh, pWho, bo, out, pPh,
                                              out + (size_t)BB * SS * EE);

    (void)in_sizes; (void)n_in; (void)out_size;
}

// round 16
// speedup vs baseline: 2.2506x; 1.0218x over previous
#include <cuda_runtime.h>
#include <cuda_fp16.h>
#include <cstdint>
#include <cstddef>

#define BB 2
#define SS 2048
#define EE 1024
#define HH 16
#define HID 256
#define N3 3072

// ---------------- scratch (device globals: allocation-free) ----------------
__device__ __half g_Xh[(size_t)BB * SS * EE];
__device__ __half g_W3[(size_t)EE * N3];        // interleaved [k][Wq|Wk|Wv]
__device__ __half g_Who[(size_t)EE * EE];
__device__ float  g_b3[N3];
__device__ __half g_QKV[(size_t)BB * SS * N3];  // [b,s][q|k|v]
__device__ __half g_CTXh[(size_t)BB * SS * EE];
// p~ stored in PERMUTED block-32 layout (see R12-R15 map)
__device__ __half g_Ph[(size_t)BB * HH * SS * SS];
__device__ float  g_invZ[(size_t)BB * HH * SS];
__device__ float  g_gate[BB * HH];
__device__ int    g_done[32];                   // per 128-row global tile

// ---------------- helpers ----------------
__device__ __forceinline__ float ex2(float x) {
    float r; asm("ex2.approx.f32 %0, %1;" : "=f"(r) : "f"(x)); return r;
}

__device__ __forceinline__ void mma_f16(float* d, const uint32_t* a, const uint32_t* b) {
    asm volatile("mma.sync.aligned.m16n8k16.row.col.f32.f16.f16.f32 "
                 "{%0,%1,%2,%3}, {%4,%5,%6,%7}, {%8,%9}, {%0,%1,%2,%3};"
                 : "+f"(d[0]), "+f"(d[1]), "+f"(d[2]), "+f"(d[3])
                 : "r"(a[0]), "r"(a[1]), "r"(a[2]), "r"(a[3]),
                   "r"(b[0]), "r"(b[1]));
}

__device__ __forceinline__ void ldsm_x4(uint32_t* r, uint32_t addr) {
    asm volatile("ldmatrix.sync.aligned.m8n8.x4.shared.b16 {%0,%1,%2,%3}, [%4];"
                 : "=r"(r[0]), "=r"(r[1]), "=r"(r[2]), "=r"(r[3]) : "r"(addr));
}
__device__ __forceinline__ void ldsm_x4_t(uint32_t* r, uint32_t addr) {
    asm volatile("ldmatrix.sync.aligned.m8n8.x4.trans.shared.b16 {%0,%1,%2,%3}, [%4];"
                 : "=r"(r[0]), "=r"(r[1]), "=r"(r[2]), "=r"(r[3]) : "r"(addr));
}

__device__ __forceinline__ void cp_async16(uint32_t smem, const void* g) {
    asm volatile("cp.async.cg.shared.global [%0], [%1], 16;" :: "r"(smem), "l"(g));
}
__device__ __forceinline__ void cp_commit() { asm volatile("cp.async.commit_group;"); }
__device__ __forceinline__ void cp_wait0()  { asm volatile("cp.async.wait_group 0;"); }
__device__ __forceinline__ void cp_wait1()  { asm volatile("cp.async.wait_group 1;"); }

__device__ __forceinline__ uint32_t h2u(__half2 h) { return *(uint32_t*)&h; }

// ================= prep: f2h conversions + gate + bias + flag reset =========
__global__ __launch_bounds__(256)
void prep(const float* __restrict__ x,
          const float* __restrict__ Wq, const float* __restrict__ Wk,
          const float* __restrict__ Wv, const float* __restrict__ Wo,
          const float* __restrict__ bq, const float* __restrict__ bk,
          const float* __restrict__ bv,
          const float* __restrict__ sf,
          const float* __restrict__ Ws1, const float* __restrict__ bs1,
          const float* __restrict__ Ws2, const float* __restrict__ bs2)
{
    const int bid = blockIdx.x, tid = threadIdx.x;
    if (bid == 0) {
        __shared__ float h1[BB][HID];
        if (tid < 32) g_done[tid] = 0;
        for (int b = 0; b < BB; ++b) {
            float acc = bs1[tid];
            for (int e = 0; e < EE; ++e)
                acc += sf[b * EE + e] * Ws1[(size_t)e * HID + tid];
            h1[b][tid] = fmaxf(acc, 0.0f);
        }
        __syncthreads();
        if (tid < BB * HH) {
            int b = tid / HH, h = tid % HH;
            float acc = bs2[h];
            for (int k = 0; k < HID; ++k)
                acc += h1[b][k] * Ws2[k * HH + h];
            g_gate[b * HH + h] = (1.0f / (1.0f + __expf(-acc))) * 0.125f;
        }
        for (int i = tid; i < EE; i += 256) {
            g_b3[i] = bq[i]; g_b3[EE + i] = bk[i]; g_b3[2 * EE + i] = bv[i];
        }
        return;
    }
    int t = (bid - 1) * 256 + tid;
    if (t < 1048576) {                    // X: 4M floats
        float4 v = ((const float4*)x)[t];
        ((__half2*)g_Xh)[2 * t]     = __floats2half2_rn(v.x, v.y);
        ((__half2*)g_Xh)[2 * t + 1] = __floats2half2_rn(v.z, v.w);
        return;
    }
    t -= 1048576;
    if (t < 3 * 262144) {                 // Wq/Wk/Wv interleave into [k][3N]
        int which = t / 262144;
        int u = t - which * 262144;
        const float* W = (which == 0) ? Wq : ((which == 1) ? Wk : Wv);
        float4 v = ((const float4*)W)[u];
        int k = u >> 8, n4 = u & 255;
        size_t d = (size_t)k * N3 + which * EE + n4 * 4;
        *(__half2*)&g_W3[d]     = __floats2half2_rn(v.x, v.y);
        *(__half2*)&g_W3[d + 2] = __floats2half2_rn(v.z, v.w);
        return;
    }
    t -= 3 * 262144;
    if (t < 262144) {                     // Wo
        float4 v = ((const float4*)Wo)[t];
        ((__half2*)g_Who)[2 * t]     = __floats2half2_rn(v.x, v.y);
        ((__half2*)g_Who)[2 * t + 1] = __floats2half2_rn(v.z, v.w);
    }
}

// ---------------- QKV GEMM: 128x128x64 tiles, dynamic smem ----------------
#define QK_SA 72
#define QK_SB 136
#define QK_ABYTES (128 * QK_SA * 2)
#define QK_BBYTES (64 * QK_SB * 2)
#define QK_SMEM (2 * QK_ABYTES + 2 * QK_BBYTES)

__global__ __launch_bounds__(256, 2)
void gemm_qkv64(const __half* __restrict__ Xh, const __half* __restrict__ W3,
                const float* __restrict__ b3, __half* __restrict__ QKV)
{
    extern __shared__ __half dsm[];
    const uint32_t base = (uint32_t)__cvta_generic_to_shared(dsm);
    const uint32_t AsB[2] = { base, base + QK_ABYTES };
    const uint32_t BsB[2] = { base + 2 * QK_ABYTES, base + 2 * QK_ABYTES + QK_BBYTES };

    const int tid = threadIdx.x;
    const int lane = tid & 31, warp = tid >> 5;
    const int wr = warp & 1, wc = warp >> 1;
    const int lr = lane >> 2, lc = lane & 3;
    const int bm = blockIdx.y * 128, bn = blockIdx.x * 128;

    auto issue = [&](int kt, int buf) {
        const int k0 = kt * 64;
#pragma unroll
        for (int i = 0; i < 4; ++i) {
            int id = tid + i * 256;
            int ar = id >> 3, ac = id & 7;
            cp_async16(AsB[buf] + (uint32_t)((ar * QK_SA + ac * 8) * 2),
                       Xh + (size_t)(bm + ar) * EE + k0 + ac * 8);
            int br = id >> 4, bc = id & 15;
            cp_async16(BsB[buf] + (uint32_t)((br * QK_SB + bc * 8) * 2),
                       W3 + (size_t)(k0 + br) * N3 + bn + bc * 8);
        }
        cp_commit();
    };

    float acc[4][4][4];
#pragma unroll
    for (int i = 0; i < 4; ++i)
#pragma unroll
        for (int j = 0; j < 4; ++j)
#pragma unroll
            for (int r = 0; r < 4; ++r) acc[i][j][r] = 0.0f;

    const int a_row_l = wr * 64 + (lane & 15);
    const int a_koff = (lane >> 4) * 8;
    const int b_krow = (lane & 7) + ((lane >> 3) & 1) * 8;
    const int b_noff = (lane >> 4) * 8;

    const int nk = EE / 64;   // 16
    issue(0, 0);

    for (int kt = 0; kt < nk; ++kt) {
        const int buf = kt & 1;
        if (kt + 1 < nk) { issue(kt + 1, buf ^ 1); cp_wait1(); }
        else cp_wait0();
        __syncthreads();

#pragma unroll
        for (int ks = 0; ks < 4; ++ks) {
            const int k0 = ks * 16;
            uint32_t af[4][4], bf[4][2];
#pragma unroll
            for (int mf = 0; mf < 4; ++mf)
                ldsm_x4(af[mf], AsB[buf] +
                        (uint32_t)(((a_row_l + mf * 16) * QK_SA + k0 + a_koff) * 2));
#pragma unroll
            for (int np = 0; np < 2; ++np) {
                uint32_t r4[4];
                int n0 = wc * 32 + np * 16;
                ldsm_x4_t(r4, BsB[buf] +
                          (uint32_t)(((k0 + b_krow) * QK_SB + n0 + b_noff) * 2));
                bf[np * 2][0] = r4[0]; bf[np * 2][1] = r4[1];
                bf[np * 2 + 1][0] = r4[2]; bf[np * 2 + 1][1] = r4[3];
            }
#pragma unroll
            for (int mf = 0; mf < 4; ++mf)
#pragma unroll
                for (int nf = 0; nf < 4; ++nf)
                    mma_f16(acc[mf][nf], af[mf], bf[nf]);
        }
        __syncthreads();
    }

#pragma unroll
    for (int nf = 0; nf < 4; ++nf) {
        int col = bn + wc * 32 + nf * 8 + lc * 2;
        float b0 = b3[col], b1 = b3[col + 1];
#pragma unroll
        for (int mf = 0; mf < 4; ++mf) {
            int row = bm + wr * 64 + mf * 16 + lr;
            *(__half2*)&QKV[(size_t)row * N3 + col] =
                __floats2half2_rn(acc[mf][nf][0] + b0, acc[mf][nf][1] + b1);
            *(__half2*)&QKV[(size_t)(row + 8) * N3 + col] =
                __floats2half2_rn(acc[mf][nf][2] + b0, acc[mf][nf][3] + b1);
        }
    }
}

// ===== merged attention + tail: flag-gated grid-partition fusion ============
// blocks [0,512): attn (bid = itile*32 + bh -> tiles complete in order)
// blocks [512,1024): out-proj GEMM 128x64 (waits on its row tile)
// blocks [1024,3072): head-mean (waits on its row tile)
#define FA_ST 72
#define FA_SMEM (5 * 128 * FA_ST * 2)

__global__ __launch_bounds__(256, 2)
void attn_tail(const __half* __restrict__ QKV, __half* __restrict__ Ph,
               __half* __restrict__ Ch,
               const __half* __restrict__ Who, const float* __restrict__ bo,
               float* __restrict__ out, float* __restrict__ om)
{
    extern __shared__ __half sm[];
    const int bid = blockIdx.x;
    const int tid = threadIdx.x;

    if (bid < 512) {
        // ================= attn producer =================
        const uint32_t QsB  = (uint32_t)__cvta_generic_to_shared(sm);
        const uint32_t KsB[2] = { QsB + 128 * FA_ST * 2, QsB + 2 * 128 * FA_ST * 2 };
        const uint32_t VsB[2] = { QsB + 3 * 128 * FA_ST * 2, QsB + 4 * 128 * FA_ST * 2 };

        const int lane = tid & 31, warp = tid >> 5;
        const int lr = lane >> 2, lc = lane & 3;
        const int itile = bid >> 5, bh = bid & 31;
        const int b = bh >> 4, h = bh & 15;
        const int mi = itile * 128;
        const int rt = b * 16 + itile;      // global 128-row tile id

#pragma unroll
        for (int i = 0; i < 4; ++i) {
            int c = tid + i * 256;
            int row = c >> 3, ch = c & 7;
            cp_async16(QsB + (uint32_t)((row * FA_ST + ch * 8) * 2),
                       QKV + (size_t)(b * SS + mi + row) * N3 + h * 64 + ch * 8);
        }
        cp_commit();

        auto issueKV = [&](int jt, int buf) {
#pragma unroll
            for (int i = 0; i < 4; ++i) {
                int c = tid + i * 256;
                int row = c >> 3, ch = c & 7;
                size_t base = (size_t)(b * SS + jt * 128 + row) * N3 + h * 64 + ch * 8;
                cp_async16(KsB[buf] + (uint32_t)((row * FA_ST + ch * 8) * 2),
                           QKV + base + 1024);
                cp_async16(VsB[buf] + (uint32_t)((row * FA_ST + ch * 8) * 2),
                           QKV + base + 2048);
            }
            cp_commit();
        };
        issueKV(0, 0);

        const float g2 = g_gate[bh] * 1.4426950408889634f;
        const float C8 = -11.541560327111708f;

        const int a_row  = warp * 16 + (lane & 15);
        const int a_koff = (lane >> 4) * 8;
        const int b1_nrow = (lane & 7) + (lane >> 4) * 8;
        const int b1_koff = ((lane >> 3) & 1) * 8;
        const int b2_krow = (lane & 7) + ((lane >> 3) & 1) * 8;
        const int b2_noff = (lane >> 4) * 8;

        cp_wait1();
        __syncthreads();
        uint32_t qf[4][4];
#pragma unroll
        for (int ks = 0; ks < 4; ++ks)
            ldsm_x4(qf[ks], QsB + (uint32_t)((a_row * FA_ST + ks * 16 + a_koff) * 2));

        float ctx[8][4];
#pragma unroll
        for (int i = 0; i < 8; ++i)
#pragma unroll
            for (int r = 0; r < 4; ++r) ctx[i][r] = 0.0f;
        float zs0 = 0.0f, zs1 = 0.0f;

        const int grow = mi + warp * 16 + lr;
        __half* Prow0 = Ph + ((size_t)bh * SS + grow) * SS;
        __half* Prow1 = Ph + ((size_t)bh * SS + grow + 8) * SS;

        auto mma1_q = [&](int buf, int q, float (&acc)[4][4]) {
#pragma unroll
            for (int i = 0; i < 4; ++i)
#pragma unroll
                for (int r = 0; r < 4; ++r) acc[i][r] = 0.0f;
#pragma unroll
            for (int ks = 0; ks < 4; ++ks)
#pragma unroll
                for (int np = 0; np < 2; ++np) {
                    uint32_t r4[4];
                    ldsm_x4(r4, KsB[buf] +
                            (uint32_t)(((q * 32 + np * 16 + b1_nrow) * FA_ST +
                                        ks * 16 + b1_koff) * 2));
                    mma_f16(acc[np * 2], qf[ks], r4);
                    mma_f16(acc[np * 2 + 1], qf[ks], r4 + 2);
                }
        };

        auto epi_q = [&](int buf, int jt, int q, float (&acc)[4][4]) {
            uint32_t r0v[4], r1v[4];
#pragma unroll
            for (int np = 0; np < 2; ++np) {
                float pa0 = ex2(fmaf(acc[np * 2][0], g2, C8));
                float pa1 = ex2(fmaf(acc[np * 2][1], g2, C8));
                float pb0 = ex2(fmaf(acc[np * 2][2], g2, C8));
                float pb1 = ex2(fmaf(acc[np * 2][3], g2, C8));
                float pc0 = ex2(fmaf(acc[np * 2 + 1][0], g2, C8));
                float pc1 = ex2(fmaf(acc[np * 2 + 1][1], g2, C8));
                float pd0 = ex2(fmaf(acc[np * 2 + 1][2], g2, C8));
                float pd1 = ex2(fmaf(acc[np * 2 + 1][3], g2, C8));
                __half2 wa = __floats2half2_rn(pa0, pa1);
                __half2 wb = __floats2half2_rn(pb0, pb1);
                __half2 wc2 = __floats2half2_rn(pc0, pc1);
                __half2 wd = __floats2half2_rn(pd0, pd1);
                zs0 += (pa0 + pa1) + (pc0 + pc1);
                zs1 += (pb0 + pb1) + (pd0 + pd1);
                r0v[np * 2] = h2u(wa); r0v[np * 2 + 1] = h2u(wc2);
                r1v[np * 2] = h2u(wb); r1v[np * 2 + 1] = h2u(wd);

                uint32_t af2[4] = { h2u(wa), h2u(wb), h2u(wc2), h2u(wd) };
#pragma unroll
                for (int n2 = 0; n2 < 4; ++n2) {
                    uint32_t r4[4];
                    ldsm_x4_t(r4, VsB[buf] +
                              (uint32_t)(((q * 32 + np * 16 + b2_krow) * FA_ST +
                                          n2 * 16 + b2_noff) * 2));
                    mma_f16(ctx[n2 * 2], af2, r4);
                    mma_f16(ctx[n2 * 2 + 1], af2, r4 + 2);
                }
            }
            int poff = jt * 128 + q * 32 + 8 * lc;
            *(uint4*)&Prow0[poff] = make_uint4(r0v[0], r0v[1], r0v[2], r0v[3]);
            *(uint4*)&Prow1[poff] = make_uint4(r1v[0], r1v[1], r1v[2], r1v[3]);
        };

        for (int jt = 0; jt < 16; ++jt) {
            const int buf = jt & 1;
            if (jt + 1 < 16) { issueKV(jt + 1, buf ^ 1); cp_wait1(); }
            else cp_wait0();
            __syncthreads();

            float accA[4][4], accB[4][4];
            mma1_q(buf, 0, accA);
            mma1_q(buf, 1, accB);
            epi_q(buf, jt, 0, accA);
            mma1_q(buf, 2, accA);
            epi_q(buf, jt, 1, accB);
            mma1_q(buf, 3, accB);
            epi_q(buf, jt, 2, accA);
            epi_q(buf, jt, 3, accB);

            __syncthreads();
        }

        zs0 += __shfl_xor_sync(0xffffffffu, zs0, 1);
        zs0 += __shfl_xor_sync(0xffffffffu, zs0, 2);
        zs1 += __shfl_xor_sync(0xffffffffu, zs1, 1);
        zs1 += __shfl_xor_sync(0xffffffffu, zs1, 2);
        float iz0 = 1.0f / zs0, iz1 = 1.0f / zs1;
        if (lc == 0) {
            g_invZ[(size_t)bh * SS + grow]     = iz0;
            g_invZ[(size_t)bh * SS + grow + 8] = iz1;
        }

        __half* Cc = Ch + (size_t)b * SS * EE + h * 64;
#pragma unroll
        for (int np = 0; np < 8; ++np) {
            int n = np * 8 + 2 * lc;
            *(__half2*)&Cc[(size_t)grow * EE + n] =
                __floats2half2_rn(ctx[np][0] * iz0, ctx[np][1] * iz0);
            *(__half2*)&Cc[(size_t)(grow + 8) * EE + n] =
                __floats2half2_rn(ctx[np][2] * iz1, ctx[np][3] * iz1);
        }

        __syncthreads();
        if (tid == 0) {
            __threadfence();
            atomicAdd(&g_done[rt], 1);
        }
        return;
    }

    if (bid < 1024) {
        // ================= out-proj GEMM 128x64 (flag-gated) =================
        const int gid = bid - 512;
        const int by = gid >> 4, bx = gid & 15;

        if (tid == 0) {
            while (atomicAdd(&g_done[by], 0) < 16) __nanosleep(200);
        }
        __syncthreads();
        __threadfence();

        constexpr int SA = 40;
        constexpr int SB = 72;
        const uint32_t base = (uint32_t)__cvta_generic_to_shared(sm);
        const uint32_t AsB[2] = { base, base + 128 * SA * 2 };
        const uint32_t BsB[2] = { base + 2 * 128 * SA * 2,
                                  base + 2 * 128 * SA * 2 + 32 * SB * 2 };

        const int lane = tid & 31, warp = tid >> 5;
        const int wr = warp & 3, wc = warp >> 2;
        const int lr = lane >> 2, lc = lane & 3;
        const int bm = by * 128, bn = bx * 64;

        const int arow0 = tid >> 2, ach0 = tid & 3;
        const int brow = tid >> 3, bch = tid & 7;

        auto issue = [&](int kt, int buf) {
            cp_async16(AsB[buf] + (uint32_t)((arow0 * SA + ach0 * 8) * 2),
                       Ch + (size_t)(bm + arow0) * EE + kt * 32 + ach0 * 8);
            cp_async16(AsB[buf] + (uint32_t)(((arow0 + 64) * SA + ach0 * 8) * 2),
                       Ch + (size_t)(bm + arow0 + 64) * EE + kt * 32 + ach0 * 8);
            cp_async16(BsB[buf] + (uint32_t)((brow * SB + bch * 8) * 2),
                       Who + (size_t)(kt * 32 + brow) * EE + bn + bch * 8);
            cp_commit();
        };

        float acc[2][4][4];
#pragma unroll
        for (int i = 0; i < 2; ++i)
#pragma unroll
            for (int j = 0; j < 4; ++j)
#pragma unroll
                for (int r = 0; r < 4; ++r) acc[i][j][r] = 0.0f;

        const int a_row_l = wr * 32 + (lane & 15);
        const int a_koff = (lane >> 4) * 8;
        const int b_krow = (lane & 7) + ((lane >> 3) & 1) * 8;
        const int b_noff = (lane >> 4) * 8;

        const int nk = EE / 32;
        issue(0, 0);

        for (int kt = 0; kt < nk; ++kt) {
            const int buf = kt & 1;
            if (kt + 1 < nk) { issue(kt + 1, buf ^ 1); cp_wait1(); }
            else cp_wait0();
            __syncthreads();

#pragma unroll
            for (int ks = 0; ks < 2; ++ks) {
                const int k0 = ks * 16;
                uint32_t af[2][4], bf[4][2];
#pragma unroll
                for (int mf = 0; mf < 2; ++mf)
                    ldsm_x4(af[mf], AsB[buf] +
                            (uint32_t)(((a_row_l + mf * 16) * SA + k0 + a_koff) * 2));
#pragma unroll
                for (int np = 0; np < 2; ++np) {
                    uint32_t r4[4];
                    int n0 = wc * 32 + np * 16;
                    ldsm_x4_t(r4, BsB[buf] +
                              (uint32_t)(((k0 + b_krow) * SB + n0 + b_noff) * 2));
                    bf[np * 2][0] = r4[0]; bf[np * 2][1] = r4[1];
                    bf[np * 2 + 1][0] = r4[2]; bf[np * 2 + 1][1] = r4[3];
                }
#pragma unroll
                for (int mf = 0; mf < 2; ++mf)
#pragma unroll
                    for (int nf = 0; nf < 4; ++nf)
                        mma_f16(acc[mf][nf], af[mf], bf[nf]);
            }
            __syncthreads();
        }

#pragma unroll
        for (int nf = 0; nf < 4; ++nf) {
            int col = bn + wc * 32 + nf * 8 + lc * 2;
            float b0 = bo[col], b1 = bo[col + 1];
#pragma unroll
            for (int mf = 0; mf < 2; ++mf) {
                int row = bm + wr * 32 + mf * 16 + lr;
                *(float2*)&out[(size_t)row * EE + col] =
                    make_float2(acc[mf][nf][0] + b0, acc[mf][nf][1] + b1);
                *(float2*)&out[(size_t)(row + 8) * EE + col] =
                    make_float2(acc[mf][nf][2] + b0, acc[mf][nf][3] + b1);
            }
        }
        return;
    }

    // ================= head-mean (flag-gated) =================
    {
        const int mid = bid - 1024;               // 0..2047
        const int rt = mid >> 6;                  // 64 mean blocks per row tile
        if (tid == 0) {
            while (atomicAdd(&g_done[rt], 0) < 16) __nanosleep(200);
        }
        __syncthreads();
        __threadfence();

        const int grow = mid * 2 + (tid >> 7);
        const int b = grow >> 11, i = grow & (SS - 1);
        const int j = tid & 127;
        const int blk = j >> 1, hf = j & 1;

        float acc[16];
#pragma unroll
        for (int s = 0; s < 16; ++s) acc[s] = 0.0f;

#pragma unroll
        for (int h4 = 0; h4 < HH; h4 += 4) {
            float w[4];
            uint4 v0[4], v1[4];
#pragma unroll
            for (int u = 0; u < 4; ++u) {
                const int hh = h4 + u;
                w[u] = g_invZ[(size_t)(b * HH + hh) * SS + i] * 0.0625f;
                const __half* base = Ph + ((size_t)(b * HH + hh) * SS + i) * SS
                                       + blk * 32 + hf * 16;
                v0[u] = *(const uint4*)base;
                v1[u] = *(const uint4*)(base + 8);
            }
#pragma unroll
            for (int u = 0; u < 4; ++u) {
                const uint32_t* vv = (const uint32_t*)&v0[u];
#pragma unroll
                for (int q = 0; q < 4; ++q) {
                    float2 f = __half22float2(*(const __half2*)&vv[q]);
                    acc[2 * q]     = fmaf(w[u], f.x, acc[2 * q]);
                    acc[2 * q + 1] = fmaf(w[u], f.y, acc[2 * q + 1]);
                }
                const uint32_t* vw = (const uint32_t*)&v1[u];
#pragma unroll
                for (int q = 0; q < 4; ++q) {
                    float2 f = __half22float2(*(const __half2*)&vw[q]);
                    acc[8 + 2 * q]     = fmaf(w[u], f.x, acc[8 + 2 * q]);
                    acc[8 + 2 * q + 1] = fmaf(w[u], f.y, acc[8 + 2 * q + 1]);
                }
            }
        }

        float* op = om + (size_t)(b * SS + i) * SS + blk * 32 + hf * 4;
        *(float4*)&op[0]  = make_float4(acc[0], acc[1], acc[8],  acc[9]);
        *(float4*)&op[8]  = make_float4(acc[2], acc[3], acc[10], acc[11]);
        *(float4*)&op[16] = make_float4(acc[4], acc[5], acc[12], acc[13]);
        *(float4*)&op[24] = make_float4(acc[6], acc[7], acc[14], acc[15]);
    }
}

// ---------------- launch ----------------
extern "C" void kernel_launch(void* const* d_in, const int* in_sizes, int n_in,
                              void* d_out, int out_size)
{
    const float* x   = (const float*)d_in[0];
    const float* sf  = (const float*)d_in[1];
    const float* Wq  = (const float*)d_in[2];
    const float* bq  = (const float*)d_in[3];
    const float* Wk  = (const float*)d_in[4];
    const float* bk  = (const float*)d_in[5];
    const float* Wv  = (const float*)d_in[6];
    const float* bv  = (const float*)d_in[7];
    const float* Ws1 = (const float*)d_in[8];
    const float* bs1 = (const float*)d_in[9];
    const float* Ws2 = (const float*)d_in[10];
    const float* bs2 = (const float*)d_in[11];
    const float* Wo  = (const float*)d_in[12];
    const float* bo  = (const float*)d_in[13];
    float* out = (float*)d_out;

    __half *pXh, *pW3, *pWho, *pQKV, *pCh, *pPh;
    float *pb3;
    cudaGetSymbolAddress((void**)&pXh, g_Xh);
    cudaGetSymbolAddress((void**)&pW3, g_W3);
    cudaGetSymbolAddress((void**)&pWho, g_Who);
    cudaGetSymbolAddress((void**)&pb3, g_b3);
    cudaGetSymbolAddress((void**)&pQKV, g_QKV);
    cudaGetSymbolAddress((void**)&pCh, g_CTXh);
    cudaGetSymbolAddress((void**)&pPh, g_Ph);

    // 0. prep: conversions + interleave + gate + bias + flag reset
    prep<<<1 + 4096 + 3072 + 1024, 256>>>(x, Wq, Wk, Wv, Wo, bq, bk, bv,
                                          sf, Ws1, bs1, Ws2, bs2);

    // 1. fused QKV projection: [4096,1024] @ [1024,3072], BK=64
    cudaFuncSetAttribute(gemm_qkv64, cudaFuncAttributeMaxDynamicSharedMemorySize, QK_SMEM);
    gemm_qkv64<<<dim3(N3 / 128, (BB * SS) / 128), 256, QK_SMEM>>>(pXh, pW3, pb3, pQKV);

    // 2. merged attention + tail (flag-gated fine-grained dependencies)
    cudaFuncSetAttribute(attn_tail, cudaFuncAttributeMaxDynamicSharedMemorySize, FA_SMEM);
    attn_tail<<<512 + 512 + 2048, 256, FA_SMEM>>>(pQKV, pPh, pCh, pWho, bo, out,
                                                  out + (size_t)BB * SS * EE);

    (void)in_sizes; (void)n_in; (void)out_size;
}

// round 17
// speedup vs baseline: 2.2747x; 1.0107x over previous
#include <cuda_runtime.h>
#include <cuda_fp16.h>
#include <cstdint>
#include <cstddef>

#define BB 2
#define SS 2048
#define EE 1024
#define HH 16
#define HID 256
#define N3 3072

// ---------------- scratch (device globals: allocation-free) ----------------
__device__ __half g_Xh[(size_t)BB * SS * EE];
__device__ __half g_W3[(size_t)EE * N3];        // interleaved [k][Wq|Wk|Wv]
__device__ __half g_Who[(size_t)EE * EE];
__device__ float  g_b3[N3];
__device__ __half g_QKV[(size_t)BB * SS * N3];  // [b,s][q|k|v]
__device__ __half g_CTXh[(size_t)BB * SS * EE];
// p~ stored in PERMUTED block-32 layout (see R12-R15 map)
__device__ __half g_Ph[(size_t)BB * HH * SS * SS];
__device__ float  g_invZ[(size_t)BB * HH * SS];
__device__ float  g_gate[BB * HH];
__device__ int    g_done[32];                   // per 128-row global tile

// ---------------- helpers ----------------
__device__ __forceinline__ float ex2(float x) {
    float r; asm("ex2.approx.f32 %0, %1;" : "=f"(r) : "f"(x)); return r;
}

__device__ __forceinline__ void mma_f16(float* d, const uint32_t* a, const uint32_t* b) {
    asm volatile("mma.sync.aligned.m16n8k16.row.col.f32.f16.f16.f32 "
                 "{%0,%1,%2,%3}, {%4,%5,%6,%7}, {%8,%9}, {%0,%1,%2,%3};"
                 : "+f"(d[0]), "+f"(d[1]), "+f"(d[2]), "+f"(d[3])
                 : "r"(a[0]), "r"(a[1]), "r"(a[2]), "r"(a[3]),
                   "r"(b[0]), "r"(b[1]));
}

__device__ __forceinline__ void ldsm_x4(uint32_t* r, uint32_t addr) {
    asm volatile("ldmatrix.sync.aligned.m8n8.x4.shared.b16 {%0,%1,%2,%3}, [%4];"
                 : "=r"(r[0]), "=r"(r[1]), "=r"(r[2]), "=r"(r[3]) : "r"(addr));
}
__device__ __forceinline__ void ldsm_x4_t(uint32_t* r, uint32_t addr) {
    asm volatile("ldmatrix.sync.aligned.m8n8.x4.trans.shared.b16 {%0,%1,%2,%3}, [%4];"
                 : "=r"(r[0]), "=r"(r[1]), "=r"(r[2]), "=r"(r[3]) : "r"(addr));
}

__device__ __forceinline__ void cp_async16(uint32_t smem, const void* g) {
    asm volatile("cp.async.cg.shared.global [%0], [%1], 16;" :: "r"(smem), "l"(g));
}
__device__ __forceinline__ void cp_commit() { asm volatile("cp.async.commit_group;"); }
__device__ __forceinline__ void cp_wait0()  { asm volatile("cp.async.wait_group 0;"); }
__device__ __forceinline__ void cp_wait1()  { asm volatile("cp.async.wait_group 1;"); }

__device__ __forceinline__ uint32_t h2u(__half2 h) { return *(uint32_t*)&h; }

// ================= prep: f2h conversions + gate + bias + flag reset =========
__global__ __launch_bounds__(256)
void prep(const float* __restrict__ x,
          const float* __restrict__ Wq, const float* __restrict__ Wk,
          const float* __restrict__ Wv, const float* __restrict__ Wo,
          const float* __restrict__ bq, const float* __restrict__ bk,
          const float* __restrict__ bv,
          const float* __restrict__ sf,
          const float* __restrict__ Ws1, const float* __restrict__ bs1,
          const float* __restrict__ Ws2, const float* __restrict__ bs2)
{
    const int bid = blockIdx.x, tid = threadIdx.x;
    if (bid == 0) {
        __shared__ float sfs[BB * EE];      // 8 KB
        __shared__ float h1[BB][HID];
        if (tid < 32) g_done[tid] = 0;
        // stage sync_features coalesced
#pragma unroll
        for (int i = 0; i < (BB * EE) / (256 * 4); ++i) {
            int idx = tid + i * 256;
            ((float4*)sfs)[idx] = ((const float4*)sf)[idx];
        }
        __syncthreads();
        // h1[b][tid] = relu(bs1 + sum_e sf[b][e]*Ws1[e][tid]) with MLP-16 loop
        for (int b = 0; b < BB; ++b) {
            float a0 = 0.0f, a1 = 0.0f, a2 = 0.0f, a3 = 0.0f;
#pragma unroll 4
            for (int e = 0; e < EE; e += 4) {
                a0 = fmaf(sfs[b * EE + e],     Ws1[(size_t)e * HID + tid], a0);
                a1 = fmaf(sfs[b * EE + e + 1], Ws1[(size_t)(e + 1) * HID + tid], a1);
                a2 = fmaf(sfs[b * EE + e + 2], Ws1[(size_t)(e + 2) * HID + tid], a2);
                a3 = fmaf(sfs[b * EE + e + 3], Ws1[(size_t)(e + 3) * HID + tid], a3);
            }
            h1[b][tid] = fmaxf(bs1[tid] + ((a0 + a1) + (a2 + a3)), 0.0f);
        }
        __syncthreads();
        if (tid < BB * HH) {
            int b = tid / HH, h = tid % HH;
            float a0 = 0.0f, a1 = 0.0f;
#pragma unroll 4
            for (int k = 0; k < HID; k += 2) {
                a0 = fmaf(h1[b][k],     Ws2[k * HH + h], a0);
                a1 = fmaf(h1[b][k + 1], Ws2[(k + 1) * HH + h], a1);
            }
            float acc = bs2[h] + a0 + a1;
            g_gate[b * HH + h] = (1.0f / (1.0f + __expf(-acc))) * 0.125f;
        }
        for (int i = tid; i < EE; i += 256) {
            g_b3[i] = bq[i]; g_b3[EE + i] = bk[i]; g_b3[2 * EE + i] = bv[i];
        }
        return;
    }
    int t = (bid - 1) * 256 + tid;
    if (t < 1048576) {                    // X: 4M floats
        float4 v = ((const float4*)x)[t];
        ((__half2*)g_Xh)[2 * t]     = __floats2half2_rn(v.x, v.y);
        ((__half2*)g_Xh)[2 * t + 1] = __floats2half2_rn(v.z, v.w);
        return;
    }
    t -= 1048576;
    if (t < 3 * 262144) {                 // Wq/Wk/Wv interleave into [k][3N]
        int which = t / 262144;
        int u = t - which * 262144;
        const float* W = (which == 0) ? Wq : ((which == 1) ? Wk : Wv);
        float4 v = ((const float4*)W)[u];
        int k = u >> 8, n4 = u & 255;
        size_t d = (size_t)k * N3 + which * EE + n4 * 4;
        *(__half2*)&g_W3[d]     = __floats2half2_rn(v.x, v.y);
        *(__half2*)&g_W3[d + 2] = __floats2half2_rn(v.z, v.w);
        return;
    }
    t -= 3 * 262144;
    if (t < 262144) {                     // Wo
        float4 v = ((const float4*)Wo)[t];
        ((__half2*)g_Who)[2 * t]     = __floats2half2_rn(v.x, v.y);
        ((__half2*)g_Who)[2 * t + 1] = __floats2half2_rn(v.z, v.w);
    }
}

// ---------------- QKV GEMM: 128x128x64 tiles, dynamic smem ----------------
#define QK_SA 72
#define QK_SB 136
#define QK_ABYTES (128 * QK_SA * 2)
#define QK_BBYTES (64 * QK_SB * 2)
#define QK_SMEM (2 * QK_ABYTES + 2 * QK_BBYTES)

__global__ __launch_bounds__(256, 2)
void gemm_qkv64(const __half* __restrict__ Xh, const __half* __restrict__ W3,
                const float* __restrict__ b3, __half* __restrict__ QKV)
{
    extern __shared__ __half dsm[];
    const uint32_t base = (uint32_t)__cvta_generic_to_shared(dsm);
    const uint32_t AsB[2] = { base, base + QK_ABYTES };
    const uint32_t BsB[2] = { base + 2 * QK_ABYTES, base + 2 * QK_ABYTES + QK_BBYTES };

    const int tid = threadIdx.x;
    const int lane = tid & 31, warp = tid >> 5;
    const int wr = warp & 1, wc = warp >> 1;
    const int lr = lane >> 2, lc = lane & 3;
    const int bm = blockIdx.y * 128, bn = blockIdx.x * 128;

    auto issue = [&](int kt, int buf) {
        const int k0 = kt * 64;
#pragma unroll
        for (int i = 0; i < 4; ++i) {
            int id = tid + i * 256;
            int ar = id >> 3, ac = id & 7;
            cp_async16(AsB[buf] + (uint32_t)((ar * QK_SA + ac * 8) * 2),
                       Xh + (size_t)(bm + ar) * EE + k0 + ac * 8);
            int br = id >> 4, bc = id & 15;
            cp_async16(BsB[buf] + (uint32_t)((br * QK_SB + bc * 8) * 2),
                       W3 + (size_t)(k0 + br) * N3 + bn + bc * 8);
        }
        cp_commit();
    };

    float acc[4][4][4];
#pragma unroll
    for (int i = 0; i < 4; ++i)
#pragma unroll
        for (int j = 0; j < 4; ++j)
#pragma unroll
            for (int r = 0; r < 4; ++r) acc[i][j][r] = 0.0f;

    const int a_row_l = wr * 64 + (lane & 15);
    const int a_koff = (lane >> 4) * 8;
    const int b_krow = (lane & 7) + ((lane >> 3) & 1) * 8;
    const int b_noff = (lane >> 4) * 8;

    const int nk = EE / 64;   // 16
    issue(0, 0);

    for (int kt = 0; kt < nk; ++kt) {
        const int buf = kt & 1;
        if (kt + 1 < nk) { issue(kt + 1, buf ^ 1); cp_wait1(); }
        else cp_wait0();
        __syncthreads();

#pragma unroll
        for (int ks = 0; ks < 4; ++ks) {
            const int k0 = ks * 16;
            uint32_t af[4][4], bf[4][2];
#pragma unroll
            for (int mf = 0; mf < 4; ++mf)
                ldsm_x4(af[mf], AsB[buf] +
                        (uint32_t)(((a_row_l + mf * 16) * QK_SA + k0 + a_koff) * 2));
#pragma unroll
            for (int np = 0; np < 2; ++np) {
                uint32_t r4[4];
                int n0 = wc * 32 + np * 16;
                ldsm_x4_t(r4, BsB[buf] +
                          (uint32_t)(((k0 + b_krow) * QK_SB + n0 + b_noff) * 2));
                bf[np * 2][0] = r4[0]; bf[np * 2][1] = r4[1];
                bf[np * 2 + 1][0] = r4[2]; bf[np * 2 + 1][1] = r4[3];
            }
#pragma unroll
            for (int mf = 0; mf < 4; ++mf)
#pragma unroll
                for (int nf = 0; nf < 4; ++nf)
                    mma_f16(acc[mf][nf], af[mf], bf[nf]);
        }
        __syncthreads();
    }

#pragma unroll
    for (int nf = 0; nf < 4; ++nf) {
        int col = bn + wc * 32 + nf * 8 + lc * 2;
        float b0 = b3[col], b1 = b3[col + 1];
#pragma unroll
        for (int mf = 0; mf < 4; ++mf) {
            int row = bm + wr * 64 + mf * 16 + lr;
            *(__half2*)&QKV[(size_t)row * N3 + col] =
                __floats2half2_rn(acc[mf][nf][0] + b0, acc[mf][nf][1] + b1);
            *(__half2*)&QKV[(size_t)(row + 8) * N3 + col] =
                __floats2half2_rn(acc[mf][nf][2] + b0, acc[mf][nf][3] + b1);
        }
    }
}

// ===== merged attention + tail: flag-gated grid-partition fusion ============
#define FA_ST 72
#define FA_SMEM (5 * 128 * FA_ST * 2)

__global__ __launch_bounds__(256, 2)
void attn_tail(const __half* __restrict__ QKV, __half* __restrict__ Ph,
               __half* __restrict__ Ch,
               const __half* __restrict__ Who, const float* __restrict__ bo,
               float* __restrict__ out, float* __restrict__ om)
{
    extern __shared__ __half sm[];
    const int bid = blockIdx.x;
    const int tid = threadIdx.x;

    if (bid < 512) {
        // ================= attn producer =================
        const uint32_t QsB  = (uint32_t)__cvta_generic_to_shared(sm);
        const uint32_t KsB[2] = { QsB + 128 * FA_ST * 2, QsB + 2 * 128 * FA_ST * 2 };
        const uint32_t VsB[2] = { QsB + 3 * 128 * FA_ST * 2, QsB + 4 * 128 * FA_ST * 2 };

        const int lane = tid & 31, warp = tid >> 5;
        const int lr = lane >> 2, lc = lane & 3;
        const int itile = bid >> 5, bh = bid & 31;
        const int b = bh >> 4, h = bh & 15;
        const int mi = itile * 128;
        const int rt = b * 16 + itile;

#pragma unroll
        for (int i = 0; i < 4; ++i) {
            int c = tid + i * 256;
            int row = c >> 3, ch = c & 7;
            cp_async16(QsB + (uint32_t)((row * FA_ST + ch * 8) * 2),
                       QKV + (size_t)(b * SS + mi + row) * N3 + h * 64 + ch * 8);
        }
        cp_commit();

        auto issueKV = [&](int jt, int buf) {
#pragma unroll
            for (int i = 0; i < 4; ++i) {
                int c = tid + i * 256;
                int row = c >> 3, ch = c & 7;
                size_t base = (size_t)(b * SS + jt * 128 + row) * N3 + h * 64 + ch * 8;
                cp_async16(KsB[buf] + (uint32_t)((row * FA_ST + ch * 8) * 2),
                           QKV + base + 1024);
                cp_async16(VsB[buf] + (uint32_t)((row * FA_ST + ch * 8) * 2),
                           QKV + base + 2048);
            }
            cp_commit();
        };
        issueKV(0, 0);

        const float g2 = g_gate[bh] * 1.4426950408889634f;
        const float C8 = -11.541560327111708f;

        const int a_row  = warp * 16 + (lane & 15);
        const int a_koff = (lane >> 4) * 8;
        const int b1_nrow = (lane & 7) + (lane >> 4) * 8;
        const int b1_koff = ((lane >> 3) & 1) * 8;
        const int b2_krow = (lane & 7) + ((lane >> 3) & 1) * 8;
        const int b2_noff = (lane >> 4) * 8;

        cp_wait1();
        __syncthreads();
        uint32_t qf[4][4];
#pragma unroll
        for (int ks = 0; ks < 4; ++ks)
            ldsm_x4(qf[ks], QsB + (uint32_t)((a_row * FA_ST + ks * 16 + a_koff) * 2));

        float ctx[8][4];
#pragma unroll
        for (int i = 0; i < 8; ++i)
#pragma unroll
            for (int r = 0; r < 4; ++r) ctx[i][r] = 0.0f;
        float zs0 = 0.0f, zs1 = 0.0f;

        const int grow = mi + warp * 16 + lr;
        __half* Prow0 = Ph + ((size_t)bh * SS + grow) * SS;
        __half* Prow1 = Ph + ((size_t)bh * SS + grow + 8) * SS;

        auto mma1_q = [&](int buf, int q, float (&acc)[4][4]) {
#pragma unroll
            for (int i = 0; i < 4; ++i)
#pragma unroll
                for (int r = 0; r < 4; ++r) acc[i][r] = 0.0f;
#pragma unroll
            for (int ks = 0; ks < 4; ++ks)
#pragma unroll
                for (int np = 0; np < 2; ++np) {
                    uint32_t r4[4];
                    ldsm_x4(r4, KsB[buf] +
                            (uint32_t)(((q * 32 + np * 16 + b1_nrow) * FA_ST +
                                        ks * 16 + b1_koff) * 2));
                    mma_f16(acc[np * 2], qf[ks], r4);
                    mma_f16(acc[np * 2 + 1], qf[ks], r4 + 2);
                }
        };

        auto epi_q = [&](int buf, int jt, int q, float (&acc)[4][4]) {
            uint32_t r0v[4], r1v[4];
#pragma unroll
            for (int np = 0; np < 2; ++np) {
                float pa0 = ex2(fmaf(acc[np * 2][0], g2, C8));
                float pa1 = ex2(fmaf(acc[np * 2][1], g2, C8));
                float pb0 = ex2(fmaf(acc[np * 2][2], g2, C8));
                float pb1 = ex2(fmaf(acc[np * 2][3], g2, C8));
                float pc0 = ex2(fmaf(acc[np * 2 + 1][0], g2, C8));
                float pc1 = ex2(fmaf(acc[np * 2 + 1][1], g2, C8));
                float pd0 = ex2(fmaf(acc[np * 2 + 1][2], g2, C8));
                float pd1 = ex2(fmaf(acc[np * 2 + 1][3], g2, C8));
                __half2 wa = __floats2half2_rn(pa0, pa1);
                __half2 wb = __floats2half2_rn(pb0, pb1);
                __half2 wc2 = __floats2half2_rn(pc0, pc1);
                __half2 wd = __floats2half2_rn(pd0, pd1);
                zs0 += (pa0 + pa1) + (pc0 + pc1);
                zs1 += (pb0 + pb1) + (pd0 + pd1);
                r0v[np * 2] = h2u(wa); r0v[np * 2 + 1] = h2u(wc2);
                r1v[np * 2] = h2u(wb); r1v[np * 2 + 1] = h2u(wd);

                uint32_t af2[4] = { h2u(wa), h2u(wb), h2u(wc2), h2u(wd) };
#pragma unroll
                for (int n2 = 0; n2 < 4; ++n2) {
                    uint32_t r4[4];
                    ldsm_x4_t(r4, VsB[buf] +
                              (uint32_t)(((q * 32 + np * 16 + b2_krow) * FA_ST +
                                          n2 * 16 + b2_noff) * 2));
                    mma_f16(ctx[n2 * 2], af2, r4);
                    mma_f16(ctx[n2 * 2 + 1], af2, r4 + 2);
                }
            }
            int poff = jt * 128 + q * 32 + 8 * lc;
            *(uint4*)&Prow0[poff] = make_uint4(r0v[0], r0v[1], r0v[2], r0v[3]);
            *(uint4*)&Prow1[poff] = make_uint4(r1v[0], r1v[1], r1v[2], r1v[3]);
        };

        for (int jt = 0; jt < 16; ++jt) {
            const int buf = jt & 1;
            if (jt + 1 < 16) { issueKV(jt + 1, buf ^ 1); cp_wait1(); }
            else cp_wait0();
            __syncthreads();

            float accA[4][4], accB[4][4];
            mma1_q(buf, 0, accA);
            mma1_q(buf, 1, accB);
            epi_q(buf, jt, 0, accA);
            mma1_q(buf, 2, accA);
            epi_q(buf, jt, 1, accB);
            mma1_q(buf, 3, accB);
            epi_q(buf, jt, 2, accA);
            epi_q(buf, jt, 3, accB);

            __syncthreads();
        }

        zs0 += __shfl_xor_sync(0xffffffffu, zs0, 1);
        zs0 += __shfl_xor_sync(0xffffffffu, zs0, 2);
        zs1 += __shfl_xor_sync(0xffffffffu, zs1, 1);
        zs1 += __shfl_xor_sync(0xffffffffu, zs1, 2);
        float iz0 = 1.0f / zs0, iz1 = 1.0f / zs1;
        if (lc == 0) {
            g_invZ[(size_t)bh * SS + grow]     = iz0;
            g_invZ[(size_t)bh * SS + grow + 8] = iz1;
        }

        __half* Cc = Ch + (size_t)b * SS * EE + h * 64;
#pragma unroll
        for (int np = 0; np < 8; ++np) {
            int n = np * 8 + 2 * lc;
            *(__half2*)&Cc[(size_t)grow * EE + n] =
                __floats2half2_rn(ctx[np][0] * iz0, ctx[np][1] * iz0);
            *(__half2*)&Cc[(size_t)(grow + 8) * EE + n] =
                __floats2half2_rn(ctx[np][2] * iz1, ctx[np][3] * iz1);
        }

        __syncthreads();
        if (tid == 0) {
            __threadfence();
            atomicAdd(&g_done[rt], 1);
        }
        return;
    }

    if (bid < 1024) {
        // ================= out-proj GEMM 128x64 (flag-gated) =================
        const int gid = bid - 512;
        const int by = gid >> 4, bx = gid & 15;

        if (tid == 0) {
            while (atomicAdd(&g_done[by], 0) < 16) __nanosleep(200);
        }
        __syncthreads();
        __threadfence();

        constexpr int SA = 40;
        constexpr int SB = 72;
        const uint32_t base = (uint32_t)__cvta_generic_to_shared(sm);
        const uint32_t AsB[2] = { base, base + 128 * SA * 2 };
        const uint32_t BsB[2] = { base + 2 * 128 * SA * 2,
                                  base + 2 * 128 * SA * 2 + 32 * SB * 2 };

        const int lane = tid & 31, warp = tid >> 5;
        const int wr = warp & 3, wc = warp >> 2;
        const int lr = lane >> 2, lc = lane & 3;
        const int bm = by * 128, bn = bx * 64;

        const int arow0 = tid >> 2, ach0 = tid & 3;
        const int brow = tid >> 3, bch = tid & 7;

        auto issue = [&](int kt, int buf) {
            cp_async16(AsB[buf] + (uint32_t)((arow0 * SA + ach0 * 8) * 2),
                       Ch + (size_t)(bm + arow0) * EE + kt * 32 + ach0 * 8);
            cp_async16(AsB[buf] + (uint32_t)(((arow0 + 64) * SA + ach0 * 8) * 2),
                       Ch + (size_t)(bm + arow0 + 64) * EE + kt * 32 + ach0 * 8);
            cp_async16(BsB[buf] + (uint32_t)((brow * SB + bch * 8) * 2),
                       Who + (size_t)(kt * 32 + brow) * EE + bn + bch * 8);
            cp_commit();
        };

        float acc[2][4][4];
#pragma unroll
        for (int i = 0; i < 2; ++i)
#pragma unroll
            for (int j = 0; j < 4; ++j)
#pragma unroll
                for (int r = 0; r < 4; ++r) acc[i][j][r] = 0.0f;

        const int a_row_l = wr * 32 + (lane & 15);
        const int a_koff = (lane >> 4) * 8;
        const int b_krow = (lane & 7) + ((lane >> 3) & 1) * 8;
        const int b_noff = (lane >> 4) * 8;

        const int nk = EE / 32;
        issue(0, 0);

        for (int kt = 0; kt < nk; ++kt) {
            const int buf = kt & 1;
            if (kt + 1 < nk) { issue(kt + 1, buf ^ 1); cp_wait1(); }
            else cp_wait0();
            __syncthreads();

#pragma unroll
            for (int ks = 0; ks < 2; ++ks) {
                const int k0 = ks * 16;
                uint32_t af[2][4], bf[4][2];
#pragma unroll
                for (int mf = 0; mf < 2; ++mf)
                    ldsm_x4(af[mf], AsB[buf] +
                            (uint32_t)(((a_row_l + mf * 16) * SA + k0 + a_koff) * 2));
#pragma unroll
                for (int np = 0; np < 2; ++np) {
                    uint32_t r4[4];
                    int n0 = wc * 32 + np * 16;
                    ldsm_x4_t(r4, BsB[buf] +
                              (uint32_t)(((k0 + b_krow) * SB + n0 + b_noff) * 2));
                    bf[np * 2][0] = r4[0]; bf[np * 2][1] = r4[1];
                    bf[np * 2 + 1][0] = r4[2]; bf[np * 2 + 1][1] = r4[3];
                }
#pragma unroll
                for (int mf = 0; mf < 2; ++mf)
#pragma unroll
                    for (int nf = 0; nf < 4; ++nf)
                        mma_f16(acc[mf][nf], af[mf], bf[nf]);
            }
            __syncthreads();
        }

#pragma unroll
        for (int nf = 0; nf < 4; ++nf) {
            int col = bn + wc * 32 + nf * 8 + lc * 2;
            float b0 = bo[col], b1 = bo[col + 1];
#pragma unroll
            for (int mf = 0; mf < 2; ++mf) {
                int row = bm + wr * 32 + mf * 16 + lr;
                *(float2*)&out[(size_t)row * EE + col] =
                    make_float2(acc[mf][nf][0] + b0, acc[mf][nf][1] + b1);
                *(float2*)&out[(size_t)(row + 8) * EE + col] =
                    make_float2(acc[mf][nf][2] + b0, acc[mf][nf][3] + b1);
            }
        }
        return;
    }

    // ================= head-mean (flag-gated) =================
    {
        const int mid = bid - 1024;               // 0..2047
        const int rt = mid >> 6;
        if (tid == 0) {
            while (atomicAdd(&g_done[rt], 0) < 16) __nanosleep(200);
        }
        __syncthreads();
        __threadfence();

        const int grow = mid * 2 + (tid >> 7);
        const int b = grow >> 11, i = grow & (SS - 1);
        const int j = tid & 127;
        const int blk = j >> 1, hf = j & 1;

        float acc[16];
#pragma unroll
        for (int s = 0; s < 16; ++s) acc[s] = 0.0f;

#pragma unroll
        for (int h4 = 0; h4 < HH; h4 += 4) {
            float w[4];
            uint4 v0[4], v1[4];
#pragma unroll
            for (int u = 0; u < 4; ++u) {
                const int hh = h4 + u;
                w[u] = g_invZ[(size_t)(b * HH + hh) * SS + i] * 0.0625f;
                const __half* base = Ph + ((size_t)(b * HH + hh) * SS + i) * SS
                                       + blk * 32 + hf * 16;
                v0[u] = *(const uint4*)base;
                v1[u] = *(const uint4*)(base + 8);
            }
#pragma unroll
            for (int u = 0; u < 4; ++u) {
                const uint32_t* vv = (const uint32_t*)&v0[u];
#pragma unroll
                for (int q = 0; q < 4; ++q) {
                    float2 f = __half22float2(*(const __half2*)&vv[q]);
                    acc[2 * q]     = fmaf(w[u], f.x, acc[2 * q]);
                    acc[2 * q + 1] = fmaf(w[u], f.y, acc[2 * q + 1]);
                }
                const uint32_t* vw = (const uint32_t*)&v1[u];
#pragma unroll
                for (int q = 0; q < 4; ++q) {
                    float2 f = __half22float2(*(const __half2*)&vw[q]);
                    acc[8 + 2 * q]     = fmaf(w[u], f.x, acc[8 + 2 * q]);
                    acc[8 + 2 * q + 1] = fmaf(w[u], f.y, acc[8 + 2 * q + 1]);
                }
            }
        }

        float* op = om + (size_t)(b * SS + i) * SS + blk * 32 + hf * 4;
        *(float4*)&op[0]  = make_float4(acc[0], acc[1], acc[8],  acc[9]);
        *(float4*)&op[8]  = make_float4(acc[2], acc[3], acc[10], acc[11]);
        *(float4*)&op[16] = make_float4(acc[4], acc[5], acc[12], acc[13]);
        *(float4*)&op[24] = make_float4(acc[6], acc[7], acc[14], acc[15]);
    }
}

// ---------------- launch ----------------
extern "C" void kernel_launch(void* const* d_in, const int* in_sizes, int n_in,
                              void* d_out, int out_size)
{
    const float* x   = (const float*)d_in[0];
    const float* sf  = (const float*)d_in[1];
    const float* Wq  = (const float*)d_in[2];
    const float* bq  = (const float*)d_in[3];
    const float* Wk  = (const float*)d_in[4];
    const float* bk  = (const float*)d_in[5];
    const float* Wv  = (const float*)d_in[6];
    const float* bv  = (const float*)d_in[7];
    const float* Ws1 = (const float*)d_in[8];
    const float* bs1 = (const float*)d_in[9];
    const float* Ws2 = (const float*)d_in[10];
    const float* bs2 = (const float*)d_in[11];
    const float* Wo  = (const float*)d_in[12];
    const float* bo  = (const float*)d_in[13];
    float* out = (float*)d_out;

    __half *pXh, *pW3, *pWho, *pQKV, *pCh, *pPh;
    float *pb3;
    cudaGetSymbolAddress((void**)&pXh, g_Xh);
    cudaGetSymbolAddress((void**)&pW3, g_W3);
    cudaGetSymbolAddress((void**)&pWho, g_Who);
    cudaGetSymbolAddress((void**)&pb3, g_b3);
    cudaGetSymbolAddress((void**)&pQKV, g_QKV);
    cudaGetSymbolAddress((void**)&pCh, g_CTXh);
    cudaGetSymbolAddress((void**)&pPh, g_Ph);

    // 0. prep: conversions + interleave + gate (MLP-16) + bias + flag reset
    prep<<<1 + 4096 + 3072 + 1024, 256>>>(x, Wq, Wk, Wv, Wo, bq, bk, bv,
                                          sf, Ws1, bs1, Ws2, bs2);

    // 1. fused QKV projection: [4096,1024] @ [1024,3072], BK=64
    cudaFuncSetAttribute(gemm_qkv64, cudaFuncAttributeMaxDynamicSharedMemorySize, QK_SMEM);
    gemm_qkv64<<<dim3(N3 / 128, (BB * SS) / 128), 256, QK_SMEM>>>(pXh, pW3, pb3, pQKV);

    // 2. merged attention + tail (flag-gated fine-grained dependencies)
    cudaFuncSetAttribute(attn_tail, cudaFuncAttributeMaxDynamicSharedMemorySize, FA_SMEM);
    attn_tail<<<512 + 512 + 2048, 256, FA_SMEM>>>(pQKV, pPh, pCh, pWho, bo, out,
                                                  out + (size_t)BB * SS * EE);

    (void)in_sizes; (void)n_in; (void)out_size;
}